// round 5
// baseline (speedup 1.0000x reference)
#include <cuda_runtime.h>
#include <cuda_bf16.h>
#include <math.h>
#include <stdint.h>

#define NB 2048   // batch
#define NF 512    // features
#define NH 256    // hidden
#define NE 64     // experts
#define NK 8      // top-k

typedef unsigned int u32;

// ---------------- scratch (no allocation allowed) ----------------
__device__ int   g_counts[NE];
__device__ int   g_tok[NE * NB];
__device__ float g_wt[NE * NB];
__device__ float g_escale[NE];
__device__ float g_efinv[NE];
__device__ float g_xinv[NB];
__device__ float g_h[NB * NH];        // 2MB fp32 hidden
__device__ float g_score[NB * NE];    // 512KB scores
// bf16 hi/lo split buffers
__device__ __nv_bfloat16 g_xhi[NB * NF];               // 2MB
__device__ __nv_bfloat16 g_xlo[NB * NF];               // 2MB
__device__ __nv_bfloat16 g_wthi[(size_t)NE * NF * NF]; // 33.5MB, layout [e][n][k]
__device__ __nv_bfloat16 g_wtlo[(size_t)NE * NF * NF]; // 33.5MB

// ---------------- PTX helpers (sm_80-era; valid on sm_100 target) ----------
__device__ __forceinline__ uint32_t smem_to_u32(const void* p) {
    uint32_t a;
    asm("{ .reg .u64 t; cvta.to.shared.u64 t, %1; cvt.u32.u64 %0, t; }"
        : "=r"(a) : "l"(p));
    return a;
}
__device__ __forceinline__ void cp16(uint32_t dst, const void* src, int srcsize) {
    asm volatile("cp.async.cg.shared.global [%0], [%1], 16, %2;"
                 :: "r"(dst), "l"(src), "r"(srcsize));
}
#define CP_COMMIT() asm volatile("cp.async.commit_group;" ::: "memory")
#define CP_WAIT(n)  asm volatile("cp.async.wait_group %0;" :: "n"(n) : "memory")

__device__ __forceinline__ void ldm_x4(u32& r0, u32& r1, u32& r2, u32& r3, u32 addr) {
    asm volatile("ldmatrix.sync.aligned.m8n8.x4.shared.b16 {%0,%1,%2,%3}, [%4];"
                 : "=r"(r0), "=r"(r1), "=r"(r2), "=r"(r3) : "r"(addr));
}
__device__ __forceinline__ void mma_bf16(float& c0, float& c1, float& c2, float& c3,
                                         u32 a0, u32 a1, u32 a2, u32 a3,
                                         u32 b0, u32 b1) {
    asm volatile("mma.sync.aligned.m16n8k16.row.col.f32.bf16.bf16.f32 "
                 "{%0,%1,%2,%3}, {%4,%5,%6,%7}, {%8,%9}, {%0,%1,%2,%3};"
                 : "+f"(c0), "+f"(c1), "+f"(c2), "+f"(c3)
                 : "r"(a0), "r"(a1), "r"(a2), "r"(a3), "r"(b0), "r"(b1));
}

// ---------------- bf16 hi/lo split ----------------
__device__ __forceinline__ void split2(float a, float b, u32& hi, u32& lo) {
    __nv_bfloat16 ah = __float2bfloat16(a), bh = __float2bfloat16(b);
    float ar = a - __bfloat162float(ah);
    float br = b - __bfloat162float(bh);
    __nv_bfloat16 al = __float2bfloat16(ar), bl = __float2bfloat16(br);
    hi = (u32)__bfloat16_as_ushort(ah) | ((u32)__bfloat16_as_ushort(bh) << 16);
    lo = (u32)__bfloat16_as_ushort(al) | ((u32)__bfloat16_as_ushort(bl) << 16);
}

// ---------------- kernel 0: per-expert scalars + count reset ----------------
__global__ void init_kernel(const float* __restrict__ ef,
                            const float* __restrict__ trust,
                            const float* __restrict__ dt) {
    int e = threadIdx.x;
    if (e < NE) {
        g_counts[e] = 0;
        g_escale[e] = trust[e] * fmaxf(0.1f, expf(-0.005f * dt[e]));
        const float4* r = (const float4*)(ef + e * NF);
        float s = 0.f;
        #pragma unroll 8
        for (int i = 0; i < NF / 4; i++) {
            float4 v = r[i];
            s += v.x * v.x + v.y * v.y + v.z * v.z + v.w * v.w;
        }
        g_efinv[e] = 1.0f / fmaxf(sqrtf(s), 1e-8f);
    }
}

// ---------------- kernel 1: zero output ----------------
__global__ void zero_kernel(float4* __restrict__ out) {
    out[blockIdx.x * 256 + threadIdx.x] = make_float4(0.f, 0.f, 0.f, 0.f);
}

// ---------------- kernel 1b: X -> bf16 hi/lo + token inv-norm (warp/row) ----
__global__ void __launch_bounds__(256)
convert_x_rows(const float* __restrict__ feat) {
    const int tid  = threadIdx.x;
    const int lane = tid & 31;
    const int row  = blockIdx.x * 8 + (tid >> 5);
    const float4* src = (const float4*)(feat + (size_t)row * NF);
    u32* xh = (u32*)g_xhi;
    u32* xl = (u32*)g_xlo;
    float s = 0.f;
    #pragma unroll
    for (int j = 0; j < 4; j++) {
        int q = lane + 32 * j;
        float4 v = src[q];
        s += v.x * v.x + v.y * v.y + v.z * v.z + v.w * v.w;
        u32 h0, l0, h1, l1;
        split2(v.x, v.y, h0, l0);
        split2(v.z, v.w, h1, l1);
        int p = row * 256 + q * 2;
        *(uint2*)(xh + p) = make_uint2(h0, h1);
        *(uint2*)(xl + p) = make_uint2(l0, l1);
    }
    #pragma unroll
    for (int off = 16; off > 0; off >>= 1)
        s += __shfl_xor_sync(0xffffffffu, s, off);
    if (lane == 0) g_xinv[row] = 1.0f / fmaxf(sqrtf(s), 1e-8f);
}

// ---------------- kernel 1c: convert + transpose W -> [e][n][k] bf16 hi/lo ----
__global__ void __launch_bounds__(256)
convert_w(const float* __restrict__ fw) {
    __shared__ float s[64][65];
    const int e  = blockIdx.z;
    const int k0 = blockIdx.x * 64;
    const int n0 = blockIdx.y * 64;
    const int tid = threadIdx.x;
    const float* src = fw + ((size_t)e * NF + k0) * NF + n0;
    #pragma unroll
    for (int i = 0; i < 16; i++) {
        int idx = tid + 256 * i;
        int kl = idx >> 6, nl = idx & 63;
        s[kl][nl] = src[(size_t)kl * NF + nl];
    }
    __syncthreads();
    u32* wh = (u32*)g_wthi;
    u32* wl = (u32*)g_wtlo;
    #pragma unroll
    for (int i = 0; i < 8; i++) {
        int idx = tid + 256 * i;
        int nl = idx >> 5;
        int kp = (idx & 31) * 2;
        float a = s[kp][nl], b = s[kp + 1][nl];
        u32 hi, lo;
        split2(a, b, hi, lo);
        size_t off = (((size_t)e * NF + n0 + nl) * NF + k0 + kp) >> 1;
        wh[off] = hi; wl[off] = lo;
    }
}

// ---------------- kernel 2a: h = X @ pw^T + pb (fp32, 32x64 tiles) ---------
__global__ void __launch_bounds__(256)
route_h(const float* __restrict__ feat, const float* __restrict__ pw,
        const float* __restrict__ pb) {
    __shared__ float xsT[32][33];   // [kk][tok]
    __shared__ float ws[32][68];    // [kk][col], 68 pad keeps 16B align

    const int tid = threadIdx.x;
    const int t0  = blockIdx.x * 32;
    const int n0  = blockIdx.y * 64;

    const int tg = tid >> 4;       // 0..15 -> 2 tokens
    const int cg = tid & 15;       // 0..15 -> 4 cols

    float acc[2][4];
    #pragma unroll
    for (int r = 0; r < 2; r++)
        #pragma unroll
        for (int c = 0; c < 4; c++) acc[r][c] = 0.f;

    const float4* feat4 = (const float4*)feat;
    const float4* pw4   = (const float4*)pw;

    for (int kb = 0; kb < NF / 32; kb++) {
        // X tile: 32 tok x 32 k
        {
            int tok = tid >> 3, kq = tid & 7;
            float4 v = feat4[(size_t)(t0 + tok) * 128 + kb * 8 + kq];
            xsT[kq * 4 + 0][tok] = v.x;
            xsT[kq * 4 + 1][tok] = v.y;
            xsT[kq * 4 + 2][tok] = v.z;
            xsT[kq * 4 + 3][tok] = v.w;
        }
        // W tile: 64 cols x 32 k (pw is [n][k] row-major)
        #pragma unroll
        for (int i = 0; i < 2; i++) {
            int idx = tid + 256 * i;
            int col = idx >> 3, kq = idx & 7;
            float4 v = pw4[(size_t)(n0 + col) * 128 + kb * 8 + kq];
            ws[kq * 4 + 0][col] = v.x;
            ws[kq * 4 + 1][col] = v.y;
            ws[kq * 4 + 2][col] = v.z;
            ws[kq * 4 + 3][col] = v.w;
        }
        __syncthreads();
        #pragma unroll
        for (int kk = 0; kk < 32; kk++) {
            float x0 = xsT[kk][tg * 2 + 0];
            float x1 = xsT[kk][tg * 2 + 1];
            float4 w = *(const float4*)&ws[kk][cg * 4];
            acc[0][0] += x0 * w.x; acc[0][1] += x0 * w.y;
            acc[0][2] += x0 * w.z; acc[0][3] += x0 * w.w;
            acc[1][0] += x1 * w.x; acc[1][1] += x1 * w.y;
            acc[1][2] += x1 * w.z; acc[1][3] += x1 * w.w;
        }
        __syncthreads();
    }

    float4 b4 = *(const float4*)(pb + n0 + cg * 4);
    float4* h4 = (float4*)g_h;
    #pragma unroll
    for (int r = 0; r < 2; r++) {
        float4 o;
        o.x = acc[r][0] + b4.x; o.y = acc[r][1] + b4.y;
        o.z = acc[r][2] + b4.z; o.w = acc[r][3] + b4.w;
        h4[(size_t)(t0 + tg * 2 + r) * 64 + (n0 >> 2) + cg] = o;
    }
}

// ---------------- kernel 2b: score[t][e] (8 tokens / block) ----------------
__global__ void __launch_bounds__(256)
route_score(const float* __restrict__ feat, const float* __restrict__ emb,
            const float* __restrict__ ef) {
    __shared__ float xs[8 * 512];
    __shared__ float hs[8 * 256];
    __shared__ float xinv8[8];

    const int tid = threadIdx.x;
    const int t0  = blockIdx.x * 8;

    float4* xs4 = (float4*)xs;
    float4* hs4 = (float4*)hs;
    const float4* feat4 = (const float4*)feat;
    const float4* h4    = (const float4*)g_h;
    #pragma unroll
    for (int j = 0; j < 4; j++) {
        int idx = tid + 256 * j;
        int tt = idx >> 7, q = idx & 127;
        xs4[tt * 128 + q] = feat4[(size_t)(t0 + tt) * 128 + q];
    }
    #pragma unroll
    for (int j = 0; j < 2; j++) {
        int idx = tid + 256 * j;
        int tt = idx >> 6, q = idx & 63;
        hs4[tt * 64 + q] = h4[(size_t)(t0 + tt) * 64 + q];
    }
    if (tid < 8) xinv8[tid] = g_xinv[t0 + tid];
    __syncthreads();

    #pragma unroll
    for (int j = 0; j < 2; j++) {
        int pid = tid + 256 * j;
        int e  = pid >> 3;
        int tt = pid & 7;
        // gate logit: h . emb_e / 16
        float dg = 0.f;
        const float4* hr = (const float4*)(hs + tt * 256);
        const float4* er = (const float4*)(emb + (size_t)e * NH);
        #pragma unroll 8
        for (int q = 0; q < 64; q++) {
            float4 a = hr[q], b = er[q];
            dg += a.x * b.x + a.y * b.y + a.z * b.z + a.w * b.w;
        }
        float gate = 1.0f / (1.0f + expf(-dg * 0.0625f));
        // cosine sim
        float ds = 0.f;
        const float4* xr = (const float4*)(xs + tt * 512);
        const float4* fr = (const float4*)(ef + (size_t)e * NF);
        #pragma unroll 8
        for (int q = 0; q < 128; q++) {
            float4 a = xr[q], b = fr[q];
            ds += a.x * b.x + a.y * b.y + a.z * b.z + a.w * b.w;
        }
        float sim = fmaxf(ds * xinv8[tt] * g_efinv[e], 0.f);
        g_score[(size_t)(t0 + tt) * NE + e] = gate * sim * g_escale[e];
    }
}

// ---------------- kernel 2c: top-8 + softmax + scatter (warp / token) ------
__global__ void __launch_bounds__(256)
route_topk() {
    const int tid  = threadIdx.x;
    const int lane = tid & 31;
    const int tok  = blockIdx.x * 8 + (tid >> 5);

    float s0 = g_score[(size_t)tok * NE + lane];
    float s1 = g_score[(size_t)tok * NE + 32 + lane];
    const int e0 = lane, e1 = 32 + lane;

    float vk[NK];
    int   ik[NK];
    #pragma unroll
    for (int k = 0; k < NK; k++) {
        float v; int ix;
        if (s0 >= s1) { v = s0; ix = e0; }   // tie -> lower index
        else          { v = s1; ix = e1; }
        #pragma unroll
        for (int off = 16; off > 0; off >>= 1) {
            float ov = __shfl_down_sync(0xffffffffu, v, off);
            int   oi = __shfl_down_sync(0xffffffffu, ix, off);
            if (ov > v || (ov == v && oi < ix)) { v = ov; ix = oi; }
        }
        v  = __shfl_sync(0xffffffffu, v, 0);
        ix = __shfl_sync(0xffffffffu, ix, 0);
        vk[k] = v; ik[k] = ix;
        if (ix == e0) s0 = -1e30f;
        if (ix == e1) s1 = -1e30f;
    }
    float m = vk[0], sum = 0.f, w[NK];
    #pragma unroll
    for (int k = 0; k < NK; k++) { w[k] = expf(vk[k] - m); sum += w[k]; }
    float inv = 1.0f / sum;
    #pragma unroll
    for (int k = 0; k < NK; k++) {
        if (lane == k) {
            int e = ik[k];
            int slot = atomicAdd(&g_counts[e], 1);
            g_tok[e * NB + slot] = tok;
            g_wt[e * NB + slot]  = w[k] * inv;
        }
    }
}

// ---------------- kernel 3: mma.sync bf16 hi/lo grouped MoE GEMM ----------
#define MG_DATA    1024
#define MG_BUF     65536
#define MG_AHI     0
#define MG_ALO     16384
#define MG_BHI     32768
#define MG_BLO     49152
#define MG_SMEM    (MG_DATA + 2 * MG_BUF)   // 132096 bytes

__global__ void __launch_bounds__(256, 1)
moe_gemm_mma(const float* __restrict__ fb, float* __restrict__ out) {
    const int e    = blockIdx.y;
    const int n0   = blockIdx.x * 128;
    const int tile = blockIdx.z;
    const int cnt  = g_counts[e];
    if (tile * 128 >= cnt) return;

    extern __shared__ char smem[];
    const uint32_t sb = smem_to_u32(smem);
    const int tid = threadIdx.x;

    int*   toks = (int*)(smem);
    float* wts  = (float*)(smem + 512);
    {
        int s = tile * 128 + tid;
        if (tid < 128) {
            if (s < cnt) { toks[tid] = g_tok[e * NB + s]; wts[tid] = g_wt[e * NB + s]; }
            else         { toks[tid] = -1;                wts[tid] = 0.f; }
        }
    }
    __syncthreads();

    const int srow  = tid >> 1;
    const int spart = (tid & 1) * 4;
    const int stok  = toks[srow];
    const int asz   = (stok >= 0) ? 16 : 0;
    const uint4* aH = (const uint4*)(g_xhi + (size_t)max(stok, 0) * NF);
    const uint4* aL = (const uint4*)(g_xlo + (size_t)max(stok, 0) * NF);
    const uint4* bH = (const uint4*)(g_wthi + ((size_t)e * NF + n0 + srow) * NF);
    const uint4* bL = (const uint4*)(g_wtlo + ((size_t)e * NF + n0 + srow) * NF);
    const uint32_t srowb = sb + MG_DATA + srow * 128;
    const int      ssw   = (srow & 7) * 16;

    #define PREFETCH(c)                                                          \
    do {                                                                         \
        const int _buf = (c) & 1;                                                \
        const uint32_t _d = srowb + _buf * MG_BUF;                               \
        _Pragma("unroll")                                                        \
        for (int j = 0; j < 4; j++) {                                            \
            const int c16 = spart + j;                                           \
            const uint32_t off = (uint32_t)((c16 * 16) ^ ssw);                   \
            cp16(_d + MG_AHI + off, aH + (c) * 8 + c16, asz);                    \
            cp16(_d + MG_ALO + off, aL + (c) * 8 + c16, asz);                    \
            cp16(_d + MG_BHI + off, bH + (c) * 8 + c16, 16);                     \
            cp16(_d + MG_BLO + off, bL + (c) * 8 + c16, 16);                     \
        }                                                                        \
    } while (0)

    PREFETCH(0);
    CP_COMMIT();

    const int lid = tid & 31;
    const int wid = tid >> 5;
    const int wm  = wid & 1;
    const int wn  = wid >> 1;

    float acc[4][4][4];
    #pragma unroll
    for (int mt = 0; mt < 4; mt++)
        #pragma unroll
        for (int nt = 0; nt < 4; nt++)
            #pragma unroll
            for (int q = 0; q < 4; q++) acc[mt][nt][q] = 0.f;

    const int fa_row = (lid & 15);
    const int fa_hi  = (lid >> 4);

    for (int c = 0; c < 8; c++) {
        if (c < 7) { PREFETCH(c + 1); CP_COMMIT(); CP_WAIT(1); }
        else       { CP_WAIT(0); }
        __syncthreads();

        const uint32_t base = sb + MG_DATA + (c & 1) * MG_BUF;

        #pragma unroll
        for (int ks = 0; ks < 4; ks++) {
            const int c16 = ks * 2 + fa_hi;
            u32 ah[4][4], al[4][4];
            #pragma unroll
            for (int mt = 0; mt < 4; mt++) {
                const int r = wm * 64 + mt * 16 + fa_row;
                const uint32_t off = r * 128 + (uint32_t)((c16 * 16) ^ ((r & 7) * 16));
                ldm_x4(ah[mt][0], ah[mt][1], ah[mt][2], ah[mt][3], base + MG_AHI + off);
                ldm_x4(al[mt][0], al[mt][1], al[mt][2], al[mt][3], base + MG_ALO + off);
            }
            u32 bh[2][4], bl[2][4];
            #pragma unroll
            for (int p = 0; p < 2; p++) {
                const int r = wn * 32 + p * 16 + fa_row;
                const uint32_t off = r * 128 + (uint32_t)((c16 * 16) ^ ((r & 7) * 16));
                ldm_x4(bh[p][0], bh[p][1], bh[p][2], bh[p][3], base + MG_BHI + off);
                ldm_x4(bl[p][0], bl[p][1], bl[p][2], bl[p][3], base + MG_BLO + off);
            }
            #pragma unroll
            for (int mt = 0; mt < 4; mt++) {
                #pragma unroll
                for (int nt = 0; nt < 4; nt++) {
                    const int p = nt >> 1, h = nt & 1;
                    float* cc = acc[mt][nt];
                    mma_bf16(cc[0], cc[1], cc[2], cc[3],
                             ah[mt][0], ah[mt][1], ah[mt][2], ah[mt][3],
                             bh[p][h], bh[p][h + 2]);
                    mma_bf16(cc[0], cc[1], cc[2], cc[3],
                             ah[mt][0], ah[mt][1], ah[mt][2], ah[mt][3],
                             bl[p][h], bl[p][h + 2]);
                    mma_bf16(cc[0], cc[1], cc[2], cc[3],
                             al[mt][0], al[mt][1], al[mt][2], al[mt][3],
                             bh[p][h], bh[p][h + 2]);
                }
            }
        }
        __syncthreads();
    }

    const float* fbr = fb + (size_t)e * NF + n0;
    #pragma unroll
    for (int mt = 0; mt < 4; mt++) {
        const int r0 = wm * 64 + mt * 16 + (lid >> 2);
        const int r1 = r0 + 8;
        const int tok0 = toks[r0], tok1 = toks[r1];
        const float w0 = wts[r0],  w1 = wts[r1];
        #pragma unroll
        for (int nt = 0; nt < 4; nt++) {
            const int cb = wn * 32 + nt * 8 + (lid & 3) * 2;
            const float b0v = fbr[cb], b1v = fbr[cb + 1];
            const float* cc = acc[mt][nt];
            if (tok0 >= 0) {
                float* orow = out + (size_t)tok0 * NF + n0 + cb;
                atomicAdd(orow + 0, w0 * (cc[0] + b0v));
                atomicAdd(orow + 1, w0 * (cc[1] + b1v));
            }
            if (tok1 >= 0) {
                float* orow = out + (size_t)tok1 * NF + n0 + cb;
                atomicAdd(orow + 0, w1 * (cc[2] + b0v));
                atomicAdd(orow + 1, w1 * (cc[3] + b1v));
            }
        }
    }
}

// ---------------- launch ----------------
extern "C" void kernel_launch(void* const* d_in, const int* in_sizes, int n_in,
                              void* d_out, int out_size) {
    const float* feat  = (const float*)d_in[0];  // [B,F]
    const float* pw    = (const float*)d_in[1];  // [H,F]
    const float* pb    = (const float*)d_in[2];  // [H]
    const float* emb   = (const float*)d_in[3];  // [E,H]
    const float* ef    = (const float*)d_in[4];  // [E,F]
    const float* trust = (const float*)d_in[5];  // [E]
    const float* dt    = (const float*)d_in[6];  // [E]
    const float* fw    = (const float*)d_in[7];  // [E,F,F]
    const float* fb    = (const float*)d_in[8];  // [E,F]
    float* out = (float*)d_out;

    static bool attr_done = false;
    if (!attr_done) {
        cudaFuncSetAttribute(moe_gemm_mma,
                             cudaFuncAttributeMaxDynamicSharedMemorySize, MG_SMEM);
        attr_done = true;
    }

    init_kernel<<<1, 64>>>(ef, trust, dt);
    zero_kernel<<<(NB * NF) / (256 * 4), 256>>>((float4*)out);
    convert_x_rows<<<NB / 8, 256>>>(feat);
    convert_w<<<dim3(8, 8, NE), 256>>>(fw);
    route_h<<<dim3(NB / 32, NH / 64), 256>>>(feat, pw, pb);
    route_score<<<NB / 8, 256>>>(feat, emb, ef);
    route_topk<<<NB / 8, 256>>>();
    moe_gemm_mma<<<dim3(4, NE, NB / 128), 256, MG_SMEM>>>(fb, out);
}

// round 6
// speedup vs baseline: 1.0857x; 1.0857x over previous
#include <cuda_runtime.h>
#include <cuda_bf16.h>
#include <math.h>
#include <stdint.h>

#define NB 2048   // batch
#define NF 512    // features
#define NH 256    // hidden
#define NE 64     // experts
#define NK 8      // top-k

typedef unsigned int u32;

// ---------------- scratch (no allocation allowed) ----------------
__device__ int   g_counts[NE];
__device__ int   g_tok[NE * NB];
__device__ float g_wt[NE * NB];
__device__ float g_escale[NE];
__device__ float g_efinv[NE];
// bf16 hi/lo split buffers
__device__ __nv_bfloat16 g_xhi[NB * NF];               // 2MB
__device__ __nv_bfloat16 g_xlo[NB * NF];               // 2MB
__device__ __nv_bfloat16 g_wthi[(size_t)NE * NF * NF]; // 33.5MB, layout [e][n][k]
__device__ __nv_bfloat16 g_wtlo[(size_t)NE * NF * NF]; // 33.5MB

// ---------------- PTX helpers (sm_80-era; valid on sm_100 target) ----------
__device__ __forceinline__ uint32_t smem_to_u32(const void* p) {
    uint32_t a;
    asm("{ .reg .u64 t; cvta.to.shared.u64 t, %1; cvt.u32.u64 %0, t; }"
        : "=r"(a) : "l"(p));
    return a;
}
__device__ __forceinline__ void cp16(uint32_t dst, const void* src, int srcsize) {
    asm volatile("cp.async.cg.shared.global [%0], [%1], 16, %2;"
                 :: "r"(dst), "l"(src), "r"(srcsize));
}
#define CP_COMMIT() asm volatile("cp.async.commit_group;" ::: "memory")
#define CP_WAIT(n)  asm volatile("cp.async.wait_group %0;" :: "n"(n) : "memory")

__device__ __forceinline__ void ldm_x4(u32& r0, u32& r1, u32& r2, u32& r3, u32 addr) {
    asm volatile("ldmatrix.sync.aligned.m8n8.x4.shared.b16 {%0,%1,%2,%3}, [%4];"
                 : "=r"(r0), "=r"(r1), "=r"(r2), "=r"(r3) : "r"(addr));
}
__device__ __forceinline__ void mma_bf16(float& c0, float& c1, float& c2, float& c3,
                                         u32 a0, u32 a1, u32 a2, u32 a3,
                                         u32 b0, u32 b1) {
    asm volatile("mma.sync.aligned.m16n8k16.row.col.f32.bf16.bf16.f32 "
                 "{%0,%1,%2,%3}, {%4,%5,%6,%7}, {%8,%9}, {%0,%1,%2,%3};"
                 : "+f"(c0), "+f"(c1), "+f"(c2), "+f"(c3)
                 : "r"(a0), "r"(a1), "r"(a2), "r"(a3), "r"(b0), "r"(b1));
}

// ---------------- bf16 hi/lo split ----------------
__device__ __forceinline__ void split2(float a, float b, u32& hi, u32& lo) {
    __nv_bfloat16 ah = __float2bfloat16(a), bh = __float2bfloat16(b);
    float ar = a - __bfloat162float(ah);
    float br = b - __bfloat162float(bh);
    __nv_bfloat16 al = __float2bfloat16(ar), bl = __float2bfloat16(br);
    hi = (u32)__bfloat16_as_ushort(ah) | ((u32)__bfloat16_as_ushort(bh) << 16);
    lo = (u32)__bfloat16_as_ushort(al) | ((u32)__bfloat16_as_ushort(bl) << 16);
}

// ---------------- kernel 0: per-expert scalars + count reset ----------------
__global__ void init_kernel(const float* __restrict__ ef,
                            const float* __restrict__ trust,
                            const float* __restrict__ dt) {
    int e = threadIdx.x;
    if (e < NE) {
        g_counts[e] = 0;
        g_escale[e] = trust[e] * fmaxf(0.1f, expf(-0.005f * dt[e]));
        const float4* r = (const float4*)(ef + e * NF);
        float s = 0.f;
        #pragma unroll 8
        for (int i = 0; i < NF / 4; i++) {
            float4 v = r[i];
            s += v.x * v.x + v.y * v.y + v.z * v.z + v.w * v.w;
        }
        g_efinv[e] = 1.0f / fmaxf(sqrtf(s), 1e-8f);
    }
}

// ---------------- kernel 1: zero output ----------------
__global__ void zero_kernel(float4* __restrict__ out) {
    out[blockIdx.x * 256 + threadIdx.x] = make_float4(0.f, 0.f, 0.f, 0.f);
}

// ---------------- kernel 1b: convert X to bf16 hi/lo ----------------
__global__ void convert_x(const float* __restrict__ feat) {
    u32* xh = (u32*)g_xhi;
    u32* xl = (u32*)g_xlo;
    int p = blockIdx.x * 256 + threadIdx.x;
    const int npairs = NB * NF / 2;
    for (; p < npairs; p += gridDim.x * 256) {
        float2 v = *(const float2*)(feat + 2 * p);
        u32 hi, lo;
        split2(v.x, v.y, hi, lo);
        xh[p] = hi; xl[p] = lo;
    }
}

// ---------------- kernel 1c: convert + transpose W -> [e][n][k] bf16 hi/lo ----
__global__ void __launch_bounds__(256)
convert_w(const float* __restrict__ fw) {
    __shared__ float s[64][65];
    const int e  = blockIdx.z;
    const int k0 = blockIdx.x * 64;
    const int n0 = blockIdx.y * 64;
    const int tid = threadIdx.x;
    const float* src = fw + ((size_t)e * NF + k0) * NF + n0;
    #pragma unroll
    for (int i = 0; i < 16; i++) {
        int idx = tid + 256 * i;
        int kl = idx >> 6, nl = idx & 63;
        s[kl][nl] = src[(size_t)kl * NF + nl];
    }
    __syncthreads();
    u32* wh = (u32*)g_wthi;
    u32* wl = (u32*)g_wtlo;
    #pragma unroll
    for (int i = 0; i < 8; i++) {
        int idx = tid + 256 * i;
        int nl = idx >> 5;
        int kp = (idx & 31) * 2;
        float a = s[kp][nl], b = s[kp + 1][nl];
        u32 hi, lo;
        split2(a, b, hi, lo);
        size_t off = (((size_t)e * NF + n0 + nl) * NF + k0 + kp) >> 1;
        wh[off] = hi; wl[off] = lo;
    }
}

// ---------------- kernel 2: routing (R4 monolith, known-good) --------------
#define XS_STRIDE 516
#define PW_STRIDE 260
#define SC_STRIDE 68
#define ROUT_SMEM ((16 * XS_STRIDE + 32 * PW_STRIDE) * 4)

__global__ void __launch_bounds__(256, 1)
routing_kernel(const float* __restrict__ feat, const float* __restrict__ pw,
               const float* __restrict__ pb,   const float* __restrict__ emb,
               const float* __restrict__ ef) {
    extern __shared__ float sm[];
    float* xs   = sm;
    float* buf  = sm + 16 * XS_STRIDE;
    float* pws  = buf;
    float* hs   = buf;
    float* sc   = buf + 16 * 256;
    float* xinv = buf + 16 * 256 + 16 * SC_STRIDE;

    const int tid = threadIdx.x;
    const int t0  = blockIdx.x * 16;

    #pragma unroll
    for (int i = 0; i < 8; i++) {
        int idx = tid + 256 * i;
        int t   = idx >> 7;
        int k4  = (idx & 127) * 4;
        float4 v = *(const float4*)(feat + (size_t)(t0 + t) * NF + k4);
        *(float4*)(xs + t * XS_STRIDE + k4) = v;
    }
    __syncthreads();

    const int t  = tid & 15;
    const int cg = tid >> 4;
    float acc[16];
    #pragma unroll
    for (int c = 0; c < 16; c++) acc[c] = 0.f;

    for (int k0 = 0; k0 < NF; k0 += 32) {
        #pragma unroll
        for (int i = 0; i < 8; i++) {
            int j  = (tid >> 3) + i * 32;
            int kk = (tid & 7) * 4;
            float4 v = *(const float4*)(pw + (size_t)j * NF + k0 + kk);
            pws[(kk + 0) * PW_STRIDE + j] = v.x;
            pws[(kk + 1) * PW_STRIDE + j] = v.y;
            pws[(kk + 2) * PW_STRIDE + j] = v.z;
            pws[(kk + 3) * PW_STRIDE + j] = v.w;
        }
        __syncthreads();
        #pragma unroll
        for (int kk = 0; kk < 32; kk++) {
            float xv = xs[t * XS_STRIDE + k0 + kk];
            const float* wr = pws + kk * PW_STRIDE + cg * 16;
            #pragma unroll
            for (int c4 = 0; c4 < 4; c4++) {
                float4 w4 = *(const float4*)(wr + c4 * 4);
                acc[c4 * 4 + 0] += xv * w4.x;
                acc[c4 * 4 + 1] += xv * w4.y;
                acc[c4 * 4 + 2] += xv * w4.z;
                acc[c4 * 4 + 3] += xv * w4.w;
            }
        }
        __syncthreads();
    }

    #pragma unroll
    for (int c4 = 0; c4 < 4; c4++) {
        float4 hv;
        int jb = cg * 16 + c4 * 4;
        hv.x = acc[c4 * 4 + 0] + pb[jb + 0];
        hv.y = acc[c4 * 4 + 1] + pb[jb + 1];
        hv.z = acc[c4 * 4 + 2] + pb[jb + 2];
        hv.w = acc[c4 * 4 + 3] + pb[jb + 3];
        *(float4*)(hs + t * 256 + jb) = hv;
    }
    if (tid < 16) {
        const float* xr = xs + tid * XS_STRIDE;
        float s = 0.f;
        #pragma unroll 8
        for (int i = 0; i < NF / 4; i++) {
            float4 v = *(const float4*)(xr + i * 4);
            s += v.x * v.x + v.y * v.y + v.z * v.z + v.w * v.w;
        }
        xinv[tid] = 1.0f / fmaxf(sqrtf(s), 1e-8f);
    }
    __syncthreads();

    #pragma unroll
    for (int i = 0; i < 4; i++) {
        int p  = tid + 256 * i;
        int e  = p >> 4;
        int tt = p & 15;
        float dg = 0.f;
        const float* hr = hs + tt * 256;
        const float* er = emb + (size_t)e * NH;
        #pragma unroll 8
        for (int j = 0; j < NH / 4; j++) {
            float4 a = *(const float4*)(hr + j * 4);
            float4 b = *(const float4*)(er + j * 4);
            dg += a.x * b.x + a.y * b.y + a.z * b.z + a.w * b.w;
        }
        float gate = 1.0f / (1.0f + expf(-dg * 0.0625f));
        float ds = 0.f;
        const float* xr = xs + tt * XS_STRIDE;
        const float* fr = ef + (size_t)e * NF;
        #pragma unroll 8
        for (int j = 0; j < NF / 4; j++) {
            float4 a = *(const float4*)(xr + j * 4);
            float4 b = *(const float4*)(fr + j * 4);
            ds += a.x * b.x + a.y * b.y + a.z * b.z + a.w * b.w;
        }
        float sim = fmaxf(ds * xinv[tt] * g_efinv[e], 0.f);
        sc[tt * SC_STRIDE + e] = gate * sim * g_escale[e];
    }
    __syncthreads();

    if (tid < 16) {
        float* row = sc + tid * SC_STRIDE;
        float v[NK]; int ix[NK];
        #pragma unroll
        for (int k = 0; k < NK; k++) {
            float best = -1.f; int bi = 0;
            for (int e = 0; e < NE; e++) {
                float s = row[e];
                if (s > best) { best = s; bi = e; }
            }
            v[k] = best; ix[k] = bi; row[bi] = -1e30f;
        }
        float m = v[0], sum = 0.f, w[NK];
        #pragma unroll
        for (int k = 0; k < NK; k++) { w[k] = expf(v[k] - m); sum += w[k]; }
        float inv = 1.0f / sum;
        int tok = t0 + tid;
        #pragma unroll
        for (int k = 0; k < NK; k++) {
            int e = ix[k];
            int slot = atomicAdd(&g_counts[e], 1);
            g_tok[e * NB + slot] = tok;
            g_wt[e * NB + slot]  = w[k] * inv;
        }
    }
}

// ---------------- kernel 3: mma.sync bf16 hi/lo grouped MoE GEMM ----------
// CTA tile: M=128 gathered tokens x N=128 cols. K chunks of 32; each smem row
// is 128B = [32k hi | 32k lo] (full SW128 swizzle). Double-buffered stages of
// 32KB -> 66KB total smem -> 2 CTAs/SM (4 warps/SMSP) for latency hiding.
// 8 warps as 2(M) x 4(N); warp tile 64x32.
// 3 passes per k16: Ahi*Bhi + Ahi*Blo + Alo*Bhi, fp32 accum in regs.
#define MG_DATA    1024
#define MG_STAGE   32768
#define MG_BOFF    16384
#define MG_SMEM    (MG_DATA + 2 * MG_STAGE)   // 66560 bytes

__global__ void __launch_bounds__(256, 2)
moe_gemm_mma(const float* __restrict__ fb, float* __restrict__ out) {
    const int e    = blockIdx.y;
    const int n0   = blockIdx.x * 128;
    const int tile = blockIdx.z;
    const int cnt  = g_counts[e];
    if (tile * 128 >= cnt) return;

    extern __shared__ char smem[];
    const uint32_t sb = smem_to_u32(smem);
    const int tid = threadIdx.x;

    int*   toks = (int*)(smem);
    float* wts  = (float*)(smem + 512);
    {
        int s = tile * 128 + tid;
        if (tid < 128) {
            if (s < cnt) { toks[tid] = g_tok[e * NB + s]; wts[tid] = g_wt[e * NB + s]; }
            else         { toks[tid] = -1;                wts[tid] = 0.f; }
        }
    }
    __syncthreads();

    // staging: 2 threads/row; thread stages 4 x 16B. spart=0 -> hi half
    // (c16 0..3), spart=4 -> lo half (c16 4..7).
    const int srow  = tid >> 1;
    const int spart = (tid & 1) * 4;
    const int stok  = toks[srow];
    const int asz   = (stok >= 0) ? 16 : 0;
    const uint4* aSrc = (const uint4*)(((tid & 1) ? g_xlo : g_xhi) +
                                       (size_t)max(stok, 0) * NF);
    const uint4* bSrc = (const uint4*)(((tid & 1) ? g_wtlo : g_wthi) +
                                       ((size_t)e * NF + n0 + srow) * NF);
    const uint32_t srowb = sb + MG_DATA + srow * 128;
    const int      ssw   = (srow & 7) * 16;

    #define PREFETCH(c)                                                          \
    do {                                                                         \
        const uint32_t _d = srowb + ((c) & 1) * MG_STAGE;                        \
        _Pragma("unroll")                                                        \
        for (int j = 0; j < 4; j++) {                                            \
            const uint32_t off = (uint32_t)(((spart + j) * 16) ^ ssw);           \
            cp16(_d + off,           aSrc + (c) * 4 + j, asz);                   \
            cp16(_d + MG_BOFF + off, bSrc + (c) * 4 + j, 16);                    \
        }                                                                        \
    } while (0)

    PREFETCH(0);
    CP_COMMIT();

    const int lid = tid & 31;
    const int wid = tid >> 5;
    const int wm  = wid & 1;
    const int wn  = wid >> 1;

    float acc[4][4][4];
    #pragma unroll
    for (int mt = 0; mt < 4; mt++)
        #pragma unroll
        for (int nt = 0; nt < 4; nt++)
            #pragma unroll
            for (int q = 0; q < 4; q++) acc[mt][nt][q] = 0.f;

    const int fa_row = (lid & 15);
    const int fa_hi  = (lid >> 4);

    for (int c = 0; c < 16; c++) {
        if (c < 15) { PREFETCH(c + 1); CP_COMMIT(); CP_WAIT(1); }
        else        { CP_WAIT(0); }
        __syncthreads();

        const uint32_t baseA = sb + MG_DATA + (c & 1) * MG_STAGE;
        const uint32_t baseB = baseA + MG_BOFF;

        #pragma unroll
        for (int ks = 0; ks < 2; ks++) {
            const int ch = ks * 2 + fa_hi;       // hi half: c16 0..3
            const int cl = ch + 4;               // lo half: c16 4..7
            u32 ah[4][4], al[4][4];
            #pragma unroll
            for (int mt = 0; mt < 4; mt++) {
                const int r = wm * 64 + mt * 16 + fa_row;
                const uint32_t rb = r * 128, rs = (r & 7) * 16;
                ldm_x4(ah[mt][0], ah[mt][1], ah[mt][2], ah[mt][3],
                       baseA + rb + (uint32_t)((ch * 16) ^ rs));
                ldm_x4(al[mt][0], al[mt][1], al[mt][2], al[mt][3],
                       baseA + rb + (uint32_t)((cl * 16) ^ rs));
            }
            u32 bh[2][4], bl[2][4];
            #pragma unroll
            for (int p = 0; p < 2; p++) {
                const int r = wn * 32 + p * 16 + fa_row;
                const uint32_t rb = r * 128, rs = (r & 7) * 16;
                ldm_x4(bh[p][0], bh[p][1], bh[p][2], bh[p][3],
                       baseB + rb + (uint32_t)((ch * 16) ^ rs));
                ldm_x4(bl[p][0], bl[p][1], bl[p][2], bl[p][3],
                       baseB + rb + (uint32_t)((cl * 16) ^ rs));
            }
            #pragma unroll
            for (int mt = 0; mt < 4; mt++) {
                #pragma unroll
                for (int nt = 0; nt < 4; nt++) {
                    const int p = nt >> 1, h = nt & 1;
                    float* cc = acc[mt][nt];
                    mma_bf16(cc[0], cc[1], cc[2], cc[3],
                             ah[mt][0], ah[mt][1], ah[mt][2], ah[mt][3],
                             bh[p][h], bh[p][h + 2]);
                    mma_bf16(cc[0], cc[1], cc[2], cc[3],
                             ah[mt][0], ah[mt][1], ah[mt][2], ah[mt][3],
                             bl[p][h], bl[p][h + 2]);
                    mma_bf16(cc[0], cc[1], cc[2], cc[3],
                             al[mt][0], al[mt][1], al[mt][2], al[mt][3],
                             bh[p][h], bh[p][h + 2]);
                }
            }
        }
        __syncthreads();
    }

    const float* fbr = fb + (size_t)e * NF + n0;
    #pragma unroll
    for (int mt = 0; mt < 4; mt++) {
        const int r0 = wm * 64 + mt * 16 + (lid >> 2);
        const int r1 = r0 + 8;
        const int tok0 = toks[r0], tok1 = toks[r1];
        const float w0 = wts[r0],  w1 = wts[r1];
        #pragma unroll
        for (int nt = 0; nt < 4; nt++) {
            const int cb = wn * 32 + nt * 8 + (lid & 3) * 2;
            const float b0v = fbr[cb], b1v = fbr[cb + 1];
            const float* cc = acc[mt][nt];
            if (tok0 >= 0) {
                float* orow = out + (size_t)tok0 * NF + n0 + cb;
                atomicAdd(orow + 0, w0 * (cc[0] + b0v));
                atomicAdd(orow + 1, w0 * (cc[1] + b1v));
            }
            if (tok1 >= 0) {
                float* orow = out + (size_t)tok1 * NF + n0 + cb;
                atomicAdd(orow + 0, w1 * (cc[2] + b0v));
                atomicAdd(orow + 1, w1 * (cc[3] + b1v));
            }
        }
    }
}

// ---------------- launch ----------------
extern "C" void kernel_launch(void* const* d_in, const int* in_sizes, int n_in,
                              void* d_out, int out_size) {
    const float* feat  = (const float*)d_in[0];  // [B,F]
    const float* pw    = (const float*)d_in[1];  // [H,F]
    const float* pb    = (const float*)d_in[2];  // [H]
    const float* emb   = (const float*)d_in[3];  // [E,H]
    const float* ef    = (const float*)d_in[4];  // [E,F]
    const float* trust = (const float*)d_in[5];  // [E]
    const float* dt    = (const float*)d_in[6];  // [E]
    const float* fw    = (const float*)d_in[7];  // [E,F,F]
    const float* fb    = (const float*)d_in[8];  // [E,F]
    float* out = (float*)d_out;

    static bool attr_done = false;
    if (!attr_done) {
        cudaFuncSetAttribute(routing_kernel,
                             cudaFuncAttributeMaxDynamicSharedMemorySize, ROUT_SMEM);
        cudaFuncSetAttribute(moe_gemm_mma,
                             cudaFuncAttributeMaxDynamicSharedMemorySize, MG_SMEM);
        attr_done = true;
    }

    init_kernel<<<1, 64>>>(ef, trust, dt);
    zero_kernel<<<(NB * NF) / (256 * 4), 256>>>((float4*)out);
    convert_x<<<512, 256>>>(feat);
    convert_w<<<dim3(8, 8, NE), 256>>>(fw);
    routing_kernel<<<NB / 16, 256, ROUT_SMEM>>>(feat, pw, pb, emb, ef);
    moe_gemm_mma<<<dim3(4, NE, NB / 128), 256, MG_SMEM>>>(fb, out);
}

// round 7
// speedup vs baseline: 1.1263x; 1.0374x over previous
#include <cuda_runtime.h>
#include <cuda_bf16.h>
#include <math.h>
#include <stdint.h>

#define NB 2048   // batch
#define NF 512    // features
#define NH 256    // hidden
#define NE 64     // experts
#define NK 8      // top-k

typedef unsigned int u32;

// ---------------- scratch (no allocation allowed) ----------------
__device__ int   g_counts[NE];
__device__ int   g_off[NE];            // exclusive prefix of counts
__device__ int   g_tok[NE * NB];
__device__ float g_escale[NE];
__device__ float g_efinv[NE];
__device__ int   g_es[NB * NK];        // per (tok,k): (e<<12)|slot
__device__ float g_wtk[NB * NK];       // per (tok,k): softmax weight
__device__ float g_y[NB * NK * NF];    // 33.5MB staging: raw expert outputs+bias
// bf16 hi/lo split buffers
__device__ __nv_bfloat16 g_xhi[NB * NF];               // 2MB
__device__ __nv_bfloat16 g_xlo[NB * NF];               // 2MB
__device__ __nv_bfloat16 g_wthi[(size_t)NE * NF * NF]; // 33.5MB, layout [e][n][k]
__device__ __nv_bfloat16 g_wtlo[(size_t)NE * NF * NF]; // 33.5MB

// ---------------- PTX helpers (sm_80-era; valid on sm_100 target) ----------
__device__ __forceinline__ uint32_t smem_to_u32(const void* p) {
    uint32_t a;
    asm("{ .reg .u64 t; cvta.to.shared.u64 t, %1; cvt.u32.u64 %0, t; }"
        : "=r"(a) : "l"(p));
    return a;
}
__device__ __forceinline__ void cp16(uint32_t dst, const void* src, int srcsize) {
    asm volatile("cp.async.cg.shared.global [%0], [%1], 16, %2;"
                 :: "r"(dst), "l"(src), "r"(srcsize));
}
#define CP_COMMIT() asm volatile("cp.async.commit_group;" ::: "memory")
#define CP_WAIT(n)  asm volatile("cp.async.wait_group %0;" :: "n"(n) : "memory")

__device__ __forceinline__ void ldm_x4(u32& r0, u32& r1, u32& r2, u32& r3, u32 addr) {
    asm volatile("ldmatrix.sync.aligned.m8n8.x4.shared.b16 {%0,%1,%2,%3}, [%4];"
                 : "=r"(r0), "=r"(r1), "=r"(r2), "=r"(r3) : "r"(addr));
}
__device__ __forceinline__ void mma_bf16(float& c0, float& c1, float& c2, float& c3,
                                         u32 a0, u32 a1, u32 a2, u32 a3,
                                         u32 b0, u32 b1) {
    asm volatile("mma.sync.aligned.m16n8k16.row.col.f32.bf16.bf16.f32 "
                 "{%0,%1,%2,%3}, {%4,%5,%6,%7}, {%8,%9}, {%0,%1,%2,%3};"
                 : "+f"(c0), "+f"(c1), "+f"(c2), "+f"(c3)
                 : "r"(a0), "r"(a1), "r"(a2), "r"(a3), "r"(b0), "r"(b1));
}

// ---------------- bf16 hi/lo split ----------------
__device__ __forceinline__ void split2(float a, float b, u32& hi, u32& lo) {
    __nv_bfloat16 ah = __float2bfloat16(a), bh = __float2bfloat16(b);
    float ar = a - __bfloat162float(ah);
    float br = b - __bfloat162float(bh);
    __nv_bfloat16 al = __float2bfloat16(ar), bl = __float2bfloat16(br);
    hi = (u32)__bfloat16_as_ushort(ah) | ((u32)__bfloat16_as_ushort(bh) << 16);
    lo = (u32)__bfloat16_as_ushort(al) | ((u32)__bfloat16_as_ushort(bl) << 16);
}

// ---------------- kernel 0: per-expert scalars + count reset ----------------
__global__ void init_kernel(const float* __restrict__ ef,
                            const float* __restrict__ trust,
                            const float* __restrict__ dt) {
    int e = threadIdx.x;
    if (e < NE) {
        g_counts[e] = 0;
        g_escale[e] = trust[e] * fmaxf(0.1f, expf(-0.005f * dt[e]));
        const float4* r = (const float4*)(ef + e * NF);
        float s = 0.f;
        #pragma unroll 8
        for (int i = 0; i < NF / 4; i++) {
            float4 v = r[i];
            s += v.x * v.x + v.y * v.y + v.z * v.z + v.w * v.w;
        }
        g_efinv[e] = 1.0f / fmaxf(sqrtf(s), 1e-8f);
    }
}

// ---------------- kernel 0b: exclusive prefix over counts ------------------
__global__ void prefix_kernel() {
    if (threadIdx.x == 0) {
        int acc = 0;
        #pragma unroll
        for (int e = 0; e < NE; e++) { g_off[e] = acc; acc += g_counts[e]; }
    }
}

// ---------------- kernel 1b: convert X to bf16 hi/lo ----------------
__global__ void convert_x(const float* __restrict__ feat) {
    u32* xh = (u32*)g_xhi;
    u32* xl = (u32*)g_xlo;
    int p = blockIdx.x * 256 + threadIdx.x;
    const int npairs = NB * NF / 2;
    for (; p < npairs; p += gridDim.x * 256) {
        float2 v = *(const float2*)(feat + 2 * p);
        u32 hi, lo;
        split2(v.x, v.y, hi, lo);
        xh[p] = hi; xl[p] = lo;
    }
}

// ---------------- kernel 1c: convert + transpose W -> [e][n][k] bf16 hi/lo ----
__global__ void __launch_bounds__(256)
convert_w(const float* __restrict__ fw) {
    __shared__ float s[64][65];
    const int e  = blockIdx.z;
    const int k0 = blockIdx.x * 64;
    const int n0 = blockIdx.y * 64;
    const int tid = threadIdx.x;
    const float* src = fw + ((size_t)e * NF + k0) * NF + n0;
    #pragma unroll
    for (int i = 0; i < 16; i++) {
        int idx = tid + 256 * i;
        int kl = idx >> 6, nl = idx & 63;
        s[kl][nl] = src[(size_t)kl * NF + nl];
    }
    __syncthreads();
    u32* wh = (u32*)g_wthi;
    u32* wl = (u32*)g_wtlo;
    #pragma unroll
    for (int i = 0; i < 8; i++) {
        int idx = tid + 256 * i;
        int nl = idx >> 5;
        int kp = (idx & 31) * 2;
        float a = s[kp][nl], b = s[kp + 1][nl];
        u32 hi, lo;
        split2(a, b, hi, lo);
        size_t off = (((size_t)e * NF + n0 + nl) * NF + k0 + kp) >> 1;
        wh[off] = hi; wl[off] = lo;
    }
}

// ---------------- kernel 2: routing (R4 monolith, known-good) --------------
#define XS_STRIDE 516
#define PW_STRIDE 260
#define SC_STRIDE 68
#define ROUT_SMEM ((16 * XS_STRIDE + 32 * PW_STRIDE) * 4)

__global__ void __launch_bounds__(256, 1)
routing_kernel(const float* __restrict__ feat, const float* __restrict__ pw,
               const float* __restrict__ pb,   const float* __restrict__ emb,
               const float* __restrict__ ef) {
    extern __shared__ float sm[];
    float* xs   = sm;
    float* buf  = sm + 16 * XS_STRIDE;
    float* pws  = buf;
    float* hs   = buf;
    float* sc   = buf + 16 * 256;
    float* xinv = buf + 16 * 256 + 16 * SC_STRIDE;

    const int tid = threadIdx.x;
    const int t0  = blockIdx.x * 16;

    #pragma unroll
    for (int i = 0; i < 8; i++) {
        int idx = tid + 256 * i;
        int t   = idx >> 7;
        int k4  = (idx & 127) * 4;
        float4 v = *(const float4*)(feat + (size_t)(t0 + t) * NF + k4);
        *(float4*)(xs + t * XS_STRIDE + k4) = v;
    }
    __syncthreads();

    const int t  = tid & 15;
    const int cg = tid >> 4;
    float acc[16];
    #pragma unroll
    for (int c = 0; c < 16; c++) acc[c] = 0.f;

    for (int k0 = 0; k0 < NF; k0 += 32) {
        #pragma unroll
        for (int i = 0; i < 8; i++) {
            int j  = (tid >> 3) + i * 32;
            int kk = (tid & 7) * 4;
            float4 v = *(const float4*)(pw + (size_t)j * NF + k0 + kk);
            pws[(kk + 0) * PW_STRIDE + j] = v.x;
            pws[(kk + 1) * PW_STRIDE + j] = v.y;
            pws[(kk + 2) * PW_STRIDE + j] = v.z;
            pws[(kk + 3) * PW_STRIDE + j] = v.w;
        }
        __syncthreads();
        #pragma unroll
        for (int kk = 0; kk < 32; kk++) {
            float xv = xs[t * XS_STRIDE + k0 + kk];
            const float* wr = pws + kk * PW_STRIDE + cg * 16;
            #pragma unroll
            for (int c4 = 0; c4 < 4; c4++) {
                float4 w4 = *(const float4*)(wr + c4 * 4);
                acc[c4 * 4 + 0] += xv * w4.x;
                acc[c4 * 4 + 1] += xv * w4.y;
                acc[c4 * 4 + 2] += xv * w4.z;
                acc[c4 * 4 + 3] += xv * w4.w;
            }
        }
        __syncthreads();
    }

    #pragma unroll
    for (int c4 = 0; c4 < 4; c4++) {
        float4 hv;
        int jb = cg * 16 + c4 * 4;
        hv.x = acc[c4 * 4 + 0] + pb[jb + 0];
        hv.y = acc[c4 * 4 + 1] + pb[jb + 1];
        hv.z = acc[c4 * 4 + 2] + pb[jb + 2];
        hv.w = acc[c4 * 4 + 3] + pb[jb + 3];
        *(float4*)(hs + t * 256 + jb) = hv;
    }
    if (tid < 16) {
        const float* xr = xs + tid * XS_STRIDE;
        float s = 0.f;
        #pragma unroll 8
        for (int i = 0; i < NF / 4; i++) {
            float4 v = *(const float4*)(xr + i * 4);
            s += v.x * v.x + v.y * v.y + v.z * v.z + v.w * v.w;
        }
        xinv[tid] = 1.0f / fmaxf(sqrtf(s), 1e-8f);
    }
    __syncthreads();

    #pragma unroll
    for (int i = 0; i < 4; i++) {
        int p  = tid + 256 * i;
        int e  = p >> 4;
        int tt = p & 15;
        float dg = 0.f;
        const float* hr = hs + tt * 256;
        const float* er = emb + (size_t)e * NH;
        #pragma unroll 8
        for (int j = 0; j < NH / 4; j++) {
            float4 a = *(const float4*)(hr + j * 4);
            float4 b = *(const float4*)(er + j * 4);
            dg += a.x * b.x + a.y * b.y + a.z * b.z + a.w * b.w;
        }
        float gate = 1.0f / (1.0f + expf(-dg * 0.0625f));
        float ds = 0.f;
        const float* xr = xs + tt * XS_STRIDE;
        const float* fr = ef + (size_t)e * NF;
        #pragma unroll 8
        for (int j = 0; j < NF / 4; j++) {
            float4 a = *(const float4*)(xr + j * 4);
            float4 b = *(const float4*)(fr + j * 4);
            ds += a.x * b.x + a.y * b.y + a.z * b.z + a.w * b.w;
        }
        float sim = fmaxf(ds * xinv[tt] * g_efinv[e], 0.f);
        sc[tt * SC_STRIDE + e] = gate * sim * g_escale[e];
    }
    __syncthreads();

    if (tid < 16) {
        float* row = sc + tid * SC_STRIDE;
        float v[NK]; int ix[NK];
        #pragma unroll
        for (int k = 0; k < NK; k++) {
            float best = -1.f; int bi = 0;
            for (int e = 0; e < NE; e++) {
                float s = row[e];
                if (s > best) { best = s; bi = e; }
            }
            v[k] = best; ix[k] = bi; row[bi] = -1e30f;
        }
        float m = v[0], sum = 0.f, w[NK];
        #pragma unroll
        for (int k = 0; k < NK; k++) { w[k] = expf(v[k] - m); sum += w[k]; }
        float inv = 1.0f / sum;
        int tok = t0 + tid;
        #pragma unroll
        for (int k = 0; k < NK; k++) {
            int e = ix[k];
            int slot = atomicAdd(&g_counts[e], 1);
            g_tok[e * NB + slot] = tok;
            g_es[tok * NK + k]  = (e << 12) | slot;
            g_wtk[tok * NK + k] = w[k] * inv;
        }
    }
}

// ---------------- kernel 3: mma.sync bf16 hi/lo grouped MoE GEMM ----------
// R4 mainloop (K chunks of 64, 132KB smem, 1 CTA/SM). Epilogue writes raw
// (acc + bias) rows to dense g_y staging (no atomics), rows at g_off[e]+slot.
#define MG_DATA    1024
#define MG_BUF     65536
#define MG_AHI     0
#define MG_ALO     16384
#define MG_BHI     32768
#define MG_BLO     49152
#define MG_SMEM    (MG_DATA + 2 * MG_BUF)   // 132096 bytes

__global__ void __launch_bounds__(256, 1)
moe_gemm_mma(const float* __restrict__ fb) {
    const int e    = blockIdx.y;
    const int n0   = blockIdx.x * 128;
    const int tile = blockIdx.z;
    const int cnt  = g_counts[e];
    if (tile * 128 >= cnt) return;

    extern __shared__ char smem[];
    const uint32_t sb = smem_to_u32(smem);
    const int tid = threadIdx.x;

    int* toks = (int*)(smem);
    {
        int s = tile * 128 + tid;
        if (tid < 128)
            toks[tid] = (s < cnt) ? g_tok[e * NB + s] : -1;
    }
    __syncthreads();

    const int srow  = tid >> 1;
    const int spart = (tid & 1) * 4;
    const int stok  = toks[srow];
    const int asz   = (stok >= 0) ? 16 : 0;
    const uint4* aH = (const uint4*)(g_xhi + (size_t)max(stok, 0) * NF);
    const uint4* aL = (const uint4*)(g_xlo + (size_t)max(stok, 0) * NF);
    const uint4* bH = (const uint4*)(g_wthi + ((size_t)e * NF + n0 + srow) * NF);
    const uint4* bL = (const uint4*)(g_wtlo + ((size_t)e * NF + n0 + srow) * NF);
    const uint32_t srowb = sb + MG_DATA + srow * 128;
    const int      ssw   = (srow & 7) * 16;

    #define PREFETCH(c)                                                          \
    do {                                                                         \
        const int _buf = (c) & 1;                                                \
        const uint32_t _d = srowb + _buf * MG_BUF;                               \
        _Pragma("unroll")                                                        \
        for (int j = 0; j < 4; j++) {                                            \
            const int c16 = spart + j;                                           \
            const uint32_t off = (uint32_t)((c16 * 16) ^ ssw);                   \
            cp16(_d + MG_AHI + off, aH + (c) * 8 + c16, asz);                    \
            cp16(_d + MG_ALO + off, aL + (c) * 8 + c16, asz);                    \
            cp16(_d + MG_BHI + off, bH + (c) * 8 + c16, 16);                     \
            cp16(_d + MG_BLO + off, bL + (c) * 8 + c16, 16);                     \
        }                                                                        \
    } while (0)

    PREFETCH(0);
    CP_COMMIT();

    const int lid = tid & 31;
    const int wid = tid >> 5;
    const int wm  = wid & 1;
    const int wn  = wid >> 1;

    float acc[4][4][4];
    #pragma unroll
    for (int mt = 0; mt < 4; mt++)
        #pragma unroll
        for (int nt = 0; nt < 4; nt++)
            #pragma unroll
            for (int q = 0; q < 4; q++) acc[mt][nt][q] = 0.f;

    const int fa_row = (lid & 15);
    const int fa_hi  = (lid >> 4);

    for (int c = 0; c < 8; c++) {
        if (c < 7) { PREFETCH(c + 1); CP_COMMIT(); CP_WAIT(1); }
        else       { CP_WAIT(0); }
        __syncthreads();

        const uint32_t base = sb + MG_DATA + (c & 1) * MG_BUF;

        #pragma unroll
        for (int ks = 0; ks < 4; ks++) {
            const int c16 = ks * 2 + fa_hi;
            u32 ah[4][4], al[4][4];
            #pragma unroll
            for (int mt = 0; mt < 4; mt++) {
                const int r = wm * 64 + mt * 16 + fa_row;
                const uint32_t off = r * 128 + (uint32_t)((c16 * 16) ^ ((r & 7) * 16));
                ldm_x4(ah[mt][0], ah[mt][1], ah[mt][2], ah[mt][3], base + MG_AHI + off);
                ldm_x4(al[mt][0], al[mt][1], al[mt][2], al[mt][3], base + MG_ALO + off);
            }
            u32 bh[2][4], bl[2][4];
            #pragma unroll
            for (int p = 0; p < 2; p++) {
                const int r = wn * 32 + p * 16 + fa_row;
                const uint32_t off = r * 128 + (uint32_t)((c16 * 16) ^ ((r & 7) * 16));
                ldm_x4(bh[p][0], bh[p][1], bh[p][2], bh[p][3], base + MG_BHI + off);
                ldm_x4(bl[p][0], bl[p][1], bl[p][2], bl[p][3], base + MG_BLO + off);
            }
            #pragma unroll
            for (int mt = 0; mt < 4; mt++) {
                #pragma unroll
                for (int nt = 0; nt < 4; nt++) {
                    const int p = nt >> 1, h = nt & 1;
                    float* cc = acc[mt][nt];
                    mma_bf16(cc[0], cc[1], cc[2], cc[3],
                             ah[mt][0], ah[mt][1], ah[mt][2], ah[mt][3],
                             bh[p][h], bh[p][h + 2]);
                    mma_bf16(cc[0], cc[1], cc[2], cc[3],
                             ah[mt][0], ah[mt][1], ah[mt][2], ah[mt][3],
                             bl[p][h], bl[p][h + 2]);
                    mma_bf16(cc[0], cc[1], cc[2], cc[3],
                             al[mt][0], al[mt][1], al[mt][2], al[mt][3],
                             bh[p][h], bh[p][h + 2]);
                }
            }
        }
        __syncthreads();
    }

    // ---- epilogue: y[off[e]+slot][n] = acc + bias (plain STG.64) ----
    const float* fbr  = fb + (size_t)e * NF + n0;
    const int rowbase = g_off[e] + tile * 128;
    #pragma unroll
    for (int mt = 0; mt < 4; mt++) {
        const int r0 = wm * 64 + mt * 16 + (lid >> 2);
        const int r1 = r0 + 8;
        const bool v0 = (toks[r0] >= 0);
        const bool v1 = (toks[r1] >= 0);
        #pragma unroll
        for (int nt = 0; nt < 4; nt++) {
            const int cb = wn * 32 + nt * 8 + (lid & 3) * 2;
            const float b0v = fbr[cb], b1v = fbr[cb + 1];
            const float* cc = acc[mt][nt];
            if (v0) {
                float2 o = make_float2(cc[0] + b0v, cc[1] + b1v);
                *(float2*)(g_y + (size_t)(rowbase + r0) * NF + n0 + cb) = o;
            }
            if (v1) {
                float2 o = make_float2(cc[2] + b0v, cc[3] + b1v);
                *(float2*)(g_y + (size_t)(rowbase + r1) * NF + n0 + cb) = o;
            }
        }
    }
}

// ---------------- kernel 4: gather out[tok] = sum_k w_k * y[row_k] --------
__global__ void __launch_bounds__(256)
gather_kernel(float* __restrict__ out) {
    const int tid = threadIdx.x;
    const int tok = blockIdx.x * 4 + (tid >> 6);
    const int f0  = (tid & 63) * 8;

    int   rows[NK];
    float ws[NK];
    #pragma unroll
    for (int k = 0; k < NK; k++) {
        int es  = g_es[tok * NK + k];
        rows[k] = g_off[es >> 12] + (es & 4095);
        ws[k]   = g_wtk[tok * NK + k];
    }
    float4 a0 = make_float4(0.f, 0.f, 0.f, 0.f);
    float4 a1 = a0;
    #pragma unroll
    for (int k = 0; k < NK; k++) {
        const float4* yr = (const float4*)(g_y + (size_t)rows[k] * NF + f0);
        float4 y0 = yr[0], y1 = yr[1];
        float w = ws[k];
        a0.x += w * y0.x; a0.y += w * y0.y; a0.z += w * y0.z; a0.w += w * y0.w;
        a1.x += w * y1.x; a1.y += w * y1.y; a1.z += w * y1.z; a1.w += w * y1.w;
    }
    float4* orow = (float4*)(out + (size_t)tok * NF + f0);
    orow[0] = a0;
    orow[1] = a1;
}

// ---------------- launch ----------------
extern "C" void kernel_launch(void* const* d_in, const int* in_sizes, int n_in,
                              void* d_out, int out_size) {
    const float* feat  = (const float*)d_in[0];  // [B,F]
    const float* pw    = (const float*)d_in[1];  // [H,F]
    const float* pb    = (const float*)d_in[2];  // [H]
    const float* emb   = (const float*)d_in[3];  // [E,H]
    const float* ef    = (const float*)d_in[4];  // [E,F]
    const float* trust = (const float*)d_in[5];  // [E]
    const float* dt    = (const float*)d_in[6];  // [E]
    const float* fw    = (const float*)d_in[7];  // [E,F,F]
    const float* fb    = (const float*)d_in[8];  // [E,F]
    float* out = (float*)d_out;

    static bool attr_done = false;
    if (!attr_done) {
        cudaFuncSetAttribute(routing_kernel,
                             cudaFuncAttributeMaxDynamicSharedMemorySize, ROUT_SMEM);
        cudaFuncSetAttribute(moe_gemm_mma,
                             cudaFuncAttributeMaxDynamicSharedMemorySize, MG_SMEM);
        attr_done = true;
    }

    init_kernel<<<1, 64>>>(ef, trust, dt);
    convert_x<<<512, 256>>>(feat);
    convert_w<<<dim3(8, 8, NE), 256>>>(fw);
    routing_kernel<<<NB / 16, 256, ROUT_SMEM>>>(feat, pw, pb, emb, ef);
    prefix_kernel<<<1, 32>>>();
    moe_gemm_mma<<<dim3(4, NE, NB / 128), 256, MG_SMEM>>>(fb);
    gather_kernel<<<NB / 4, 256>>>(out);
}

// round 8
// speedup vs baseline: 1.3093x; 1.1625x over previous
#include <cuda_runtime.h>
#include <cuda_bf16.h>
#include <math.h>
#include <stdint.h>

#define NB 2048   // batch
#define NF 512    // features
#define NH 256    // hidden
#define NE 64     // experts
#define NK 8      // top-k

typedef unsigned int u32;

// ---------------- scratch (no allocation allowed) ----------------
__device__ int   g_counts[NE];
__device__ int   g_tok[NE * NB];
__device__ float g_wt[NE * NB];
__device__ float g_escale[NE];
__device__ float g_efinv[NE];
// bf16 hi/lo split buffers
__device__ __nv_bfloat16 g_xhi[NB * NF];               // 2MB
__device__ __nv_bfloat16 g_xlo[NB * NF];               // 2MB
__device__ __nv_bfloat16 g_wthi[(size_t)NE * NF * NF]; // 33.5MB, layout [e][n][k]
__device__ __nv_bfloat16 g_wtlo[(size_t)NE * NF * NF]; // 33.5MB

// ---------------- PTX helpers (sm_80-era; valid on sm_100 target) ----------
__device__ __forceinline__ uint32_t smem_to_u32(const void* p) {
    uint32_t a;
    asm("{ .reg .u64 t; cvta.to.shared.u64 t, %1; cvt.u32.u64 %0, t; }"
        : "=r"(a) : "l"(p));
    return a;
}
__device__ __forceinline__ void cp16(uint32_t dst, const void* src, int srcsize) {
    asm volatile("cp.async.cg.shared.global [%0], [%1], 16, %2;"
                 :: "r"(dst), "l"(src), "r"(srcsize));
}
#define CP_COMMIT() asm volatile("cp.async.commit_group;" ::: "memory")
#define CP_WAIT(n)  asm volatile("cp.async.wait_group %0;" :: "n"(n) : "memory")

__device__ __forceinline__ void ldm_x4(u32& r0, u32& r1, u32& r2, u32& r3, u32 addr) {
    asm volatile("ldmatrix.sync.aligned.m8n8.x4.shared.b16 {%0,%1,%2,%3}, [%4];"
                 : "=r"(r0), "=r"(r1), "=r"(r2), "=r"(r3) : "r"(addr));
}
__device__ __forceinline__ void mma_bf16(float& c0, float& c1, float& c2, float& c3,
                                         u32 a0, u32 a1, u32 a2, u32 a3,
                                         u32 b0, u32 b1) {
    asm volatile("mma.sync.aligned.m16n8k16.row.col.f32.bf16.bf16.f32 "
                 "{%0,%1,%2,%3}, {%4,%5,%6,%7}, {%8,%9}, {%0,%1,%2,%3};"
                 : "+f"(c0), "+f"(c1), "+f"(c2), "+f"(c3)
                 : "r"(a0), "r"(a1), "r"(a2), "r"(a3), "r"(b0), "r"(b1));
}

// ---------------- bf16 hi/lo split ----------------
__device__ __forceinline__ void split2(float a, float b, u32& hi, u32& lo) {
    __nv_bfloat16 ah = __float2bfloat16(a), bh = __float2bfloat16(b);
    float ar = a - __bfloat162float(ah);
    float br = b - __bfloat162float(bh);
    __nv_bfloat16 al = __float2bfloat16(ar), bl = __float2bfloat16(br);
    hi = (u32)__bfloat16_as_ushort(ah) | ((u32)__bfloat16_as_ushort(bh) << 16);
    lo = (u32)__bfloat16_as_ushort(al) | ((u32)__bfloat16_as_ushort(bl) << 16);
}

// ---------------- kernel 0: per-expert scalars + count reset ----------------
__global__ void init_kernel(const float* __restrict__ ef,
                            const float* __restrict__ trust,
                            const float* __restrict__ dt) {
    int e = threadIdx.x;
    if (e < NE) {
        g_counts[e] = 0;
        g_escale[e] = trust[e] * fmaxf(0.1f, expf(-0.005f * dt[e]));
        const float4* r = (const float4*)(ef + e * NF);
        float s = 0.f;
        #pragma unroll 8
        for (int i = 0; i < NF / 4; i++) {
            float4 v = r[i];
            s += v.x * v.x + v.y * v.y + v.z * v.z + v.w * v.w;
        }
        g_efinv[e] = 1.0f / fmaxf(sqrtf(s), 1e-8f);
    }
}

// ---------------- kernel 1: zero output ----------------
__global__ void zero_kernel(float4* __restrict__ out) {
    out[blockIdx.x * 256 + threadIdx.x] = make_float4(0.f, 0.f, 0.f, 0.f);
}

// ---------------- kernel 1b: convert X to bf16 hi/lo ----------------
__global__ void convert_x(const float* __restrict__ feat) {
    u32* xh = (u32*)g_xhi;
    u32* xl = (u32*)g_xlo;
    int p = blockIdx.x * 256 + threadIdx.x;
    const int npairs = NB * NF / 2;
    for (; p < npairs; p += gridDim.x * 256) {
        float2 v = *(const float2*)(feat + 2 * p);
        u32 hi, lo;
        split2(v.x, v.y, hi, lo);
        xh[p] = hi; xl[p] = lo;
    }
}

// ---------------- kernel 1c: convert + transpose W -> [e][n][k] bf16 hi/lo ----
__global__ void __launch_bounds__(256)
convert_w(const float* __restrict__ fw) {
    __shared__ float s[64][65];
    const int e  = blockIdx.z;
    const int k0 = blockIdx.x * 64;
    const int n0 = blockIdx.y * 64;
    const int tid = threadIdx.x;
    const float* src = fw + ((size_t)e * NF + k0) * NF + n0;
    #pragma unroll
    for (int i = 0; i < 16; i++) {
        int idx = tid + 256 * i;
        int kl = idx >> 6, nl = idx & 63;
        s[kl][nl] = src[(size_t)kl * NF + nl];
    }
    __syncthreads();
    u32* wh = (u32*)g_wthi;
    u32* wl = (u32*)g_wtlo;
    #pragma unroll
    for (int i = 0; i < 8; i++) {
        int idx = tid + 256 * i;
        int nl = idx >> 5;
        int kp = (idx & 31) * 2;
        float a = s[kp][nl], b = s[kp + 1][nl];
        u32 hi, lo;
        split2(a, b, hi, lo);
        size_t off = (((size_t)e * NF + n0 + nl) * NF + k0 + kp) >> 1;
        wh[off] = hi; wl[off] = lo;
    }
}

// ---------------- kernel 2: routing v3 (8 tokens/CTA, 256 CTAs) ------------
// All-fp32. Phase 1: h GEMM via smem tiles. Phase 2: gate/sim as smem GEMMs
// with staged emb/ef tiles (no global-latency dot chains). 59KB smem -> 2 CTAs/SM.
#define XS_STRIDE 516
#define PW_STRIDE 260
#define HS_STRIDE 260
#define ES_STRIDE 68
#define SC_STRIDE 68
#define R_XS   0
#define R_PWS  (8 * XS_STRIDE)                       // 4128
#define R_HS   (R_PWS + 32 * PW_STRIDE)              // 12448
#define R_SC   (R_HS + 8 * HS_STRIDE)                // 14528
#define R_XINV (R_SC + 8 * SC_STRIDE)                // 15072
#define ROUT_SMEM ((R_XINV + 16) * 4)                // ~60.4KB

__global__ void __launch_bounds__(256, 2)
routing_kernel(const float* __restrict__ feat, const float* __restrict__ pw,
               const float* __restrict__ pb,   const float* __restrict__ emb,
               const float* __restrict__ ef) {
    extern __shared__ float sm[];
    float* xs   = sm + R_XS;
    float* pws  = sm + R_PWS;    // also reused as est[] in phase 2
    float* hs   = sm + R_HS;
    float* sc   = sm + R_SC;
    float* xinv = sm + R_XINV;

    const int tid = threadIdx.x;
    const int t0  = blockIdx.x * 8;

    // ---- load X tile [8][512] ----
    const float4* feat4 = (const float4*)feat;
    #pragma unroll
    for (int i = 0; i < 4; i++) {
        int idx = tid + 256 * i;            // 0..1023
        int t   = idx >> 7;                 // 0..7
        int q   = idx & 127;
        float4 v = feat4[(size_t)(t0 + t) * 128 + q];
        *(float4*)(xs + t * XS_STRIDE + q * 4) = v;
    }

    // ---- phase 1: h[8][256] = X @ pw^T ----
    const int t  = tid & 7;
    const int cg = tid >> 3;                // 0..31, cols cg*8..+7
    float acc[8];
    #pragma unroll
    for (int c = 0; c < 8; c++) acc[c] = 0.f;

    const float4* pw4 = (const float4*)pw;
    for (int k0 = 0; k0 < NF; k0 += 32) {
        #pragma unroll
        for (int i = 0; i < 8; i++) {
            int j  = (tid >> 3) + i * 32;
            int kk = (tid & 7) * 4;
            float4 v = pw4[(size_t)j * 128 + (k0 >> 2) + (tid & 7)];
            pws[(kk + 0) * PW_STRIDE + j] = v.x;
            pws[(kk + 1) * PW_STRIDE + j] = v.y;
            pws[(kk + 2) * PW_STRIDE + j] = v.z;
            pws[(kk + 3) * PW_STRIDE + j] = v.w;
        }
        __syncthreads();
        #pragma unroll
        for (int kk = 0; kk < 32; kk++) {
            float xv = xs[t * XS_STRIDE + k0 + kk];
            const float* wr = pws + kk * PW_STRIDE + cg * 8;
            float4 w0 = *(const float4*)(wr);
            float4 w1 = *(const float4*)(wr + 4);
            acc[0] += xv * w0.x; acc[1] += xv * w0.y;
            acc[2] += xv * w0.z; acc[3] += xv * w0.w;
            acc[4] += xv * w1.x; acc[5] += xv * w1.y;
            acc[6] += xv * w1.z; acc[7] += xv * w1.w;
        }
        __syncthreads();
    }

    // ---- write h (+bias) ----
    {
        float4 b0 = *(const float4*)(pb + cg * 8);
        float4 b1 = *(const float4*)(pb + cg * 8 + 4);
        float* hr = hs + t * HS_STRIDE + cg * 8;
        hr[0] = acc[0] + b0.x; hr[1] = acc[1] + b0.y;
        hr[2] = acc[2] + b0.z; hr[3] = acc[3] + b0.w;
        hr[4] = acc[4] + b1.x; hr[5] = acc[5] + b1.y;
        hr[6] = acc[6] + b1.z; hr[7] = acc[7] + b1.w;
    }
    // ---- per-token inverse norm ----
    if (tid < 8) {
        const float* xr = xs + tid * XS_STRIDE;
        float s = 0.f;
        #pragma unroll 8
        for (int i = 0; i < NF / 4; i++) {
            float4 v = *(const float4*)(xr + i * 4);
            s += v.x * v.x + v.y * v.y + v.z * v.z + v.w * v.w;
        }
        xinv[tid] = 1.0f / fmaxf(sqrtf(s), 1e-8f);
    }

    // ---- phase 2: G = h @ emb^T (K=256) and S = X @ ef^T (K=512) ----
    float* est = pws;                        // reuse buffer, est[kk][e], stride 68
    const int eg = tid >> 3;                 // 0..31 -> experts eg*2, eg*2+1
    const int t2 = tid & 7;
    float g2[2] = {0.f, 0.f};
    float s2[2] = {0.f, 0.f};

    const float4* emb4 = (const float4*)emb;
    for (int k0 = 0; k0 < NH; k0 += 32) {
        __syncthreads();   // protect est from previous readers
        #pragma unroll
        for (int i = 0; i < 2; i++) {
            int idx = tid + 256 * i;        // 0..511
            int e   = idx >> 3;             // 0..63
            int kq  = idx & 7;
            float4 v = emb4[(size_t)e * 64 + (k0 >> 2) + kq];
            est[(kq * 4 + 0) * ES_STRIDE + e] = v.x;
            est[(kq * 4 + 1) * ES_STRIDE + e] = v.y;
            est[(kq * 4 + 2) * ES_STRIDE + e] = v.z;
            est[(kq * 4 + 3) * ES_STRIDE + e] = v.w;
        }
        __syncthreads();
        #pragma unroll
        for (int kk = 0; kk < 32; kk++) {
            float hv = hs[t2 * HS_STRIDE + k0 + kk];
            float2 w = *(const float2*)(est + kk * ES_STRIDE + eg * 2);
            g2[0] += hv * w.x; g2[1] += hv * w.y;
        }
    }

    const float4* ef4 = (const float4*)ef;
    for (int k0 = 0; k0 < NF; k0 += 32) {
        __syncthreads();
        #pragma unroll
        for (int i = 0; i < 2; i++) {
            int idx = tid + 256 * i;
            int e   = idx >> 3;
            int kq  = idx & 7;
            float4 v = ef4[(size_t)e * 128 + (k0 >> 2) + kq];
            est[(kq * 4 + 0) * ES_STRIDE + e] = v.x;
            est[(kq * 4 + 1) * ES_STRIDE + e] = v.y;
            est[(kq * 4 + 2) * ES_STRIDE + e] = v.z;
            est[(kq * 4 + 3) * ES_STRIDE + e] = v.w;
        }
        __syncthreads();
        #pragma unroll
        for (int kk = 0; kk < 32; kk++) {
            float xv = xs[t2 * XS_STRIDE + k0 + kk];
            float2 w = *(const float2*)(est + kk * ES_STRIDE + eg * 2);
            s2[0] += xv * w.x; s2[1] += xv * w.y;
        }
    }
    __syncthreads();

    // ---- score = gate * sim * escale ----
    #pragma unroll
    for (int c = 0; c < 2; c++) {
        int e = eg * 2 + c;
        float gate = 1.0f / (1.0f + expf(-g2[c] * 0.0625f));
        float sim  = fmaxf(s2[c] * xinv[t2] * g_efinv[e], 0.f);
        sc[t2 * SC_STRIDE + e] = gate * sim * g_escale[e];
    }
    __syncthreads();

    // ---- top-8 + softmax + scatter ----
    if (tid < 8) {
        float* row = sc + tid * SC_STRIDE;
        float v[NK]; int ix[NK];
        #pragma unroll
        for (int k = 0; k < NK; k++) {
            float best = -1.f; int bi = 0;
            for (int e = 0; e < NE; e++) {
                float s = row[e];
                if (s > best) { best = s; bi = e; }
            }
            v[k] = best; ix[k] = bi; row[bi] = -1e30f;
        }
        float m = v[0], sum = 0.f, w[NK];
        #pragma unroll
        for (int k = 0; k < NK; k++) { w[k] = expf(v[k] - m); sum += w[k]; }
        float inv = 1.0f / sum;
        int tok = t0 + tid;
        #pragma unroll
        for (int k = 0; k < NK; k++) {
            int e = ix[k];
            int slot = atomicAdd(&g_counts[e], 1);
            g_tok[e * NB + slot] = tok;
            g_wt[e * NB + slot]  = w[k] * inv;
        }
    }
}

// ---------------- kernel 3: mma.sync bf16 hi/lo grouped MoE GEMM (R4) ------
#define MG_DATA    1024
#define MG_BUF     65536
#define MG_AHI     0
#define MG_ALO     16384
#define MG_BHI     32768
#define MG_BLO     49152
#define MG_SMEM    (MG_DATA + 2 * MG_BUF)   // 132096 bytes

__global__ void __launch_bounds__(256, 1)
moe_gemm_mma(const float* __restrict__ fb, float* __restrict__ out) {
    const int e    = blockIdx.y;
    const int n0   = blockIdx.x * 128;
    const int tile = blockIdx.z;
    const int cnt  = g_counts[e];
    if (tile * 128 >= cnt) return;

    extern __shared__ char smem[];
    const uint32_t sb = smem_to_u32(smem);
    const int tid = threadIdx.x;

    int*   toks = (int*)(smem);
    float* wts  = (float*)(smem + 512);
    {
        int s = tile * 128 + tid;
        if (tid < 128) {
            if (s < cnt) { toks[tid] = g_tok[e * NB + s]; wts[tid] = g_wt[e * NB + s]; }
            else         { toks[tid] = -1;                wts[tid] = 0.f; }
        }
    }
    __syncthreads();

    const int srow  = tid >> 1;
    const int spart = (tid & 1) * 4;
    const int stok  = toks[srow];
    const int asz   = (stok >= 0) ? 16 : 0;
    const uint4* aH = (const uint4*)(g_xhi + (size_t)max(stok, 0) * NF);
    const uint4* aL = (const uint4*)(g_xlo + (size_t)max(stok, 0) * NF);
    const uint4* bH = (const uint4*)(g_wthi + ((size_t)e * NF + n0 + srow) * NF);
    const uint4* bL = (const uint4*)(g_wtlo + ((size_t)e * NF + n0 + srow) * NF);
    const uint32_t srowb = sb + MG_DATA + srow * 128;
    const int      ssw   = (srow & 7) * 16;

    #define PREFETCH(c)                                                          \
    do {                                                                         \
        const int _buf = (c) & 1;                                                \
        const uint32_t _d = srowb + _buf * MG_BUF;                               \
        _Pragma("unroll")                                                        \
        for (int j = 0; j < 4; j++) {                                            \
            const int c16 = spart + j;                                           \
            const uint32_t off = (uint32_t)((c16 * 16) ^ ssw);                   \
            cp16(_d + MG_AHI + off, aH + (c) * 8 + c16, asz);                    \
            cp16(_d + MG_ALO + off, aL + (c) * 8 + c16, asz);                    \
            cp16(_d + MG_BHI + off, bH + (c) * 8 + c16, 16);                     \
            cp16(_d + MG_BLO + off, bL + (c) * 8 + c16, 16);                     \
        }                                                                        \
    } while (0)

    PREFETCH(0);
    CP_COMMIT();

    const int lid = tid & 31;
    const int wid = tid >> 5;
    const int wm  = wid & 1;
    const int wn  = wid >> 1;

    float acc[4][4][4];
    #pragma unroll
    for (int mt = 0; mt < 4; mt++)
        #pragma unroll
        for (int nt = 0; nt < 4; nt++)
            #pragma unroll
            for (int q = 0; q < 4; q++) acc[mt][nt][q] = 0.f;

    const int fa_row = (lid & 15);
    const int fa_hi  = (lid >> 4);

    for (int c = 0; c < 8; c++) {
        if (c < 7) { PREFETCH(c + 1); CP_COMMIT(); CP_WAIT(1); }
        else       { CP_WAIT(0); }
        __syncthreads();

        const uint32_t base = sb + MG_DATA + (c & 1) * MG_BUF;

        #pragma unroll
        for (int ks = 0; ks < 4; ks++) {
            const int c16 = ks * 2 + fa_hi;
            u32 ah[4][4], al[4][4];
            #pragma unroll
            for (int mt = 0; mt < 4; mt++) {
                const int r = wm * 64 + mt * 16 + fa_row;
                const uint32_t off = r * 128 + (uint32_t)((c16 * 16) ^ ((r & 7) * 16));
                ldm_x4(ah[mt][0], ah[mt][1], ah[mt][2], ah[mt][3], base + MG_AHI + off);
                ldm_x4(al[mt][0], al[mt][1], al[mt][2], al[mt][3], base + MG_ALO + off);
            }
            u32 bh[2][4], bl[2][4];
            #pragma unroll
            for (int p = 0; p < 2; p++) {
                const int r = wn * 32 + p * 16 + fa_row;
                const uint32_t off = r * 128 + (uint32_t)((c16 * 16) ^ ((r & 7) * 16));
                ldm_x4(bh[p][0], bh[p][1], bh[p][2], bh[p][3], base + MG_BHI + off);
                ldm_x4(bl[p][0], bl[p][1], bl[p][2], bl[p][3], base + MG_BLO + off);
            }
            #pragma unroll
            for (int mt = 0; mt < 4; mt++) {
                #pragma unroll
                for (int nt = 0; nt < 4; nt++) {
                    const int p = nt >> 1, h = nt & 1;
                    float* cc = acc[mt][nt];
                    mma_bf16(cc[0], cc[1], cc[2], cc[3],
                             ah[mt][0], ah[mt][1], ah[mt][2], ah[mt][3],
                             bh[p][h], bh[p][h + 2]);
                    mma_bf16(cc[0], cc[1], cc[2], cc[3],
                             ah[mt][0], ah[mt][1], ah[mt][2], ah[mt][3],
                             bl[p][h], bl[p][h + 2]);
                    mma_bf16(cc[0], cc[1], cc[2], cc[3],
                             al[mt][0], al[mt][1], al[mt][2], al[mt][3],
                             bh[p][h], bh[p][h + 2]);
                }
            }
        }
        __syncthreads();
    }

    const float* fbr = fb + (size_t)e * NF + n0;
    #pragma unroll
    for (int mt = 0; mt < 4; mt++) {
        const int r0 = wm * 64 + mt * 16 + (lid >> 2);
        const int r1 = r0 + 8;
        const int tok0 = toks[r0], tok1 = toks[r1];
        const float w0 = wts[r0],  w1 = wts[r1];
        #pragma unroll
        for (int nt = 0; nt < 4; nt++) {
            const int cb = wn * 32 + nt * 8 + (lid & 3) * 2;
            const float b0v = fbr[cb], b1v = fbr[cb + 1];
            const float* cc = acc[mt][nt];
            if (tok0 >= 0) {
                float* orow = out + (size_t)tok0 * NF + n0 + cb;
                atomicAdd(orow + 0, w0 * (cc[0] + b0v));
                atomicAdd(orow + 1, w0 * (cc[1] + b1v));
            }
            if (tok1 >= 0) {
                float* orow = out + (size_t)tok1 * NF + n0 + cb;
                atomicAdd(orow + 0, w1 * (cc[2] + b0v));
                atomicAdd(orow + 1, w1 * (cc[3] + b1v));
            }
        }
    }
}

// ---------------- launch ----------------
extern "C" void kernel_launch(void* const* d_in, const int* in_sizes, int n_in,
                              void* d_out, int out_size) {
    const float* feat  = (const float*)d_in[0];  // [B,F]
    const float* pw    = (const float*)d_in[1];  // [H,F]
    const float* pb    = (const float*)d_in[2];  // [H]
    const float* emb   = (const float*)d_in[3];  // [E,H]
    const float* ef    = (const float*)d_in[4];  // [E,F]
    const float* trust = (const float*)d_in[5];  // [E]
    const float* dt    = (const float*)d_in[6];  // [E]
    const float* fw    = (const float*)d_in[7];  // [E,F,F]
    const float* fb    = (const float*)d_in[8];  // [E,F]
    float* out = (float*)d_out;

    static bool attr_done = false;
    if (!attr_done) {
        cudaFuncSetAttribute(routing_kernel,
                             cudaFuncAttributeMaxDynamicSharedMemorySize, ROUT_SMEM);
        cudaFuncSetAttribute(moe_gemm_mma,
                             cudaFuncAttributeMaxDynamicSharedMemorySize, MG_SMEM);
        attr_done = true;
    }

    init_kernel<<<1, 64>>>(ef, trust, dt);
    zero_kernel<<<(NB * NF) / (256 * 4), 256>>>((float4*)out);
    convert_x<<<512, 256>>>(feat);
    convert_w<<<dim3(8, 8, NE), 256>>>(fw);
    routing_kernel<<<NB / 8, 256, ROUT_SMEM>>>(feat, pw, pb, emb, ef);
    moe_gemm_mma<<<dim3(4, NE, NB / 128), 256, MG_SMEM>>>(fb, out);
}

// round 9
// speedup vs baseline: 1.3803x; 1.0543x over previous
#include <cuda_runtime.h>
#include <cuda_bf16.h>
#include <math.h>
#include <stdint.h>

#define NB 2048   // batch
#define NF 512    // features
#define NH 256    // hidden
#define NE 64     // experts
#define NK 8      // top-k

typedef unsigned int u32;
typedef unsigned long long u64;

// ---------------- scratch (no allocation allowed) ----------------
__device__ int   g_counts[NE];
__device__ int   g_tok[NE * NB];
__device__ float g_wt[NE * NB];
__device__ float g_escale[NE];
__device__ float g_efinv[NE];
__device__ float g_gw[NE * NF];        // gate matrix: (pw^T emb^T)^T = emb@pw  [e][f]
__device__ float g_gc[NE];             // gate bias:   pb . emb_e
// bf16 hi/lo split buffers
__device__ __nv_bfloat16 g_xhi[NB * NF];               // 2MB
__device__ __nv_bfloat16 g_xlo[NB * NF];               // 2MB
__device__ __nv_bfloat16 g_wthi[(size_t)NE * NF * NF]; // 33.5MB, layout [e][n][k]
__device__ __nv_bfloat16 g_wtlo[(size_t)NE * NF * NF]; // 33.5MB

// ---------------- PTX helpers ----------------
__device__ __forceinline__ uint32_t smem_to_u32(const void* p) {
    uint32_t a;
    asm("{ .reg .u64 t; cvta.to.shared.u64 t, %1; cvt.u32.u64 %0, t; }"
        : "=r"(a) : "l"(p));
    return a;
}
__device__ __forceinline__ void cp16(uint32_t dst, const void* src, int srcsize) {
    asm volatile("cp.async.cg.shared.global [%0], [%1], 16, %2;"
                 :: "r"(dst), "l"(src), "r"(srcsize));
}
#define CP_COMMIT() asm volatile("cp.async.commit_group;" ::: "memory")
#define CP_WAIT(n)  asm volatile("cp.async.wait_group %0;" :: "n"(n) : "memory")

__device__ __forceinline__ void ldm_x4(u32& r0, u32& r1, u32& r2, u32& r3, u32 addr) {
    asm volatile("ldmatrix.sync.aligned.m8n8.x4.shared.b16 {%0,%1,%2,%3}, [%4];"
                 : "=r"(r0), "=r"(r1), "=r"(r2), "=r"(r3) : "r"(addr));
}
__device__ __forceinline__ void mma_bf16(float& c0, float& c1, float& c2, float& c3,
                                         u32 a0, u32 a1, u32 a2, u32 a3,
                                         u32 b0, u32 b1) {
    asm volatile("mma.sync.aligned.m16n8k16.row.col.f32.bf16.bf16.f32 "
                 "{%0,%1,%2,%3}, {%4,%5,%6,%7}, {%8,%9}, {%0,%1,%2,%3};"
                 : "+f"(c0), "+f"(c1), "+f"(c2), "+f"(c3)
                 : "r"(a0), "r"(a1), "r"(a2), "r"(a3), "r"(b0), "r"(b1));
}
// packed fp32 FMA (bit-exact 2x IEEE fp32 FMA, validated R2)
__device__ __forceinline__ void fma2(u64& acc, u64 a, u64 b) {
    asm("fma.rn.f32x2 %0, %1, %2, %0;" : "+l"(acc) : "l"(a), "l"(b));
}
__device__ __forceinline__ u64 pack_dup(float x) {
    u64 p;
    asm("mov.b64 %0, {%1, %1};" : "=l"(p) : "f"(x));
    return p;
}
__device__ __forceinline__ float2 unpack2(u64 v) {
    float2 r;
    asm("mov.b64 {%0, %1}, %2;" : "=f"(r.x), "=f"(r.y) : "l"(v));
    return r;
}

// ---------------- bf16 hi/lo split ----------------
__device__ __forceinline__ void split2(float a, float b, u32& hi, u32& lo) {
    __nv_bfloat16 ah = __float2bfloat16(a), bh = __float2bfloat16(b);
    float ar = a - __bfloat162float(ah);
    float br = b - __bfloat162float(bh);
    __nv_bfloat16 al = __float2bfloat16(ar), bl = __float2bfloat16(br);
    hi = (u32)__bfloat16_as_ushort(ah) | ((u32)__bfloat16_as_ushort(bh) << 16);
    lo = (u32)__bfloat16_as_ushort(al) | ((u32)__bfloat16_as_ushort(bl) << 16);
}

// ---------------- kernel 0: per-expert scalars + count reset ----------------
__global__ void init_kernel(const float* __restrict__ ef,
                            const float* __restrict__ trust,
                            const float* __restrict__ dt) {
    int e = threadIdx.x;
    if (e < NE) {
        g_counts[e] = 0;
        g_escale[e] = trust[e] * fmaxf(0.1f, expf(-0.005f * dt[e]));
        const float4* r = (const float4*)(ef + e * NF);
        float s = 0.f;
        #pragma unroll 8
        for (int i = 0; i < NF / 4; i++) {
            float4 v = r[i];
            s += v.x * v.x + v.y * v.y + v.z * v.z + v.w * v.w;
        }
        g_efinv[e] = 1.0f / fmaxf(sqrtf(s), 1e-8f);
    }
}

// ---------------- kernel 0b: gate matrix precompute --------------------
// g_gw[e][f] = sum_h pw[h][f] * emb[e][h];  g_gc[e] = sum_h pb[h]*emb[e][h]
__global__ void __launch_bounds__(256)
pregate_kernel(const float* __restrict__ pw, const float* __restrict__ pb,
               const float* __restrict__ emb) {
    __shared__ float es[NH];
    const int e   = blockIdx.x;
    const int tid = threadIdx.x;
    es[tid] = emb[(size_t)e * NH + tid];
    __syncthreads();

    const int f0 = tid, f1 = tid + 256;
    float a0 = 0.f, a1 = 0.f;
    #pragma unroll 8
    for (int h = 0; h < NH; h++) {
        float ev = es[h];
        a0 += ev * pw[(size_t)h * NF + f0];
        a1 += ev * pw[(size_t)h * NF + f1];
    }
    g_gw[e * NF + f0] = a0;
    g_gw[e * NF + f1] = a1;

    if (tid < 32) {
        float s = 0.f;
        #pragma unroll
        for (int h = tid; h < NH; h += 32) s += pb[h] * es[h];
        #pragma unroll
        for (int off = 16; off > 0; off >>= 1)
            s += __shfl_xor_sync(0xffffffffu, s, off);
        if (tid == 0) g_gc[e] = s;
    }
}

// ---------------- kernel 1: zero output ----------------
__global__ void zero_kernel(float4* __restrict__ out) {
    out[blockIdx.x * 256 + threadIdx.x] = make_float4(0.f, 0.f, 0.f, 0.f);
}

// ---------------- kernel 1b: convert X to bf16 hi/lo ----------------
__global__ void convert_x(const float* __restrict__ feat) {
    u32* xh = (u32*)g_xhi;
    u32* xl = (u32*)g_xlo;
    int p = blockIdx.x * 256 + threadIdx.x;
    const int npairs = NB * NF / 2;
    for (; p < npairs; p += gridDim.x * 256) {
        float2 v = *(const float2*)(feat + 2 * p);
        u32 hi, lo;
        split2(v.x, v.y, hi, lo);
        xh[p] = hi; xl[p] = lo;
    }
}

// ---------------- kernel 1c: convert + transpose W -> [e][n][k] bf16 hi/lo ----
__global__ void __launch_bounds__(256)
convert_w(const float* __restrict__ fw) {
    __shared__ float s[64][65];
    const int e  = blockIdx.z;
    const int k0 = blockIdx.x * 64;
    const int n0 = blockIdx.y * 64;
    const int tid = threadIdx.x;
    const float* src = fw + ((size_t)e * NF + k0) * NF + n0;
    #pragma unroll
    for (int i = 0; i < 16; i++) {
        int idx = tid + 256 * i;
        int kl = idx >> 6, nl = idx & 63;
        s[kl][nl] = src[(size_t)kl * NF + nl];
    }
    __syncthreads();
    u32* wh = (u32*)g_wthi;
    u32* wl = (u32*)g_wtlo;
    #pragma unroll
    for (int i = 0; i < 8; i++) {
        int idx = tid + 256 * i;
        int nl = idx >> 5;
        int kp = (idx & 31) * 2;
        float a = s[kp][nl], b = s[kp + 1][nl];
        u32 hi, lo;
        split2(a, b, hi, lo);
        size_t off = (((size_t)e * NF + n0 + nl) * NF + k0 + kp) >> 1;
        wh[off] = hi; wl[off] = lo;
    }
}

// ---------------- kernel 2: routing v4 -------------------------------------
// One fused fp32 GEMM: [16 tok x 128 cols] = X @ [g_gw ; ef]^T over K=512,
// via fma.rn.f32x2. Cols 0-63 -> gate logits (X.M^T), 64-127 -> raw sims.
// Then score = sigmoid((L+gc)/16) * max(0,S*xinv*efinv) * escale, top-8.
#define V4_XSS 516
#define V4_BSS 132
#define V4_XS   0
#define V4_BS   (16 * V4_XSS)                 // 8256
#define V4_LS   (V4_BS + 32 * V4_BSS)         // 12480
#define V4_SS   (V4_LS + 16 * 68)             // 13568
#define V4_SC   (V4_SS + 16 * 68)             // 14656
#define V4_XI   (V4_SC + 16 * 68)             // 15744
#define ROUT_SMEM ((V4_XI + 16) * 4)          // ~63KB

__global__ void __launch_bounds__(256, 1)
routing_v4(const float* __restrict__ feat, const float* __restrict__ ef) {
    extern __shared__ float sm[];
    float* xs   = sm + V4_XS;
    float* bs   = sm + V4_BS;
    float* Ls   = sm + V4_LS;
    float* Ss   = sm + V4_SS;
    float* sc   = sm + V4_SC;
    float* xinv = sm + V4_XI;

    const int tid = threadIdx.x;
    const int t0  = blockIdx.x * 16;

    // ---- load X tile [16][512] ----
    const float4* feat4 = (const float4*)feat;
    #pragma unroll
    for (int i = 0; i < 8; i++) {
        int idx = tid + 256 * i;
        int t   = idx >> 7;
        int q   = idx & 127;
        float4 v = feat4[(size_t)(t0 + t) * 128 + q];
        *(float4*)(xs + t * V4_XSS + q * 4) = v;
    }
    __syncthreads();

    if (tid < 16) {
        const float* xr = xs + tid * V4_XSS;
        float s = 0.f;
        #pragma unroll 8
        for (int i = 0; i < NF / 4; i++) {
            float4 v = *(const float4*)(xr + i * 4);
            s += v.x * v.x + v.y * v.y + v.z * v.z + v.w * v.w;
        }
        xinv[tid] = 1.0f / fmaxf(sqrtf(s), 1e-8f);
    }

    // ---- fused GEMM: 16 tok x 128 cols, K=512 ----
    const int t  = tid & 15;
    const int cg = tid >> 4;                 // 0..15 -> cols cg*8..+7
    u64 acc[4];
    #pragma unroll
    for (int p = 0; p < 4; p++) acc[p] = 0ULL;

    for (int k0 = 0; k0 < NF; k0 += 32) {
        // stage B' chunk [32 k][128 rows] transposed: rows 0-63 g_gw, 64-127 ef
        #pragma unroll
        for (int i = 0; i < 4; i++) {
            int idx = tid + 256 * i;         // 0..1023
            int row = idx >> 3;
            int kq  = idx & 7;
            const float* src = (row < 64) ? (g_gw + row * NF)
                                          : (ef + (size_t)(row - 64) * NF);
            float4 v = *(const float4*)(src + k0 + kq * 4);
            bs[(kq * 4 + 0) * V4_BSS + row] = v.x;
            bs[(kq * 4 + 1) * V4_BSS + row] = v.y;
            bs[(kq * 4 + 2) * V4_BSS + row] = v.z;
            bs[(kq * 4 + 3) * V4_BSS + row] = v.w;
        }
        __syncthreads();
        #pragma unroll
        for (int kk = 0; kk < 32; kk++) {
            u64 xp = pack_dup(xs[t * V4_XSS + k0 + kk]);
            const float* wr = bs + kk * V4_BSS + cg * 8;
            ulonglong2 wa = *(const ulonglong2*)(wr);
            ulonglong2 wb = *(const ulonglong2*)(wr + 4);
            fma2(acc[0], xp, wa.x);
            fma2(acc[1], xp, wa.y);
            fma2(acc[2], xp, wb.x);
            fma2(acc[3], xp, wb.y);
        }
        __syncthreads();
    }

    // ---- spill L / S ----
    {
        float* dst = (cg < 8) ? (Ls + t * 68 + cg * 8)
                              : (Ss + t * 68 + (cg - 8) * 8);
        #pragma unroll
        for (int p = 0; p < 4; p++) {
            float2 v = unpack2(acc[p]);
            dst[2 * p]     = v.x;
            dst[2 * p + 1] = v.y;
        }
    }
    __syncthreads();

    // ---- scores ----
    #pragma unroll
    for (int i = 0; i < 4; i++) {
        int pid = tid + 256 * i;             // 0..1023
        int e   = pid >> 4;
        int tt  = pid & 15;
        float gate = 1.0f / (1.0f + expf(-(Ls[tt * 68 + e] + g_gc[e]) * 0.0625f));
        float sim  = fmaxf(Ss[tt * 68 + e] * xinv[tt] * g_efinv[e], 0.f);
        sc[tt * 68 + e] = gate * sim * g_escale[e];
    }
    __syncthreads();

    // ---- top-8 + softmax + scatter ----
    if (tid < 16) {
        float* row = sc + tid * 68;
        float v[NK]; int ix[NK];
        #pragma unroll
        for (int k = 0; k < NK; k++) {
            float best = -1.f; int bi = 0;
            for (int e = 0; e < NE; e++) {
                float s = row[e];
                if (s > best) { best = s; bi = e; }
            }
            v[k] = best; ix[k] = bi; row[bi] = -1e30f;
        }
        float m = v[0], sum = 0.f, w[NK];
        #pragma unroll
        for (int k = 0; k < NK; k++) { w[k] = expf(v[k] - m); sum += w[k]; }
        float inv = 1.0f / sum;
        int tok = t0 + tid;
        #pragma unroll
        for (int k = 0; k < NK; k++) {
            int e = ix[k];
            int slot = atomicAdd(&g_counts[e], 1);
            g_tok[e * NB + slot] = tok;
            g_wt[e * NB + slot]  = w[k] * inv;
        }
    }
}

// ---------------- kernel 3: mma.sync bf16 hi/lo grouped MoE GEMM (R4/R8) ---
#define MG_DATA    1024
#define MG_BUF     65536
#define MG_AHI     0
#define MG_ALO     16384
#define MG_BHI     32768
#define MG_BLO     49152
#define MG_SMEM    (MG_DATA + 2 * MG_BUF)   // 132096 bytes

__global__ void __launch_bounds__(256, 1)
moe_gemm_mma(const float* __restrict__ fb, float* __restrict__ out) {
    const int e    = blockIdx.y;
    const int n0   = blockIdx.x * 128;
    const int tile = blockIdx.z;
    const int cnt  = g_counts[e];
    if (tile * 128 >= cnt) return;

    extern __shared__ char smem[];
    const uint32_t sb = smem_to_u32(smem);
    const int tid = threadIdx.x;

    int*   toks = (int*)(smem);
    float* wts  = (float*)(smem + 512);
    {
        int s = tile * 128 + tid;
        if (tid < 128) {
            if (s < cnt) { toks[tid] = g_tok[e * NB + s]; wts[tid] = g_wt[e * NB + s]; }
            else         { toks[tid] = -1;                wts[tid] = 0.f; }
        }
    }
    __syncthreads();

    const int srow  = tid >> 1;
    const int spart = (tid & 1) * 4;
    const int stok  = toks[srow];
    const int asz   = (stok >= 0) ? 16 : 0;
    const uint4* aH = (const uint4*)(g_xhi + (size_t)max(stok, 0) * NF);
    const uint4* aL = (const uint4*)(g_xlo + (size_t)max(stok, 0) * NF);
    const uint4* bH = (const uint4*)(g_wthi + ((size_t)e * NF + n0 + srow) * NF);
    const uint4* bL = (const uint4*)(g_wtlo + ((size_t)e * NF + n0 + srow) * NF);
    const uint32_t srowb = sb + MG_DATA + srow * 128;
    const int      ssw   = (srow & 7) * 16;

    #define PREFETCH(c)                                                          \
    do {                                                                         \
        const int _buf = (c) & 1;                                                \
        const uint32_t _d = srowb + _buf * MG_BUF;                               \
        _Pragma("unroll")                                                        \
        for (int j = 0; j < 4; j++) {                                            \
            const int c16 = spart + j;                                           \
            const uint32_t off = (uint32_t)((c16 * 16) ^ ssw);                   \
            cp16(_d + MG_AHI + off, aH + (c) * 8 + c16, asz);                    \
            cp16(_d + MG_ALO + off, aL + (c) * 8 + c16, asz);                    \
            cp16(_d + MG_BHI + off, bH + (c) * 8 + c16, 16);                     \
            cp16(_d + MG_BLO + off, bL + (c) * 8 + c16, 16);                     \
        }                                                                        \
    } while (0)

    PREFETCH(0);
    CP_COMMIT();

    const int lid = tid & 31;
    const int wid = tid >> 5;
    const int wm  = wid & 1;
    const int wn  = wid >> 1;

    float acc[4][4][4];
    #pragma unroll
    for (int mt = 0; mt < 4; mt++)
        #pragma unroll
        for (int nt = 0; nt < 4; nt++)
            #pragma unroll
            for (int q = 0; q < 4; q++) acc[mt][nt][q] = 0.f;

    const int fa_row = (lid & 15);
    const int fa_hi  = (lid >> 4);

    for (int c = 0; c < 8; c++) {
        if (c < 7) { PREFETCH(c + 1); CP_COMMIT(); CP_WAIT(1); }
        else       { CP_WAIT(0); }
        __syncthreads();

        const uint32_t base = sb + MG_DATA + (c & 1) * MG_BUF;

        #pragma unroll
        for (int ks = 0; ks < 4; ks++) {
            const int c16 = ks * 2 + fa_hi;
            u32 ah[4][4], al[4][4];
            #pragma unroll
            for (int mt = 0; mt < 4; mt++) {
                const int r = wm * 64 + mt * 16 + fa_row;
                const uint32_t off = r * 128 + (uint32_t)((c16 * 16) ^ ((r & 7) * 16));
                ldm_x4(ah[mt][0], ah[mt][1], ah[mt][2], ah[mt][3], base + MG_AHI + off);
                ldm_x4(al[mt][0], al[mt][1], al[mt][2], al[mt][3], base + MG_ALO + off);
            }
            u32 bh[2][4], bl[2][4];
            #pragma unroll
            for (int p = 0; p < 2; p++) {
                const int r = wn * 32 + p * 16 + fa_row;
                const uint32_t off = r * 128 + (uint32_t)((c16 * 16) ^ ((r & 7) * 16));
                ldm_x4(bh[p][0], bh[p][1], bh[p][2], bh[p][3], base + MG_BHI + off);
                ldm_x4(bl[p][0], bl[p][1], bl[p][2], bl[p][3], base + MG_BLO + off);
            }
            #pragma unroll
            for (int mt = 0; mt < 4; mt++) {
                #pragma unroll
                for (int nt = 0; nt < 4; nt++) {
                    const int p = nt >> 1, h = nt & 1;
                    float* cc = acc[mt][nt];
                    mma_bf16(cc[0], cc[1], cc[2], cc[3],
                             ah[mt][0], ah[mt][1], ah[mt][2], ah[mt][3],
                             bh[p][h], bh[p][h + 2]);
                    mma_bf16(cc[0], cc[1], cc[2], cc[3],
                             ah[mt][0], ah[mt][1], ah[mt][2], ah[mt][3],
                             bl[p][h], bl[p][h + 2]);
                    mma_bf16(cc[0], cc[1], cc[2], cc[3],
                             al[mt][0], al[mt][1], al[mt][2], al[mt][3],
                             bh[p][h], bh[p][h + 2]);
                }
            }
        }
        __syncthreads();
    }

    const float* fbr = fb + (size_t)e * NF + n0;
    #pragma unroll
    for (int mt = 0; mt < 4; mt++) {
        const int r0 = wm * 64 + mt * 16 + (lid >> 2);
        const int r1 = r0 + 8;
        const int tok0 = toks[r0], tok1 = toks[r1];
        const float w0 = wts[r0],  w1 = wts[r1];
        #pragma unroll
        for (int nt = 0; nt < 4; nt++) {
            const int cb = wn * 32 + nt * 8 + (lid & 3) * 2;
            const float b0v = fbr[cb], b1v = fbr[cb + 1];
            const float* cc = acc[mt][nt];
            if (tok0 >= 0) {
                float* orow = out + (size_t)tok0 * NF + n0 + cb;
                atomicAdd(orow + 0, w0 * (cc[0] + b0v));
                atomicAdd(orow + 1, w0 * (cc[1] + b1v));
            }
            if (tok1 >= 0) {
                float* orow = out + (size_t)tok1 * NF + n0 + cb;
                atomicAdd(orow + 0, w1 * (cc[2] + b0v));
                atomicAdd(orow + 1, w1 * (cc[3] + b1v));
            }
        }
    }
}

// ---------------- launch ----------------
extern "C" void kernel_launch(void* const* d_in, const int* in_sizes, int n_in,
                              void* d_out, int out_size) {
    const float* feat  = (const float*)d_in[0];  // [B,F]
    const float* pw    = (const float*)d_in[1];  // [H,F]
    const float* pb    = (const float*)d_in[2];  // [H]
    const float* emb   = (const float*)d_in[3];  // [E,H]
    const float* ef    = (const float*)d_in[4];  // [E,F]
    const float* trust = (const float*)d_in[5];  // [E]
    const float* dt    = (const float*)d_in[6];  // [E]
    const float* fw    = (const float*)d_in[7];  // [E,F,F]
    const float* fb    = (const float*)d_in[8];  // [E,F]
    float* out = (float*)d_out;

    static bool attr_done = false;
    if (!attr_done) {
        cudaFuncSetAttribute(routing_v4,
                             cudaFuncAttributeMaxDynamicSharedMemorySize, ROUT_SMEM);
        cudaFuncSetAttribute(moe_gemm_mma,
                             cudaFuncAttributeMaxDynamicSharedMemorySize, MG_SMEM);
        attr_done = true;
    }

    init_kernel<<<1, 64>>>(ef, trust, dt);
    pregate_kernel<<<NE, 256>>>(pw, pb, emb);
    zero_kernel<<<(NB * NF) / (256 * 4), 256>>>((float4*)out);
    convert_x<<<512, 256>>>(feat);
    convert_w<<<dim3(8, 8, NE), 256>>>(fw);
    routing_v4<<<NB / 16, 256, ROUT_SMEM>>>(feat, ef);
    moe_gemm_mma<<<dim3(4, NE, NB / 128), 256, MG_SMEM>>>(fb, out);
}

// round 10
// speedup vs baseline: 1.3898x; 1.0068x over previous
#include <cuda_runtime.h>
#include <cuda_bf16.h>
#include <math.h>
#include <stdint.h>

#define NB 2048   // batch
#define NF 512    // features
#define NH 256    // hidden
#define NE 64     // experts
#define NK 8      // top-k

typedef unsigned int u32;
typedef unsigned long long u64;

// ---------------- scratch (no allocation allowed) ----------------
__device__ int   g_counts[NE];
__device__ int   g_tok[NE * NB];
__device__ float g_wt[NE * NB];
__device__ float g_escale[NE];
__device__ float g_efinv[NE];
__device__ float g_xinv[NB];
__device__ float g_gw[NE * NF];        // gate matrix: emb @ pw  [e][f]
__device__ float g_gc[NE];             // gate bias:   pb . emb_e
__device__ float g_L[NB * NE];         // raw gate logits (pre-bias)
__device__ float g_S[NB * NE];         // raw sims (pre-normalization)
// bf16 hi/lo split buffers
__device__ __nv_bfloat16 g_xhi[NB * NF];               // 2MB
__device__ __nv_bfloat16 g_xlo[NB * NF];               // 2MB
__device__ __nv_bfloat16 g_wthi[(size_t)NE * NF * NF]; // 33.5MB, layout [e][n][k]
__device__ __nv_bfloat16 g_wtlo[(size_t)NE * NF * NF]; // 33.5MB

// ---------------- PTX helpers ----------------
__device__ __forceinline__ uint32_t smem_to_u32(const void* p) {
    uint32_t a;
    asm("{ .reg .u64 t; cvta.to.shared.u64 t, %1; cvt.u32.u64 %0, t; }"
        : "=r"(a) : "l"(p));
    return a;
}
__device__ __forceinline__ void cp16(uint32_t dst, const void* src, int srcsize) {
    asm volatile("cp.async.cg.shared.global [%0], [%1], 16, %2;"
                 :: "r"(dst), "l"(src), "r"(srcsize));
}
#define CP_COMMIT() asm volatile("cp.async.commit_group;" ::: "memory")
#define CP_WAIT(n)  asm volatile("cp.async.wait_group %0;" :: "n"(n) : "memory")

__device__ __forceinline__ void ldm_x4(u32& r0, u32& r1, u32& r2, u32& r3, u32 addr) {
    asm volatile("ldmatrix.sync.aligned.m8n8.x4.shared.b16 {%0,%1,%2,%3}, [%4];"
                 : "=r"(r0), "=r"(r1), "=r"(r2), "=r"(r3) : "r"(addr));
}
__device__ __forceinline__ void mma_bf16(float& c0, float& c1, float& c2, float& c3,
                                         u32 a0, u32 a1, u32 a2, u32 a3,
                                         u32 b0, u32 b1) {
    asm volatile("mma.sync.aligned.m16n8k16.row.col.f32.bf16.bf16.f32 "
                 "{%0,%1,%2,%3}, {%4,%5,%6,%7}, {%8,%9}, {%0,%1,%2,%3};"
                 : "+f"(c0), "+f"(c1), "+f"(c2), "+f"(c3)
                 : "r"(a0), "r"(a1), "r"(a2), "r"(a3), "r"(b0), "r"(b1));
}
__device__ __forceinline__ void fma2(u64& acc, u64 a, u64 b) {
    asm("fma.rn.f32x2 %0, %1, %2, %0;" : "+l"(acc) : "l"(a), "l"(b));
}
__device__ __forceinline__ u64 pack_dup(float x) {
    u64 p;
    asm("mov.b64 %0, {%1, %1};" : "=l"(p) : "f"(x));
    return p;
}
__device__ __forceinline__ float2 unpack2(u64 v) {
    float2 r;
    asm("mov.b64 {%0, %1}, %2;" : "=f"(r.x), "=f"(r.y) : "l"(v));
    return r;
}

// ---------------- bf16 hi/lo split ----------------
__device__ __forceinline__ void split2(float a, float b, u32& hi, u32& lo) {
    __nv_bfloat16 ah = __float2bfloat16(a), bh = __float2bfloat16(b);
    float ar = a - __bfloat162float(ah);
    float br = b - __bfloat162float(bh);
    __nv_bfloat16 al = __float2bfloat16(ar), bl = __float2bfloat16(br);
    hi = (u32)__bfloat16_as_ushort(ah) | ((u32)__bfloat16_as_ushort(bh) << 16);
    lo = (u32)__bfloat16_as_ushort(al) | ((u32)__bfloat16_as_ushort(bl) << 16);
}

// ---------------- kernel 0: per-expert scalars + count reset ----------------
__global__ void init_kernel(const float* __restrict__ ef,
                            const float* __restrict__ trust,
                            const float* __restrict__ dt) {
    int e = threadIdx.x;
    if (e < NE) {
        g_counts[e] = 0;
        g_escale[e] = trust[e] * fmaxf(0.1f, expf(-0.005f * dt[e]));
        const float4* r = (const float4*)(ef + e * NF);
        float s = 0.f;
        #pragma unroll 8
        for (int i = 0; i < NF / 4; i++) {
            float4 v = r[i];
            s += v.x * v.x + v.y * v.y + v.z * v.z + v.w * v.w;
        }
        g_efinv[e] = 1.0f / fmaxf(sqrtf(s), 1e-8f);
    }
}

// ---------------- kernel 0b: gate matrix precompute --------------------
__global__ void __launch_bounds__(256)
pregate_kernel(const float* __restrict__ pw, const float* __restrict__ pb,
               const float* __restrict__ emb) {
    __shared__ float es[NH];
    const int e   = blockIdx.x;
    const int tid = threadIdx.x;
    es[tid] = emb[(size_t)e * NH + tid];
    __syncthreads();

    const int f0 = tid, f1 = tid + 256;
    float a0 = 0.f, a1 = 0.f;
    #pragma unroll 8
    for (int h = 0; h < NH; h++) {
        float ev = es[h];
        a0 += ev * pw[(size_t)h * NF + f0];
        a1 += ev * pw[(size_t)h * NF + f1];
    }
    g_gw[e * NF + f0] = a0;
    g_gw[e * NF + f1] = a1;

    if (tid < 32) {
        float s = 0.f;
        #pragma unroll
        for (int h = tid; h < NH; h += 32) s += pb[h] * es[h];
        #pragma unroll
        for (int off = 16; off > 0; off >>= 1)
            s += __shfl_xor_sync(0xffffffffu, s, off);
        if (tid == 0) g_gc[e] = s;
    }
}

// ---------------- kernel 1: zero output ----------------
__global__ void zero_kernel(float4* __restrict__ out) {
    out[blockIdx.x * 256 + threadIdx.x] = make_float4(0.f, 0.f, 0.f, 0.f);
}

// ---------------- kernel 1b: convert X to bf16 hi/lo ----------------
__global__ void convert_x(const float* __restrict__ feat) {
    u32* xh = (u32*)g_xhi;
    u32* xl = (u32*)g_xlo;
    int p = blockIdx.x * 256 + threadIdx.x;
    const int npairs = NB * NF / 2;
    for (; p < npairs; p += gridDim.x * 256) {
        float2 v = *(const float2*)(feat + 2 * p);
        u32 hi, lo;
        split2(v.x, v.y, hi, lo);
        xh[p] = hi; xl[p] = lo;
    }
}

// ---------------- kernel 1c: convert + transpose W -> [e][n][k] bf16 hi/lo ----
__global__ void __launch_bounds__(256)
convert_w(const float* __restrict__ fw) {
    __shared__ float s[64][65];
    const int e  = blockIdx.z;
    const int k0 = blockIdx.x * 64;
    const int n0 = blockIdx.y * 64;
    const int tid = threadIdx.x;
    const float* src = fw + ((size_t)e * NF + k0) * NF + n0;
    #pragma unroll
    for (int i = 0; i < 16; i++) {
        int idx = tid + 256 * i;
        int kl = idx >> 6, nl = idx & 63;
        s[kl][nl] = src[(size_t)kl * NF + nl];
    }
    __syncthreads();
    u32* wh = (u32*)g_wthi;
    u32* wl = (u32*)g_wtlo;
    #pragma unroll
    for (int i = 0; i < 8; i++) {
        int idx = tid + 256 * i;
        int nl = idx >> 5;
        int kp = (idx & 31) * 2;
        float a = s[kp][nl], b = s[kp + 1][nl];
        u32 hi, lo;
        split2(a, b, hi, lo);
        size_t off = (((size_t)e * NF + n0 + nl) * NF + k0 + kp) >> 1;
        wh[off] = hi; wl[off] = lo;
    }
}

// ---------------- kernel 2a: routing GEMM halves ---------------------------
// grid (2, 128): blockIdx.x=0 -> L = X @ g_gw^T ; =1 -> S = X @ ef^T (+xinv).
// 16 tokens x 64 cols per CTA, K=512 in chunks of 32, fma.rn.f32x2.
#define V5_XSS 516
#define V5_BSS 68
#define V5_XS  0
#define V5_BS  (16 * V5_XSS)                  // 8256
#define ROUT_SMEM ((V5_BS + 32 * V5_BSS) * 4) // ~41.7KB

__global__ void __launch_bounds__(256)
route_gemm(const float* __restrict__ feat, const float* __restrict__ ef) {
    extern __shared__ float sm[];
    float* xs = sm + V5_XS;
    float* bs = sm + V5_BS;

    const int tid  = threadIdx.x;
    const int half = blockIdx.x;
    const int t0   = blockIdx.y * 16;

    // ---- load X tile [16][512] ----
    const float4* feat4 = (const float4*)feat;
    #pragma unroll
    for (int i = 0; i < 8; i++) {
        int idx = tid + 256 * i;
        int t   = idx >> 7;
        int q   = idx & 127;
        float4 v = feat4[(size_t)(t0 + t) * 128 + q];
        *(float4*)(xs + t * V5_XSS + q * 4) = v;
    }
    __syncthreads();

    if (half == 1 && tid < 16) {
        const float* xr = xs + tid * V5_XSS;
        float s = 0.f;
        #pragma unroll 8
        for (int i = 0; i < NF / 4; i++) {
            float4 v = *(const float4*)(xr + i * 4);
            s += v.x * v.x + v.y * v.y + v.z * v.z + v.w * v.w;
        }
        g_xinv[t0 + tid] = 1.0f / fmaxf(sqrtf(s), 1e-8f);
    }

    const float* bsrc = half ? ef : g_gw;
    const int t  = tid & 15;
    const int cg = tid >> 4;              // 0..15 -> cols cg*4..+3
    u64 acc0 = 0ULL, acc1 = 0ULL;

    for (int k0 = 0; k0 < NF; k0 += 32) {
        // stage B chunk: 64 rows x 32 k, transposed -> bs[kk][row]
        #pragma unroll
        for (int i = 0; i < 2; i++) {
            int idx = tid + 256 * i;      // 0..511
            int row = idx >> 3;           // 0..63
            int kq  = idx & 7;
            float4 v = *(const float4*)(bsrc + (size_t)row * NF + k0 + kq * 4);
            bs[(kq * 4 + 0) * V5_BSS + row] = v.x;
            bs[(kq * 4 + 1) * V5_BSS + row] = v.y;
            bs[(kq * 4 + 2) * V5_BSS + row] = v.z;
            bs[(kq * 4 + 3) * V5_BSS + row] = v.w;
        }
        __syncthreads();
        #pragma unroll
        for (int kk = 0; kk < 32; kk++) {
            u64 xp = pack_dup(xs[t * V5_XSS + k0 + kk]);
            ulonglong2 w = *(const ulonglong2*)(bs + kk * V5_BSS + cg * 4);
            fma2(acc0, xp, w.x);
            fma2(acc1, xp, w.y);
        }
        __syncthreads();
    }

    float* dst = (half ? g_S : g_L) + (size_t)(t0 + t) * NE + cg * 4;
    float2 a0 = unpack2(acc0), a1 = unpack2(acc1);
    dst[0] = a0.x; dst[1] = a0.y; dst[2] = a1.x; dst[3] = a1.y;
}

// ---------------- kernel 2b: score + top-8 + softmax + scatter (warp/token) -
__global__ void __launch_bounds__(256)
route_topk() {
    const int tid  = threadIdx.x;
    const int lane = tid & 31;
    const int tok  = blockIdx.x * 8 + (tid >> 5);
    const float xi = g_xinv[tok];

    float s0, s1;
    {
        int e0 = lane, e1 = lane + 32;
        float gate0 = 1.0f / (1.0f + expf(-(g_L[(size_t)tok * NE + e0] + g_gc[e0]) * 0.0625f));
        float gate1 = 1.0f / (1.0f + expf(-(g_L[(size_t)tok * NE + e1] + g_gc[e1]) * 0.0625f));
        float sim0  = fmaxf(g_S[(size_t)tok * NE + e0] * xi * g_efinv[e0], 0.f);
        float sim1  = fmaxf(g_S[(size_t)tok * NE + e1] * xi * g_efinv[e1], 0.f);
        s0 = gate0 * sim0 * g_escale[e0];
        s1 = gate1 * sim1 * g_escale[e1];
    }
    const int e0 = lane, e1 = lane + 32;

    float vk[NK];
    int   ik[NK];
    #pragma unroll
    for (int k = 0; k < NK; k++) {
        float v; int ix;
        if (s0 >= s1) { v = s0; ix = e0; }    // tie -> lower index
        else          { v = s1; ix = e1; }
        #pragma unroll
        for (int off = 16; off > 0; off >>= 1) {
            float ov = __shfl_down_sync(0xffffffffu, v, off);
            int   oi = __shfl_down_sync(0xffffffffu, ix, off);
            if (ov > v || (ov == v && oi < ix)) { v = ov; ix = oi; }
        }
        v  = __shfl_sync(0xffffffffu, v, 0);
        ix = __shfl_sync(0xffffffffu, ix, 0);
        vk[k] = v; ik[k] = ix;
        if (ix == e0) s0 = -1e30f;
        if (ix == e1) s1 = -1e30f;
    }
    float m = vk[0], sum = 0.f, w[NK];
    #pragma unroll
    for (int k = 0; k < NK; k++) { w[k] = expf(vk[k] - m); sum += w[k]; }
    float inv = 1.0f / sum;
    if (lane < NK) {
        int e = ik[lane];
        int slot = atomicAdd(&g_counts[e], 1);
        g_tok[e * NB + slot] = tok;
        g_wt[e * NB + slot]  = w[lane] * inv;
    }
}

// ---------------- kernel 3: mma.sync bf16 hi/lo grouped MoE GEMM (R4/R8) ---
#define MG_DATA    1024
#define MG_BUF     65536
#define MG_AHI     0
#define MG_ALO     16384
#define MG_BHI     32768
#define MG_BLO     49152
#define MG_SMEM    (MG_DATA + 2 * MG_BUF)   // 132096 bytes

__global__ void __launch_bounds__(256, 1)
moe_gemm_mma(const float* __restrict__ fb, float* __restrict__ out) {
    const int e    = blockIdx.y;
    const int n0   = blockIdx.x * 128;
    const int tile = blockIdx.z;
    const int cnt  = g_counts[e];
    if (tile * 128 >= cnt) return;

    extern __shared__ char smem[];
    const uint32_t sb = smem_to_u32(smem);
    const int tid = threadIdx.x;

    int*   toks = (int*)(smem);
    float* wts  = (float*)(smem + 512);
    {
        int s = tile * 128 + tid;
        if (tid < 128) {
            if (s < cnt) { toks[tid] = g_tok[e * NB + s]; wts[tid] = g_wt[e * NB + s]; }
            else         { toks[tid] = -1;                wts[tid] = 0.f; }
        }
    }
    __syncthreads();

    const int srow  = tid >> 1;
    const int spart = (tid & 1) * 4;
    const int stok  = toks[srow];
    const int asz   = (stok >= 0) ? 16 : 0;
    const uint4* aH = (const uint4*)(g_xhi + (size_t)max(stok, 0) * NF);
    const uint4* aL = (const uint4*)(g_xlo + (size_t)max(stok, 0) * NF);
    const uint4* bH = (const uint4*)(g_wthi + ((size_t)e * NF + n0 + srow) * NF);
    const uint4* bL = (const uint4*)(g_wtlo + ((size_t)e * NF + n0 + srow) * NF);
    const uint32_t srowb = sb + MG_DATA + srow * 128;
    const int      ssw   = (srow & 7) * 16;

    #define PREFETCH(c)                                                          \
    do {                                                                         \
        const int _buf = (c) & 1;                                                \
        const uint32_t _d = srowb + _buf * MG_BUF;                               \
        _Pragma("unroll")                                                        \
        for (int j = 0; j < 4; j++) {                                            \
            const int c16 = spart + j;                                           \
            const uint32_t off = (uint32_t)((c16 * 16) ^ ssw);                   \
            cp16(_d + MG_AHI + off, aH + (c) * 8 + c16, asz);                    \
            cp16(_d + MG_ALO + off, aL + (c) * 8 + c16, asz);                    \
            cp16(_d + MG_BHI + off, bH + (c) * 8 + c16, 16);                     \
            cp16(_d + MG_BLO + off, bL + (c) * 8 + c16, 16);                     \
        }                                                                        \
    } while (0)

    PREFETCH(0);
    CP_COMMIT();

    const int lid = tid & 31;
    const int wid = tid >> 5;
    const int wm  = wid & 1;
    const int wn  = wid >> 1;

    float acc[4][4][4];
    #pragma unroll
    for (int mt = 0; mt < 4; mt++)
        #pragma unroll
        for (int nt = 0; nt < 4; nt++)
            #pragma unroll
            for (int q = 0; q < 4; q++) acc[mt][nt][q] = 0.f;

    const int fa_row = (lid & 15);
    const int fa_hi  = (lid >> 4);

    for (int c = 0; c < 8; c++) {
        if (c < 7) { PREFETCH(c + 1); CP_COMMIT(); CP_WAIT(1); }
        else       { CP_WAIT(0); }
        __syncthreads();

        const uint32_t base = sb + MG_DATA + (c & 1) * MG_BUF;

        #pragma unroll
        for (int ks = 0; ks < 4; ks++) {
            const int c16 = ks * 2 + fa_hi;
            u32 ah[4][4], al[4][4];
            #pragma unroll
            for (int mt = 0; mt < 4; mt++) {
                const int r = wm * 64 + mt * 16 + fa_row;
                const uint32_t off = r * 128 + (uint32_t)((c16 * 16) ^ ((r & 7) * 16));
                ldm_x4(ah[mt][0], ah[mt][1], ah[mt][2], ah[mt][3], base + MG_AHI + off);
                ldm_x4(al[mt][0], al[mt][1], al[mt][2], al[mt][3], base + MG_ALO + off);
            }
            u32 bh[2][4], bl[2][4];
            #pragma unroll
            for (int p = 0; p < 2; p++) {
                const int r = wn * 32 + p * 16 + fa_row;
                const uint32_t off = r * 128 + (uint32_t)((c16 * 16) ^ ((r & 7) * 16));
                ldm_x4(bh[p][0], bh[p][1], bh[p][2], bh[p][3], base + MG_BHI + off);
                ldm_x4(bl[p][0], bl[p][1], bl[p][2], bl[p][3], base + MG_BLO + off);
            }
            #pragma unroll
            for (int mt = 0; mt < 4; mt++) {
                #pragma unroll
                for (int nt = 0; nt < 4; nt++) {
                    const int p = nt >> 1, h = nt & 1;
                    float* cc = acc[mt][nt];
                    mma_bf16(cc[0], cc[1], cc[2], cc[3],
                             ah[mt][0], ah[mt][1], ah[mt][2], ah[mt][3],
                             bh[p][h], bh[p][h + 2]);
                    mma_bf16(cc[0], cc[1], cc[2], cc[3],
                             ah[mt][0], ah[mt][1], ah[mt][2], ah[mt][3],
                             bl[p][h], bl[p][h + 2]);
                    mma_bf16(cc[0], cc[1], cc[2], cc[3],
                             al[mt][0], al[mt][1], al[mt][2], al[mt][3],
                             bh[p][h], bh[p][h + 2]);
                }
            }
        }
        __syncthreads();
    }

    const float* fbr = fb + (size_t)e * NF + n0;
    #pragma unroll
    for (int mt = 0; mt < 4; mt++) {
        const int r0 = wm * 64 + mt * 16 + (lid >> 2);
        const int r1 = r0 + 8;
        const int tok0 = toks[r0], tok1 = toks[r1];
        const float w0 = wts[r0],  w1 = wts[r1];
        #pragma unroll
        for (int nt = 0; nt < 4; nt++) {
            const int cb = wn * 32 + nt * 8 + (lid & 3) * 2;
            const float b0v = fbr[cb], b1v = fbr[cb + 1];
            const float* cc = acc[mt][nt];
            if (tok0 >= 0) {
                float* orow = out + (size_t)tok0 * NF + n0 + cb;
                atomicAdd(orow + 0, w0 * (cc[0] + b0v));
                atomicAdd(orow + 1, w0 * (cc[1] + b1v));
            }
            if (tok1 >= 0) {
                float* orow = out + (size_t)tok1 * NF + n0 + cb;
                atomicAdd(orow + 0, w1 * (cc[2] + b0v));
                atomicAdd(orow + 1, w1 * (cc[3] + b1v));
            }
        }
    }
}

// ---------------- launch ----------------
extern "C" void kernel_launch(void* const* d_in, const int* in_sizes, int n_in,
                              void* d_out, int out_size) {
    const float* feat  = (const float*)d_in[0];  // [B,F]
    const float* pw    = (const float*)d_in[1];  // [H,F]
    const float* pb    = (const float*)d_in[2];  // [H]
    const float* emb   = (const float*)d_in[3];  // [E,H]
    const float* ef    = (const float*)d_in[4];  // [E,F]
    const float* trust = (const float*)d_in[5];  // [E]
    const float* dt    = (const float*)d_in[6];  // [E]
    const float* fw    = (const float*)d_in[7];  // [E,F,F]
    const float* fb    = (const float*)d_in[8];  // [E,F]
    float* out = (float*)d_out;

    static bool attr_done = false;
    if (!attr_done) {
        cudaFuncSetAttribute(route_gemm,
                             cudaFuncAttributeMaxDynamicSharedMemorySize, ROUT_SMEM);
        cudaFuncSetAttribute(moe_gemm_mma,
                             cudaFuncAttributeMaxDynamicSharedMemorySize, MG_SMEM);
        attr_done = true;
    }

    init_kernel<<<1, 64>>>(ef, trust, dt);
    pregate_kernel<<<NE, 256>>>(pw, pb, emb);
    zero_kernel<<<(NB * NF) / (256 * 4), 256>>>((float4*)out);
    convert_x<<<512, 256>>>(feat);
    convert_w<<<dim3(8, 8, NE), 256>>>(fw);
    route_gemm<<<dim3(2, NB / 16), 256, ROUT_SMEM>>>(feat, ef);
    route_topk<<<NB / 8, 256>>>();
    moe_gemm_mma<<<dim3(4, NE, NB / 128), 256, MG_SMEM>>>(fb, out);
}

// round 11
// speedup vs baseline: 1.4245x; 1.0250x over previous
#include <cuda_runtime.h>
#include <cuda_bf16.h>
#include <math.h>
#include <stdint.h>

#define NB 2048   // batch
#define NF 512    // features
#define NH 256    // hidden
#define NE 64     // experts
#define NK 8      // top-k

typedef unsigned int u32;
typedef unsigned long long u64;

// ---------------- scratch (no allocation allowed) ----------------
__device__ int   g_counts[NE];
__device__ int   g_tok[NE * NB];
__device__ float g_wt[NE * NB];
__device__ float g_escale[NE];
__device__ float g_efinv[NE];
__device__ float g_xinv[NB];
__device__ float g_gw[NE * NF];        // gate matrix: emb @ pw  [e][f]
__device__ float g_gc[NE];             // gate bias:   pb . emb_e
__device__ float g_L[NB * NE];         // raw gate logits (pre-bias)
__device__ float g_S[NB * NE];         // raw sims (pre-normalization)
// bf16 hi/lo split buffers
__device__ __nv_bfloat16 g_xhi[NB * NF];               // 2MB
__device__ __nv_bfloat16 g_xlo[NB * NF];               // 2MB
__device__ __nv_bfloat16 g_wthi[(size_t)NE * NF * NF]; // 33.5MB, layout [e][n][k]
__device__ __nv_bfloat16 g_wtlo[(size_t)NE * NF * NF]; // 33.5MB

// ---------------- PTX helpers ----------------
__device__ __forceinline__ uint32_t smem_to_u32(const void* p) {
    uint32_t a;
    asm("{ .reg .u64 t; cvta.to.shared.u64 t, %1; cvt.u32.u64 %0, t; }"
        : "=r"(a) : "l"(p));
    return a;
}
__device__ __forceinline__ void cp16(uint32_t dst, const void* src, int srcsize) {
    asm volatile("cp.async.cg.shared.global [%0], [%1], 16, %2;"
                 :: "r"(dst), "l"(src), "r"(srcsize));
}
#define CP_COMMIT() asm volatile("cp.async.commit_group;" ::: "memory")
#define CP_WAIT(n)  asm volatile("cp.async.wait_group %0;" :: "n"(n) : "memory")

__device__ __forceinline__ void ldm_x4(u32& r0, u32& r1, u32& r2, u32& r3, u32 addr) {
    asm volatile("ldmatrix.sync.aligned.m8n8.x4.shared.b16 {%0,%1,%2,%3}, [%4];"
                 : "=r"(r0), "=r"(r1), "=r"(r2), "=r"(r3) : "r"(addr));
}
__device__ __forceinline__ void mma_bf16(float& c0, float& c1, float& c2, float& c3,
                                         u32 a0, u32 a1, u32 a2, u32 a3,
                                         u32 b0, u32 b1) {
    asm volatile("mma.sync.aligned.m16n8k16.row.col.f32.bf16.bf16.f32 "
                 "{%0,%1,%2,%3}, {%4,%5,%6,%7}, {%8,%9}, {%0,%1,%2,%3};"
                 : "+f"(c0), "+f"(c1), "+f"(c2), "+f"(c3)
                 : "r"(a0), "r"(a1), "r"(a2), "r"(a3), "r"(b0), "r"(b1));
}
__device__ __forceinline__ void fma2(u64& acc, u64 a, u64 b) {
    asm("fma.rn.f32x2 %0, %1, %2, %0;" : "+l"(acc) : "l"(a), "l"(b));
}
__device__ __forceinline__ u64 pack_dup(float x) {
    u64 p;
    asm("mov.b64 %0, {%1, %1};" : "=l"(p) : "f"(x));
    return p;
}
__device__ __forceinline__ float2 unpack2(u64 v) {
    float2 r;
    asm("mov.b64 {%0, %1}, %2;" : "=f"(r.x), "=f"(r.y) : "l"(v));
    return r;
}

// ---------------- bf16 hi/lo split ----------------
__device__ __forceinline__ void split2(float a, float b, u32& hi, u32& lo) {
    __nv_bfloat16 ah = __float2bfloat16(a), bh = __float2bfloat16(b);
    float ar = a - __bfloat162float(ah);
    float br = b - __bfloat162float(bh);
    __nv_bfloat16 al = __float2bfloat16(ar), bl = __float2bfloat16(br);
    hi = (u32)__bfloat16_as_ushort(ah) | ((u32)__bfloat16_as_ushort(bh) << 16);
    lo = (u32)__bfloat16_as_ushort(al) | ((u32)__bfloat16_as_ushort(bl) << 16);
}

// ---------------- kernel 0: per-expert scalars + count reset ----------------
__global__ void init_kernel(const float* __restrict__ ef,
                            const float* __restrict__ trust,
                            const float* __restrict__ dt) {
    int e = threadIdx.x;
    if (e < NE) {
        g_counts[e] = 0;
        g_escale[e] = trust[e] * fmaxf(0.1f, expf(-0.005f * dt[e]));
        const float4* r = (const float4*)(ef + e * NF);
        float s = 0.f;
        #pragma unroll 8
        for (int i = 0; i < NF / 4; i++) {
            float4 v = r[i];
            s += v.x * v.x + v.y * v.y + v.z * v.z + v.w * v.w;
        }
        g_efinv[e] = 1.0f / fmaxf(sqrtf(s), 1e-8f);
    }
}

// ---------------- kernel 0b: gate matrix precompute --------------------
__global__ void __launch_bounds__(256)
pregate_kernel(const float* __restrict__ pw, const float* __restrict__ pb,
               const float* __restrict__ emb) {
    __shared__ float es[NH];
    const int e   = blockIdx.x;
    const int tid = threadIdx.x;
    es[tid] = emb[(size_t)e * NH + tid];
    __syncthreads();

    const int f0 = tid, f1 = tid + 256;
    float a0 = 0.f, a1 = 0.f;
    #pragma unroll 8
    for (int h = 0; h < NH; h++) {
        float ev = es[h];
        a0 += ev * pw[(size_t)h * NF + f0];
        a1 += ev * pw[(size_t)h * NF + f1];
    }
    g_gw[e * NF + f0] = a0;
    g_gw[e * NF + f1] = a1;

    if (tid < 32) {
        float s = 0.f;
        #pragma unroll
        for (int h = tid; h < NH; h += 32) s += pb[h] * es[h];
        #pragma unroll
        for (int off = 16; off > 0; off >>= 1)
            s += __shfl_xor_sync(0xffffffffu, s, off);
        if (tid == 0) g_gc[e] = s;
    }
}

// ---------------- kernel 1: zero output ----------------
__global__ void zero_kernel(float4* __restrict__ out) {
    out[blockIdx.x * 256 + threadIdx.x] = make_float4(0.f, 0.f, 0.f, 0.f);
}

// ---------------- kernel 1b: convert X to bf16 hi/lo ----------------
__global__ void convert_x(const float* __restrict__ feat) {
    u32* xh = (u32*)g_xhi;
    u32* xl = (u32*)g_xlo;
    int p = blockIdx.x * 256 + threadIdx.x;
    const int npairs = NB * NF / 2;
    for (; p < npairs; p += gridDim.x * 256) {
        float2 v = *(const float2*)(feat + 2 * p);
        u32 hi, lo;
        split2(v.x, v.y, hi, lo);
        xh[p] = hi; xl[p] = lo;
    }
}

// ---------------- kernel 1c: convert + transpose W -> [e][n][k] bf16 hi/lo ----
__global__ void __launch_bounds__(256)
convert_w(const float* __restrict__ fw) {
    __shared__ float s[64][65];
    const int e  = blockIdx.z;
    const int k0 = blockIdx.x * 64;
    const int n0 = blockIdx.y * 64;
    const int tid = threadIdx.x;
    const float* src = fw + ((size_t)e * NF + k0) * NF + n0;
    #pragma unroll
    for (int i = 0; i < 16; i++) {
        int idx = tid + 256 * i;
        int kl = idx >> 6, nl = idx & 63;
        s[kl][nl] = src[(size_t)kl * NF + nl];
    }
    __syncthreads();
    u32* wh = (u32*)g_wthi;
    u32* wl = (u32*)g_wtlo;
    #pragma unroll
    for (int i = 0; i < 8; i++) {
        int idx = tid + 256 * i;
        int nl = idx >> 5;
        int kp = (idx & 31) * 2;
        float a = s[kp][nl], b = s[kp + 1][nl];
        u32 hi, lo;
        split2(a, b, hi, lo);
        size_t off = (((size_t)e * NF + n0 + nl) * NF + k0 + kp) >> 1;
        wh[off] = hi; wl[off] = lo;
    }
}

// ---------------- kernel 2a: routing GEMM halves ---------------------------
#define V5_XSS 516
#define V5_BSS 68
#define V5_XS  0
#define V5_BS  (16 * V5_XSS)                  // 8256
#define ROUT_SMEM ((V5_BS + 32 * V5_BSS) * 4) // ~41.7KB

__global__ void __launch_bounds__(256)
route_gemm(const float* __restrict__ feat, const float* __restrict__ ef) {
    extern __shared__ float sm[];
    float* xs = sm + V5_XS;
    float* bs = sm + V5_BS;

    const int tid  = threadIdx.x;
    const int half = blockIdx.x;
    const int t0   = blockIdx.y * 16;

    const float4* feat4 = (const float4*)feat;
    #pragma unroll
    for (int i = 0; i < 8; i++) {
        int idx = tid + 256 * i;
        int t   = idx >> 7;
        int q   = idx & 127;
        float4 v = feat4[(size_t)(t0 + t) * 128 + q];
        *(float4*)(xs + t * V5_XSS + q * 4) = v;
    }
    __syncthreads();

    if (half == 1 && tid < 16) {
        const float* xr = xs + tid * V5_XSS;
        float s = 0.f;
        #pragma unroll 8
        for (int i = 0; i < NF / 4; i++) {
            float4 v = *(const float4*)(xr + i * 4);
            s += v.x * v.x + v.y * v.y + v.z * v.z + v.w * v.w;
        }
        g_xinv[t0 + tid] = 1.0f / fmaxf(sqrtf(s), 1e-8f);
    }

    const float* bsrc = half ? ef : g_gw;
    const int t  = tid & 15;
    const int cg = tid >> 4;
    u64 acc0 = 0ULL, acc1 = 0ULL;

    for (int k0 = 0; k0 < NF; k0 += 32) {
        #pragma unroll
        for (int i = 0; i < 2; i++) {
            int idx = tid + 256 * i;
            int row = idx >> 3;
            int kq  = idx & 7;
            float4 v = *(const float4*)(bsrc + (size_t)row * NF + k0 + kq * 4);
            bs[(kq * 4 + 0) * V5_BSS + row] = v.x;
            bs[(kq * 4 + 1) * V5_BSS + row] = v.y;
            bs[(kq * 4 + 2) * V5_BSS + row] = v.z;
            bs[(kq * 4 + 3) * V5_BSS + row] = v.w;
        }
        __syncthreads();
        #pragma unroll
        for (int kk = 0; kk < 32; kk++) {
            u64 xp = pack_dup(xs[t * V5_XSS + k0 + kk]);
            ulonglong2 w = *(const ulonglong2*)(bs + kk * V5_BSS + cg * 4);
            fma2(acc0, xp, w.x);
            fma2(acc1, xp, w.y);
        }
        __syncthreads();
    }

    float* dst = (half ? g_S : g_L) + (size_t)(t0 + t) * NE + cg * 4;
    float2 a0 = unpack2(acc0), a1 = unpack2(acc1);
    dst[0] = a0.x; dst[1] = a0.y; dst[2] = a1.x; dst[3] = a1.y;
}

// ---------------- kernel 2b: score + top-8 + softmax + scatter -------------
__global__ void __launch_bounds__(256)
route_topk() {
    const int tid  = threadIdx.x;
    const int lane = tid & 31;
    const int tok  = blockIdx.x * 8 + (tid >> 5);
    const float xi = g_xinv[tok];

    float s0, s1;
    {
        int e0 = lane, e1 = lane + 32;
        float gate0 = 1.0f / (1.0f + expf(-(g_L[(size_t)tok * NE + e0] + g_gc[e0]) * 0.0625f));
        float gate1 = 1.0f / (1.0f + expf(-(g_L[(size_t)tok * NE + e1] + g_gc[e1]) * 0.0625f));
        float sim0  = fmaxf(g_S[(size_t)tok * NE + e0] * xi * g_efinv[e0], 0.f);
        float sim1  = fmaxf(g_S[(size_t)tok * NE + e1] * xi * g_efinv[e1], 0.f);
        s0 = gate0 * sim0 * g_escale[e0];
        s1 = gate1 * sim1 * g_escale[e1];
    }
    const int e0 = lane, e1 = lane + 32;

    float vk[NK];
    int   ik[NK];
    #pragma unroll
    for (int k = 0; k < NK; k++) {
        float v; int ix;
        if (s0 >= s1) { v = s0; ix = e0; }
        else          { v = s1; ix = e1; }
        #pragma unroll
        for (int off = 16; off > 0; off >>= 1) {
            float ov = __shfl_down_sync(0xffffffffu, v, off);
            int   oi = __shfl_down_sync(0xffffffffu, ix, off);
            if (ov > v || (ov == v && oi < ix)) { v = ov; ix = oi; }
        }
        v  = __shfl_sync(0xffffffffu, v, 0);
        ix = __shfl_sync(0xffffffffu, ix, 0);
        vk[k] = v; ik[k] = ix;
        if (ix == e0) s0 = -1e30f;
        if (ix == e1) s1 = -1e30f;
    }
    float m = vk[0], sum = 0.f, w[NK];
    #pragma unroll
    for (int k = 0; k < NK; k++) { w[k] = expf(vk[k] - m); sum += w[k]; }
    float inv = 1.0f / sum;
    if (lane < NK) {
        int e = ik[lane];
        int slot = atomicAdd(&g_counts[e], 1);
        g_tok[e * NB + slot] = tok;
        g_wt[e * NB + slot]  = w[lane] * inv;
    }
}

// ---------------- kernel 3: mma.sync bf16 hi/lo grouped MoE GEMM (R4/R8) ---
#define MG_DATA    1024
#define MG_BUF     65536
#define MG_AHI     0
#define MG_ALO     16384
#define MG_BHI     32768
#define MG_BLO     49152
#define MG_SMEM    (MG_DATA + 2 * MG_BUF)   // 132096 bytes

__global__ void __launch_bounds__(256, 1)
moe_gemm_mma(const float* __restrict__ fb, float* __restrict__ out) {
    const int e    = blockIdx.y;
    const int n0   = blockIdx.x * 128;
    const int tile = blockIdx.z;
    const int cnt  = g_counts[e];
    if (tile * 128 >= cnt) return;

    extern __shared__ char smem[];
    const uint32_t sb = smem_to_u32(smem);
    const int tid = threadIdx.x;

    int*   toks = (int*)(smem);
    float* wts  = (float*)(smem + 512);
    {
        int s = tile * 128 + tid;
        if (tid < 128) {
            if (s < cnt) { toks[tid] = g_tok[e * NB + s]; wts[tid] = g_wt[e * NB + s]; }
            else         { toks[tid] = -1;                wts[tid] = 0.f; }
        }
    }
    __syncthreads();

    const int srow  = tid >> 1;
    const int spart = (tid & 1) * 4;
    const int stok  = toks[srow];
    const int asz   = (stok >= 0) ? 16 : 0;
    const uint4* aH = (const uint4*)(g_xhi + (size_t)max(stok, 0) * NF);
    const uint4* aL = (const uint4*)(g_xlo + (size_t)max(stok, 0) * NF);
    const uint4* bH = (const uint4*)(g_wthi + ((size_t)e * NF + n0 + srow) * NF);
    const uint4* bL = (const uint4*)(g_wtlo + ((size_t)e * NF + n0 + srow) * NF);
    const uint32_t srowb = sb + MG_DATA + srow * 128;
    const int      ssw   = (srow & 7) * 16;

    #define PREFETCH(c)                                                          \
    do {                                                                         \
        const int _buf = (c) & 1;                                                \
        const uint32_t _d = srowb + _buf * MG_BUF;                               \
        _Pragma("unroll")                                                        \
        for (int j = 0; j < 4; j++) {                                            \
            const int c16 = spart + j;                                           \
            const uint32_t off = (uint32_t)((c16 * 16) ^ ssw);                   \
            cp16(_d + MG_AHI + off, aH + (c) * 8 + c16, asz);                    \
            cp16(_d + MG_ALO + off, aL + (c) * 8 + c16, asz);                    \
            cp16(_d + MG_BHI + off, bH + (c) * 8 + c16, 16);                     \
            cp16(_d + MG_BLO + off, bL + (c) * 8 + c16, 16);                     \
        }                                                                        \
    } while (0)

    PREFETCH(0);
    CP_COMMIT();

    const int lid = tid & 31;
    const int wid = tid >> 5;
    const int wm  = wid & 1;
    const int wn  = wid >> 1;

    float acc[4][4][4];
    #pragma unroll
    for (int mt = 0; mt < 4; mt++)
        #pragma unroll
        for (int nt = 0; nt < 4; nt++)
            #pragma unroll
            for (int q = 0; q < 4; q++) acc[mt][nt][q] = 0.f;

    const int fa_row = (lid & 15);
    const int fa_hi  = (lid >> 4);

    for (int c = 0; c < 8; c++) {
        if (c < 7) { PREFETCH(c + 1); CP_COMMIT(); CP_WAIT(1); }
        else       { CP_WAIT(0); }
        __syncthreads();

        const uint32_t base = sb + MG_DATA + (c & 1) * MG_BUF;

        #pragma unroll
        for (int ks = 0; ks < 4; ks++) {
            const int c16 = ks * 2 + fa_hi;
            u32 ah[4][4], al[4][4];
            #pragma unroll
            for (int mt = 0; mt < 4; mt++) {
                const int r = wm * 64 + mt * 16 + fa_row;
                const uint32_t off = r * 128 + (uint32_t)((c16 * 16) ^ ((r & 7) * 16));
                ldm_x4(ah[mt][0], ah[mt][1], ah[mt][2], ah[mt][3], base + MG_AHI + off);
                ldm_x4(al[mt][0], al[mt][1], al[mt][2], al[mt][3], base + MG_ALO + off);
            }
            u32 bh[2][4], bl[2][4];
            #pragma unroll
            for (int p = 0; p < 2; p++) {
                const int r = wn * 32 + p * 16 + fa_row;
                const uint32_t off = r * 128 + (uint32_t)((c16 * 16) ^ ((r & 7) * 16));
                ldm_x4(bh[p][0], bh[p][1], bh[p][2], bh[p][3], base + MG_BHI + off);
                ldm_x4(bl[p][0], bl[p][1], bl[p][2], bl[p][3], base + MG_BLO + off);
            }
            #pragma unroll
            for (int mt = 0; mt < 4; mt++) {
                #pragma unroll
                for (int nt = 0; nt < 4; nt++) {
                    const int p = nt >> 1, h = nt & 1;
                    float* cc = acc[mt][nt];
                    mma_bf16(cc[0], cc[1], cc[2], cc[3],
                             ah[mt][0], ah[mt][1], ah[mt][2], ah[mt][3],
                             bh[p][h], bh[p][h + 2]);
                    mma_bf16(cc[0], cc[1], cc[2], cc[3],
                             ah[mt][0], ah[mt][1], ah[mt][2], ah[mt][3],
                             bl[p][h], bl[p][h + 2]);
                    mma_bf16(cc[0], cc[1], cc[2], cc[3],
                             al[mt][0], al[mt][1], al[mt][2], al[mt][3],
                             bh[p][h], bh[p][h + 2]);
                }
            }
        }
        __syncthreads();
    }

    const float* fbr = fb + (size_t)e * NF + n0;
    #pragma unroll
    for (int mt = 0; mt < 4; mt++) {
        const int r0 = wm * 64 + mt * 16 + (lid >> 2);
        const int r1 = r0 + 8;
        const int tok0 = toks[r0], tok1 = toks[r1];
        const float w0 = wts[r0],  w1 = wts[r1];
        #pragma unroll
        for (int nt = 0; nt < 4; nt++) {
            const int cb = wn * 32 + nt * 8 + (lid & 3) * 2;
            const float b0v = fbr[cb], b1v = fbr[cb + 1];
            const float* cc = acc[mt][nt];
            if (tok0 >= 0) {
                float* orow = out + (size_t)tok0 * NF + n0 + cb;
                atomicAdd(orow + 0, w0 * (cc[0] + b0v));
                atomicAdd(orow + 1, w0 * (cc[1] + b1v));
            }
            if (tok1 >= 0) {
                float* orow = out + (size_t)tok1 * NF + n0 + cb;
                atomicAdd(orow + 0, w1 * (cc[2] + b0v));
                atomicAdd(orow + 1, w1 * (cc[3] + b1v));
            }
        }
    }
}

// ---------------- launch (forked-stream graph) ----------------
extern "C" void kernel_launch(void* const* d_in, const int* in_sizes, int n_in,
                              void* d_out, int out_size) {
    const float* feat  = (const float*)d_in[0];  // [B,F]
    const float* pw    = (const float*)d_in[1];  // [H,F]
    const float* pb    = (const float*)d_in[2];  // [H]
    const float* emb   = (const float*)d_in[3];  // [E,H]
    const float* ef    = (const float*)d_in[4];  // [E,F]
    const float* trust = (const float*)d_in[5];  // [E]
    const float* dt    = (const float*)d_in[6];  // [E]
    const float* fw    = (const float*)d_in[7];  // [E,F,F]
    const float* fb    = (const float*)d_in[8];  // [E,F]
    float* out = (float*)d_out;

    static bool init_done = false;
    static cudaStream_t s1, s2;
    static cudaEvent_t evRoot, evJ1, evJ2;
    if (!init_done) {
        cudaFuncSetAttribute(route_gemm,
                             cudaFuncAttributeMaxDynamicSharedMemorySize, ROUT_SMEM);
        cudaFuncSetAttribute(moe_gemm_mma,
                             cudaFuncAttributeMaxDynamicSharedMemorySize, MG_SMEM);
        cudaStreamCreateWithFlags(&s1, cudaStreamNonBlocking);
        cudaStreamCreateWithFlags(&s2, cudaStreamNonBlocking);
        cudaEventCreateWithFlags(&evRoot, cudaEventDisableTiming);
        cudaEventCreateWithFlags(&evJ1,   cudaEventDisableTiming);
        cudaEventCreateWithFlags(&evJ2,   cudaEventDisableTiming);
        init_done = true;
    }

    // fork
    cudaEventRecord(evRoot, 0);
    cudaStreamWaitEvent(s1, evRoot, 0);
    cudaStreamWaitEvent(s2, evRoot, 0);

    // side 1: weight conversion (DRAM-bound, 23us)
    convert_w<<<dim3(8, 8, NE), 256, 0, s1>>>(fw);
    // side 2: output zero + X conversion (11us)
    zero_kernel<<<(NB * NF) / (256 * 4), 256, 0, s2>>>((float4*)out);
    convert_x<<<512, 256, 0, s2>>>(feat);
    // main: routing chain (compute-bound, ~20us)
    init_kernel<<<1, 64>>>(ef, trust, dt);
    pregate_kernel<<<NE, 256>>>(pw, pb, emb);
    route_gemm<<<dim3(2, NB / 16), 256, ROUT_SMEM>>>(feat, ef);
    route_topk<<<NB / 8, 256>>>();

    // join
    cudaEventRecord(evJ1, s1);
    cudaEventRecord(evJ2, s2);
    cudaStreamWaitEvent(0, evJ1, 0);
    cudaStreamWaitEvent(0, evJ2, 0);

    moe_gemm_mma<<<dim3(4, NE, NB / 128), 256, MG_SMEM>>>(fb, out);
}

// round 12
// speedup vs baseline: 1.5219x; 1.0684x over previous
#include <cuda_runtime.h>
#include <cuda_bf16.h>
#include <math.h>
#include <stdint.h>

#define NB 2048   // batch
#define NF 512    // features
#define NH 256    // hidden
#define NE 64     // experts
#define NK 8      // top-k

typedef unsigned int u32;
typedef unsigned long long u64;

// ---------------- scratch (no allocation allowed) ----------------
__device__ int   g_counts[NE];
__device__ int   g_tok[NE * NB];
__device__ float g_wt[NE * NB];
__device__ float g_escale[NE];
__device__ float g_efinv[NE];
__device__ float g_xinv[NB];
__device__ float g_gw[NE * NF];        // gate matrix: emb @ pw  [e][f]
__device__ float g_gc[NE];             // gate bias:   pb . emb_e
__device__ float g_L[NB * NE];         // raw gate logits (pre-bias)
__device__ float g_S[NB * NE];         // raw sims (pre-normalization)
// bf16 hi/lo split buffers
__device__ __nv_bfloat16 g_xhi[NB * NF];               // 2MB
__device__ __nv_bfloat16 g_xlo[NB * NF];               // 2MB
__device__ __nv_bfloat16 g_wthi[(size_t)NE * NF * NF]; // 33.5MB, layout [e][n][k]
__device__ __nv_bfloat16 g_wtlo[(size_t)NE * NF * NF]; // 33.5MB

// ---------------- PTX helpers ----------------
__device__ __forceinline__ uint32_t smem_to_u32(const void* p) {
    uint32_t a;
    asm("{ .reg .u64 t; cvta.to.shared.u64 t, %1; cvt.u32.u64 %0, t; }"
        : "=r"(a) : "l"(p));
    return a;
}
__device__ __forceinline__ void cp16(uint32_t dst, const void* src, int srcsize) {
    asm volatile("cp.async.cg.shared.global [%0], [%1], 16, %2;"
                 :: "r"(dst), "l"(src), "r"(srcsize));
}
#define CP_COMMIT() asm volatile("cp.async.commit_group;" ::: "memory")
#define CP_WAIT(n)  asm volatile("cp.async.wait_group %0;" :: "n"(n) : "memory")

__device__ __forceinline__ void ldm_x4(u32& r0, u32& r1, u32& r2, u32& r3, u32 addr) {
    asm volatile("ldmatrix.sync.aligned.m8n8.x4.shared.b16 {%0,%1,%2,%3}, [%4];"
                 : "=r"(r0), "=r"(r1), "=r"(r2), "=r"(r3) : "r"(addr));
}
__device__ __forceinline__ void mma_bf16(float& c0, float& c1, float& c2, float& c3,
                                         u32 a0, u32 a1, u32 a2, u32 a3,
                                         u32 b0, u32 b1) {
    asm volatile("mma.sync.aligned.m16n8k16.row.col.f32.bf16.bf16.f32 "
                 "{%0,%1,%2,%3}, {%4,%5,%6,%7}, {%8,%9}, {%0,%1,%2,%3};"
                 : "+f"(c0), "+f"(c1), "+f"(c2), "+f"(c3)
                 : "r"(a0), "r"(a1), "r"(a2), "r"(a3), "r"(b0), "r"(b1));
}
__device__ __forceinline__ void fma2(u64& acc, u64 a, u64 b) {
    asm("fma.rn.f32x2 %0, %1, %2, %0;" : "+l"(acc) : "l"(a), "l"(b));
}
__device__ __forceinline__ u64 pack_dup(float x) {
    u64 p;
    asm("mov.b64 %0, {%1, %1};" : "=l"(p) : "f"(x));
    return p;
}
__device__ __forceinline__ float2 unpack2(u64 v) {
    float2 r;
    asm("mov.b64 {%0, %1}, %2;" : "=f"(r.x), "=f"(r.y) : "l"(v));
    return r;
}

// ---------------- bf16 hi/lo split ----------------
__device__ __forceinline__ void split2(float a, float b, u32& hi, u32& lo) {
    __nv_bfloat16 ah = __float2bfloat16(a), bh = __float2bfloat16(b);
    float ar = a - __bfloat162float(ah);
    float br = b - __bfloat162float(bh);
    __nv_bfloat16 al = __float2bfloat16(ar), bl = __float2bfloat16(br);
    hi = (u32)__bfloat16_as_ushort(ah) | ((u32)__bfloat16_as_ushort(bh) << 16);
    lo = (u32)__bfloat16_as_ushort(al) | ((u32)__bfloat16_as_ushort(bl) << 16);
}

// ---------------- kernel 0: per-expert scalars (warp/expert, parallel) -----
__global__ void __launch_bounds__(1024)
init_kernel(const float* __restrict__ ef, const float* __restrict__ trust,
            const float* __restrict__ dt) {
    const int w    = (blockIdx.x * 1024 + threadIdx.x) >> 5;   // expert = warp
    const int lane = threadIdx.x & 31;
    const float4* r = (const float4*)(ef + (size_t)w * NF);
    float s = 0.f;
    #pragma unroll
    for (int j = 0; j < 4; j++) {
        float4 v = r[lane + 32 * j];
        s += v.x * v.x + v.y * v.y + v.z * v.z + v.w * v.w;
    }
    #pragma unroll
    for (int off = 16; off > 0; off >>= 1)
        s += __shfl_xor_sync(0xffffffffu, s, off);
    if (lane == 0) {
        g_counts[w] = 0;
        g_escale[w] = trust[w] * fmaxf(0.1f, expf(-0.005f * dt[w]));
        g_efinv[w]  = 1.0f / fmaxf(sqrtf(s), 1e-8f);
    }
}

// ---------------- kernel 0b: gate matrix precompute --------------------
__global__ void __launch_bounds__(256)
pregate_kernel(const float* __restrict__ pw, const float* __restrict__ pb,
               const float* __restrict__ emb) {
    __shared__ float es[NH];
    const int e   = blockIdx.x;
    const int tid = threadIdx.x;
    es[tid] = emb[(size_t)e * NH + tid];
    __syncthreads();

    const int f0 = tid, f1 = tid + 256;
    float a0 = 0.f, a1 = 0.f;
    #pragma unroll 8
    for (int h = 0; h < NH; h++) {
        float ev = es[h];
        a0 += ev * pw[(size_t)h * NF + f0];
        a1 += ev * pw[(size_t)h * NF + f1];
    }
    g_gw[e * NF + f0] = a0;
    g_gw[e * NF + f1] = a1;

    if (tid < 32) {
        float s = 0.f;
        #pragma unroll
        for (int h = tid; h < NH; h += 32) s += pb[h] * es[h];
        #pragma unroll
        for (int off = 16; off > 0; off >>= 1)
            s += __shfl_xor_sync(0xffffffffu, s, off);
        if (tid == 0) g_gc[e] = s;
    }
}

// ---------------- kernel 1: zero output ----------------
__global__ void zero_kernel(float4* __restrict__ out) {
    out[blockIdx.x * 256 + threadIdx.x] = make_float4(0.f, 0.f, 0.f, 0.f);
}

// ---------------- kernel 1b: convert X to bf16 hi/lo ----------------
__global__ void convert_x(const float* __restrict__ feat) {
    u32* xh = (u32*)g_xhi;
    u32* xl = (u32*)g_xlo;
    int p = blockIdx.x * 256 + threadIdx.x;
    const int npairs = NB * NF / 2;
    for (; p < npairs; p += gridDim.x * 256) {
        float2 v = *(const float2*)(feat + 2 * p);
        u32 hi, lo;
        split2(v.x, v.y, hi, lo);
        xh[p] = hi; xl[p] = lo;
    }
}

// ---------------- kernel 1c: convert + transpose W -> [e][n][k] bf16 hi/lo ----
__global__ void __launch_bounds__(256)
convert_w(const float* __restrict__ fw) {
    __shared__ float s[64][65];
    const int e  = blockIdx.z;
    const int k0 = blockIdx.x * 64;
    const int n0 = blockIdx.y * 64;
    const int tid = threadIdx.x;
    const float* src = fw + ((size_t)e * NF + k0) * NF + n0;
    #pragma unroll
    for (int i = 0; i < 16; i++) {
        int idx = tid + 256 * i;
        int kl = idx >> 6, nl = idx & 63;
        s[kl][nl] = src[(size_t)kl * NF + nl];
    }
    __syncthreads();
    u32* wh = (u32*)g_wthi;
    u32* wl = (u32*)g_wtlo;
    #pragma unroll
    for (int i = 0; i < 8; i++) {
        int idx = tid + 256 * i;
        int nl = idx >> 5;
        int kp = (idx & 31) * 2;
        float a = s[kp][nl], b = s[kp + 1][nl];
        u32 hi, lo;
        split2(a, b, hi, lo);
        size_t off = (((size_t)e * NF + n0 + nl) * NF + k0 + kp) >> 1;
        wh[off] = hi; wl[off] = lo;
    }
}

// ---------------- kernel 2a: routing GEMM halves ---------------------------
#define V5_XSS 516
#define V5_BSS 68
#define V5_XS  0
#define V5_BS  (16 * V5_XSS)                  // 8256
#define ROUT_SMEM ((V5_BS + 32 * V5_BSS) * 4) // ~41.7KB

__global__ void __launch_bounds__(256)
route_gemm(const float* __restrict__ feat, const float* __restrict__ ef) {
    extern __shared__ float sm[];
    float* xs = sm + V5_XS;
    float* bs = sm + V5_BS;

    const int tid  = threadIdx.x;
    const int half = blockIdx.x;
    const int t0   = blockIdx.y * 16;

    const float4* feat4 = (const float4*)feat;
    #pragma unroll
    for (int i = 0; i < 8; i++) {
        int idx = tid + 256 * i;
        int t   = idx >> 7;
        int q   = idx & 127;
        float4 v = feat4[(size_t)(t0 + t) * 128 + q];
        *(float4*)(xs + t * V5_XSS + q * 4) = v;
    }
    __syncthreads();

    if (half == 1 && tid < 16) {
        const float* xr = xs + tid * V5_XSS;
        float s = 0.f;
        #pragma unroll 8
        for (int i = 0; i < NF / 4; i++) {
            float4 v = *(const float4*)(xr + i * 4);
            s += v.x * v.x + v.y * v.y + v.z * v.z + v.w * v.w;
        }
        g_xinv[t0 + tid] = 1.0f / fmaxf(sqrtf(s), 1e-8f);
    }

    const float* bsrc = half ? ef : g_gw;
    const int t  = tid & 15;
    const int cg = tid >> 4;
    u64 acc0 = 0ULL, acc1 = 0ULL;

    for (int k0 = 0; k0 < NF; k0 += 32) {
        #pragma unroll
        for (int i = 0; i < 2; i++) {
            int idx = tid + 256 * i;
            int row = idx >> 3;
            int kq  = idx & 7;
            float4 v = *(const float4*)(bsrc + (size_t)row * NF + k0 + kq * 4);
            bs[(kq * 4 + 0) * V5_BSS + row] = v.x;
            bs[(kq * 4 + 1) * V5_BSS + row] = v.y;
            bs[(kq * 4 + 2) * V5_BSS + row] = v.z;
            bs[(kq * 4 + 3) * V5_BSS + row] = v.w;
        }
        __syncthreads();
        #pragma unroll
        for (int kk = 0; kk < 32; kk++) {
            u64 xp = pack_dup(xs[t * V5_XSS + k0 + kk]);
            ulonglong2 w = *(const ulonglong2*)(bs + kk * V5_BSS + cg * 4);
            fma2(acc0, xp, w.x);
            fma2(acc1, xp, w.y);
        }
        __syncthreads();
    }

    float* dst = (half ? g_S : g_L) + (size_t)(t0 + t) * NE + cg * 4;
    float2 a0 = unpack2(acc0), a1 = unpack2(acc1);
    dst[0] = a0.x; dst[1] = a0.y; dst[2] = a1.x; dst[3] = a1.y;
}

// ---------------- kernel 2b: score + top-8 + softmax + scatter -------------
__global__ void __launch_bounds__(256)
route_topk() {
    const int tid  = threadIdx.x;
    const int lane = tid & 31;
    const int tok  = blockIdx.x * 8 + (tid >> 5);
    const float xi = g_xinv[tok];

    float s0, s1;
    {
        int e0 = lane, e1 = lane + 32;
        float gate0 = 1.0f / (1.0f + expf(-(g_L[(size_t)tok * NE + e0] + g_gc[e0]) * 0.0625f));
        float gate1 = 1.0f / (1.0f + expf(-(g_L[(size_t)tok * NE + e1] + g_gc[e1]) * 0.0625f));
        float sim0  = fmaxf(g_S[(size_t)tok * NE + e0] * xi * g_efinv[e0], 0.f);
        float sim1  = fmaxf(g_S[(size_t)tok * NE + e1] * xi * g_efinv[e1], 0.f);
        s0 = gate0 * sim0 * g_escale[e0];
        s1 = gate1 * sim1 * g_escale[e1];
    }
    const int e0 = lane, e1 = lane + 32;

    float vk[NK];
    int   ik[NK];
    #pragma unroll
    for (int k = 0; k < NK; k++) {
        float v; int ix;
        if (s0 >= s1) { v = s0; ix = e0; }
        else          { v = s1; ix = e1; }
        #pragma unroll
        for (int off = 16; off > 0; off >>= 1) {
            float ov = __shfl_down_sync(0xffffffffu, v, off);
            int   oi = __shfl_down_sync(0xffffffffu, ix, off);
            if (ov > v || (ov == v && oi < ix)) { v = ov; ix = oi; }
        }
        v  = __shfl_sync(0xffffffffu, v, 0);
        ix = __shfl_sync(0xffffffffu, ix, 0);
        vk[k] = v; ik[k] = ix;
        if (ix == e0) s0 = -1e30f;
        if (ix == e1) s1 = -1e30f;
    }
    float m = vk[0], sum = 0.f, w[NK];
    #pragma unroll
    for (int k = 0; k < NK; k++) { w[k] = expf(vk[k] - m); sum += w[k]; }
    float inv = 1.0f / sum;
    if (lane < NK) {
        int e = ik[lane];
        int slot = atomicAdd(&g_counts[e], 1);
        g_tok[e * NB + slot] = tok;
        g_wt[e * NB + slot]  = w[lane] * inv;
    }
}

// ---------------- kernel 3: mma.sync bf16 hi/lo grouped MoE GEMM (R4/R8) ---
#define MG_DATA    1024
#define MG_BUF     65536
#define MG_AHI     0
#define MG_ALO     16384
#define MG_BHI     32768
#define MG_BLO     49152
#define MG_SMEM    (MG_DATA + 2 * MG_BUF)   // 132096 bytes

__global__ void __launch_bounds__(256, 1)
moe_gemm_mma(const float* __restrict__ fb, float* __restrict__ out) {
    const int e    = blockIdx.y;
    const int n0   = blockIdx.x * 128;
    const int tile = blockIdx.z;
    const int cnt  = g_counts[e];
    if (tile * 128 >= cnt) return;

    extern __shared__ char smem[];
    const uint32_t sb = smem_to_u32(smem);
    const int tid = threadIdx.x;

    int*   toks = (int*)(smem);
    float* wts  = (float*)(smem + 512);
    {
        int s = tile * 128 + tid;
        if (tid < 128) {
            if (s < cnt) { toks[tid] = g_tok[e * NB + s]; wts[tid] = g_wt[e * NB + s]; }
            else         { toks[tid] = -1;                wts[tid] = 0.f; }
        }
    }
    __syncthreads();

    const int srow  = tid >> 1;
    const int spart = (tid & 1) * 4;
    const int stok  = toks[srow];
    const int asz   = (stok >= 0) ? 16 : 0;
    const uint4* aH = (const uint4*)(g_xhi + (size_t)max(stok, 0) * NF);
    const uint4* aL = (const uint4*)(g_xlo + (size_t)max(stok, 0) * NF);
    const uint4* bH = (const uint4*)(g_wthi + ((size_t)e * NF + n0 + srow) * NF);
    const uint4* bL = (const uint4*)(g_wtlo + ((size_t)e * NF + n0 + srow) * NF);
    const uint32_t srowb = sb + MG_DATA + srow * 128;
    const int      ssw   = (srow & 7) * 16;

    #define PREFETCH(c)                                                          \
    do {                                                                         \
        const int _buf = (c) & 1;                                                \
        const uint32_t _d = srowb + _buf * MG_BUF;                               \
        _Pragma("unroll")                                                        \
        for (int j = 0; j < 4; j++) {                                            \
            const int c16 = spart + j;                                           \
            const uint32_t off = (uint32_t)((c16 * 16) ^ ssw);                   \
            cp16(_d + MG_AHI + off, aH + (c) * 8 + c16, asz);                    \
            cp16(_d + MG_ALO + off, aL + (c) * 8 + c16, asz);                    \
            cp16(_d + MG_BHI + off, bH + (c) * 8 + c16, 16);                     \
            cp16(_d + MG_BLO + off, bL + (c) * 8 + c16, 16);                     \
        }                                                                        \
    } while (0)

    PREFETCH(0);
    CP_COMMIT();

    const int lid = tid & 31;
    const int wid = tid >> 5;
    const int wm  = wid & 1;
    const int wn  = wid >> 1;

    float acc[4][4][4];
    #pragma unroll
    for (int mt = 0; mt < 4; mt++)
        #pragma unroll
        for (int nt = 0; nt < 4; nt++)
            #pragma unroll
            for (int q = 0; q < 4; q++) acc[mt][nt][q] = 0.f;

    const int fa_row = (lid & 15);
    const int fa_hi  = (lid >> 4);

    for (int c = 0; c < 8; c++) {
        if (c < 7) { PREFETCH(c + 1); CP_COMMIT(); CP_WAIT(1); }
        else       { CP_WAIT(0); }
        __syncthreads();

        const uint32_t base = sb + MG_DATA + (c & 1) * MG_BUF;

        #pragma unroll
        for (int ks = 0; ks < 4; ks++) {
            const int c16 = ks * 2 + fa_hi;
            u32 ah[4][4], al[4][4];
            #pragma unroll
            for (int mt = 0; mt < 4; mt++) {
                const int r = wm * 64 + mt * 16 + fa_row;
                const uint32_t off = r * 128 + (uint32_t)((c16 * 16) ^ ((r & 7) * 16));
                ldm_x4(ah[mt][0], ah[mt][1], ah[mt][2], ah[mt][3], base + MG_AHI + off);
                ldm_x4(al[mt][0], al[mt][1], al[mt][2], al[mt][3], base + MG_ALO + off);
            }
            u32 bh[2][4], bl[2][4];
            #pragma unroll
            for (int p = 0; p < 2; p++) {
                const int r = wn * 32 + p * 16 + fa_row;
                const uint32_t off = r * 128 + (uint32_t)((c16 * 16) ^ ((r & 7) * 16));
                ldm_x4(bh[p][0], bh[p][1], bh[p][2], bh[p][3], base + MG_BHI + off);
                ldm_x4(bl[p][0], bl[p][1], bl[p][2], bl[p][3], base + MG_BLO + off);
            }
            #pragma unroll
            for (int mt = 0; mt < 4; mt++) {
                #pragma unroll
                for (int nt = 0; nt < 4; nt++) {
                    const int p = nt >> 1, h = nt & 1;
                    float* cc = acc[mt][nt];
                    mma_bf16(cc[0], cc[1], cc[2], cc[3],
                             ah[mt][0], ah[mt][1], ah[mt][2], ah[mt][3],
                             bh[p][h], bh[p][h + 2]);
                    mma_bf16(cc[0], cc[1], cc[2], cc[3],
                             ah[mt][0], ah[mt][1], ah[mt][2], ah[mt][3],
                             bl[p][h], bl[p][h + 2]);
                    mma_bf16(cc[0], cc[1], cc[2], cc[3],
                             al[mt][0], al[mt][1], al[mt][2], al[mt][3],
                             bh[p][h], bh[p][h + 2]);
                }
            }
        }
        __syncthreads();
    }

    const float* fbr = fb + (size_t)e * NF + n0;
    #pragma unroll
    for (int mt = 0; mt < 4; mt++) {
        const int r0 = wm * 64 + mt * 16 + (lid >> 2);
        const int r1 = r0 + 8;
        const int tok0 = toks[r0], tok1 = toks[r1];
        const float w0 = wts[r0],  w1 = wts[r1];
        #pragma unroll
        for (int nt = 0; nt < 4; nt++) {
            const int cb = wn * 32 + nt * 8 + (lid & 3) * 2;
            const float b0v = fbr[cb], b1v = fbr[cb + 1];
            const float* cc = acc[mt][nt];
            if (tok0 >= 0) {
                float* orow = out + (size_t)tok0 * NF + n0 + cb;
                atomicAdd(orow + 0, w0 * (cc[0] + b0v));
                atomicAdd(orow + 1, w0 * (cc[1] + b1v));
            }
            if (tok1 >= 0) {
                float* orow = out + (size_t)tok1 * NF + n0 + cb;
                atomicAdd(orow + 0, w1 * (cc[2] + b0v));
                atomicAdd(orow + 1, w1 * (cc[3] + b1v));
            }
        }
    }
}

// ---------------- launch (forked-stream graph) ----------------
extern "C" void kernel_launch(void* const* d_in, const int* in_sizes, int n_in,
                              void* d_out, int out_size) {
    const float* feat  = (const float*)d_in[0];  // [B,F]
    const float* pw    = (const float*)d_in[1];  // [H,F]
    const float* pb    = (const float*)d_in[2];  // [H]
    const float* emb   = (const float*)d_in[3];  // [E,H]
    const float* ef    = (const float*)d_in[4];  // [E,F]
    const float* trust = (const float*)d_in[5];  // [E]
    const float* dt    = (const float*)d_in[6];  // [E]
    const float* fw    = (const float*)d_in[7];  // [E,F,F]
    const float* fb    = (const float*)d_in[8];  // [E,F]
    float* out = (float*)d_out;

    static bool init_done = false;
    static cudaStream_t s1, s2;
    static cudaEvent_t evRoot, evJ1, evJ2;
    if (!init_done) {
        cudaFuncSetAttribute(route_gemm,
                             cudaFuncAttributeMaxDynamicSharedMemorySize, ROUT_SMEM);
        cudaFuncSetAttribute(moe_gemm_mma,
                             cudaFuncAttributeMaxDynamicSharedMemorySize, MG_SMEM);
        cudaStreamCreateWithFlags(&s1, cudaStreamNonBlocking);
        cudaStreamCreateWithFlags(&s2, cudaStreamNonBlocking);
        cudaEventCreateWithFlags(&evRoot, cudaEventDisableTiming);
        cudaEventCreateWithFlags(&evJ1,   cudaEventDisableTiming);
        cudaEventCreateWithFlags(&evJ2,   cudaEventDisableTiming);
        init_done = true;
    }

    // fork
    cudaEventRecord(evRoot, 0);
    cudaStreamWaitEvent(s1, evRoot, 0);
    cudaStreamWaitEvent(s2, evRoot, 0);

    // side 1: weight conversion (DRAM-bound, ~23us)
    convert_w<<<dim3(8, 8, NE), 256, 0, s1>>>(fw);
    // side 2: output zero + X conversion + per-expert init (~13us)
    zero_kernel<<<(NB * NF) / (256 * 4), 256, 0, s2>>>((float4*)out);
    convert_x<<<512, 256, 0, s2>>>(feat);
    init_kernel<<<2, 1024, 0, s2>>>(ef, trust, dt);
    // main: gate precompute -> routing GEMM (~16us)
    pregate_kernel<<<NE, 256>>>(pw, pb, emb);
    route_gemm<<<dim3(2, NB / 16), 256, ROUT_SMEM>>>(feat, ef);

    // topk needs init (s2) + route_gemm (main)
    cudaEventRecord(evJ2, s2);
    cudaStreamWaitEvent(0, evJ2, 0);
    route_topk<<<NB / 8, 256>>>();

    // moe needs everything
    cudaEventRecord(evJ1, s1);
    cudaStreamWaitEvent(0, evJ1, 0);
    moe_gemm_mma<<<dim3(4, NE, NB / 128), 256, MG_SMEM>>>(fb, out);
}

// round 13
// speedup vs baseline: 1.9812x; 1.3018x over previous
#include <cuda_runtime.h>
#include <cuda_fp16.h>
#include <math.h>
#include <stdint.h>

#define NB 2048   // batch
#define NF 512    // features
#define NH 256    // hidden
#define NE 64     // experts
#define NK 8      // top-k

typedef unsigned int u32;
typedef unsigned long long u64;

// ---------------- scratch (no allocation allowed) ----------------
__device__ int   g_counts[NE];
__device__ int   g_tok[NE * NB];
__device__ float g_wt[NE * NB];
__device__ float g_escale[NE];
__device__ float g_efinv[NE];
__device__ float g_xinv[NB];
__device__ float g_gw[NE * NF];        // gate matrix: emb @ pw  [e][f]
__device__ float g_gc[NE];             // gate bias:   pb . emb_e
__device__ float g_L[NB * NE];         // raw gate logits (pre-bias)
__device__ float g_S[NB * NE];         // raw sims (pre-normalization)
// fp16 buffers: X rounded (hi only), W split hi/lo
__device__ __half g_xh[NB * NF];                   // 2MB
__device__ __half g_wthi[(size_t)NE * NF * NF];    // 33.5MB, layout [e][n][k]
__device__ __half g_wtlo[(size_t)NE * NF * NF];    // 33.5MB

// ---------------- PTX helpers ----------------
__device__ __forceinline__ uint32_t smem_to_u32(const void* p) {
    uint32_t a;
    asm("{ .reg .u64 t; cvta.to.shared.u64 t, %1; cvt.u32.u64 %0, t; }"
        : "=r"(a) : "l"(p));
    return a;
}
__device__ __forceinline__ void cp16(uint32_t dst, const void* src, int srcsize) {
    asm volatile("cp.async.cg.shared.global [%0], [%1], 16, %2;"
                 :: "r"(dst), "l"(src), "r"(srcsize));
}
#define CP_COMMIT() asm volatile("cp.async.commit_group;" ::: "memory")
#define CP_WAIT(n)  asm volatile("cp.async.wait_group %0;" :: "n"(n) : "memory")

__device__ __forceinline__ void ldm_x4(u32& r0, u32& r1, u32& r2, u32& r3, u32 addr) {
    asm volatile("ldmatrix.sync.aligned.m8n8.x4.shared.b16 {%0,%1,%2,%3}, [%4];"
                 : "=r"(r0), "=r"(r1), "=r"(r2), "=r"(r3) : "r"(addr));
}
__device__ __forceinline__ void mma_f16(float& c0, float& c1, float& c2, float& c3,
                                        u32 a0, u32 a1, u32 a2, u32 a3,
                                        u32 b0, u32 b1) {
    asm volatile("mma.sync.aligned.m16n8k16.row.col.f32.f16.f16.f32 "
                 "{%0,%1,%2,%3}, {%4,%5,%6,%7}, {%8,%9}, {%0,%1,%2,%3};"
                 : "+f"(c0), "+f"(c1), "+f"(c2), "+f"(c3)
                 : "r"(a0), "r"(a1), "r"(a2), "r"(a3), "r"(b0), "r"(b1));
}
__device__ __forceinline__ void fma2(u64& acc, u64 a, u64 b) {
    asm("fma.rn.f32x2 %0, %1, %2, %0;" : "+l"(acc) : "l"(a), "l"(b));
}
__device__ __forceinline__ u64 pack_dup(float x) {
    u64 p;
    asm("mov.b64 %0, {%1, %1};" : "=l"(p) : "f"(x));
    return p;
}
__device__ __forceinline__ float2 unpack2(u64 v) {
    float2 r;
    asm("mov.b64 {%0, %1}, %2;" : "=f"(r.x), "=f"(r.y) : "l"(v));
    return r;
}

// ---------------- fp16 helpers ----------------
__device__ __forceinline__ u32 pack_h2(float a, float b) {
    __half ha = __float2half(a), hb = __float2half(b);
    return (u32)__half_as_ushort(ha) | ((u32)__half_as_ushort(hb) << 16);
}
__device__ __forceinline__ void split2_h(float a, float b, u32& hi, u32& lo) {
    __half ah = __float2half(a), bh = __float2half(b);
    float ar = a - __half2float(ah);
    float br = b - __half2float(bh);
    __half al = __float2half(ar), bl = __float2half(br);
    hi = (u32)__half_as_ushort(ah) | ((u32)__half_as_ushort(bh) << 16);
    lo = (u32)__half_as_ushort(al) | ((u32)__half_as_ushort(bl) << 16);
}

// ---------------- kernel 0: per-expert scalars (warp/expert) ---------------
__global__ void __launch_bounds__(1024)
init_kernel(const float* __restrict__ ef, const float* __restrict__ trust,
            const float* __restrict__ dt) {
    const int w    = (blockIdx.x * 1024 + threadIdx.x) >> 5;
    const int lane = threadIdx.x & 31;
    const float4* r = (const float4*)(ef + (size_t)w * NF);
    float s = 0.f;
    #pragma unroll
    for (int j = 0; j < 4; j++) {
        float4 v = r[lane + 32 * j];
        s += v.x * v.x + v.y * v.y + v.z * v.z + v.w * v.w;
    }
    #pragma unroll
    for (int off = 16; off > 0; off >>= 1)
        s += __shfl_xor_sync(0xffffffffu, s, off);
    if (lane == 0) {
        g_counts[w] = 0;
        g_escale[w] = trust[w] * fmaxf(0.1f, expf(-0.005f * dt[w]));
        g_efinv[w]  = 1.0f / fmaxf(sqrtf(s), 1e-8f);
    }
}

// ---------------- kernel 0b: gate matrix precompute --------------------
__global__ void __launch_bounds__(256)
pregate_kernel(const float* __restrict__ pw, const float* __restrict__ pb,
               const float* __restrict__ emb) {
    __shared__ float es[NH];
    const int e   = blockIdx.x;
    const int tid = threadIdx.x;
    es[tid] = emb[(size_t)e * NH + tid];
    __syncthreads();

    const int f0 = tid, f1 = tid + 256;
    float a0 = 0.f, a1 = 0.f;
    #pragma unroll 8
    for (int h = 0; h < NH; h++) {
        float ev = es[h];
        a0 += ev * pw[(size_t)h * NF + f0];
        a1 += ev * pw[(size_t)h * NF + f1];
    }
    g_gw[e * NF + f0] = a0;
    g_gw[e * NF + f1] = a1;

    if (tid < 32) {
        float s = 0.f;
        #pragma unroll
        for (int h = tid; h < NH; h += 32) s += pb[h] * es[h];
        #pragma unroll
        for (int off = 16; off > 0; off >>= 1)
            s += __shfl_xor_sync(0xffffffffu, s, off);
        if (tid == 0) g_gc[e] = s;
    }
}

// ---------------- kernel 1: zero output ----------------
__global__ void zero_kernel(float4* __restrict__ out) {
    out[blockIdx.x * 256 + threadIdx.x] = make_float4(0.f, 0.f, 0.f, 0.f);
}

// ---------------- kernel 1b: X -> fp16 (round only) ----------------
__global__ void convert_x(const float* __restrict__ feat) {
    u32* xh = (u32*)g_xh;
    int p = blockIdx.x * 256 + threadIdx.x;
    const int npairs = NB * NF / 2;
    for (; p < npairs; p += gridDim.x * 256) {
        float2 v = *(const float2*)(feat + 2 * p);
        xh[p] = pack_h2(v.x, v.y);
    }
}

// ---------------- kernel 1c: convert + transpose W -> [e][n][k] fp16 hi/lo --
__global__ void __launch_bounds__(256)
convert_w(const float* __restrict__ fw) {
    __shared__ float s[64][65];
    const int e  = blockIdx.z;
    const int k0 = blockIdx.x * 64;
    const int n0 = blockIdx.y * 64;
    const int tid = threadIdx.x;
    const float* src = fw + ((size_t)e * NF + k0) * NF + n0;
    #pragma unroll
    for (int i = 0; i < 16; i++) {
        int idx = tid + 256 * i;
        int kl = idx >> 6, nl = idx & 63;
        s[kl][nl] = src[(size_t)kl * NF + nl];
    }
    __syncthreads();
    u32* wh = (u32*)g_wthi;
    u32* wl = (u32*)g_wtlo;
    #pragma unroll
    for (int i = 0; i < 8; i++) {
        int idx = tid + 256 * i;
        int nl = idx >> 5;
        int kp = (idx & 31) * 2;
        float a = s[kp][nl], b = s[kp + 1][nl];
        u32 hi, lo;
        split2_h(a, b, hi, lo);
        size_t off = (((size_t)e * NF + n0 + nl) * NF + k0 + kp) >> 1;
        wh[off] = hi; wl[off] = lo;
    }
}

// ---------------- kernel 2a: routing GEMM halves ---------------------------
#define V5_XSS 516
#define V5_BSS 68
#define V5_XS  0
#define V5_BS  (16 * V5_XSS)                  // 8256
#define ROUT_SMEM ((V5_BS + 32 * V5_BSS) * 4) // ~41.7KB

__global__ void __launch_bounds__(256)
route_gemm(const float* __restrict__ feat, const float* __restrict__ ef) {
    extern __shared__ float sm[];
    float* xs = sm + V5_XS;
    float* bs = sm + V5_BS;

    const int tid  = threadIdx.x;
    const int half = blockIdx.x;
    const int t0   = blockIdx.y * 16;

    const float4* feat4 = (const float4*)feat;
    #pragma unroll
    for (int i = 0; i < 8; i++) {
        int idx = tid + 256 * i;
        int t   = idx >> 7;
        int q   = idx & 127;
        float4 v = feat4[(size_t)(t0 + t) * 128 + q];
        *(float4*)(xs + t * V5_XSS + q * 4) = v;
    }
    __syncthreads();

    if (half == 1 && tid < 16) {
        const float* xr = xs + tid * V5_XSS;
        float s = 0.f;
        #pragma unroll 8
        for (int i = 0; i < NF / 4; i++) {
            float4 v = *(const float4*)(xr + i * 4);
            s += v.x * v.x + v.y * v.y + v.z * v.z + v.w * v.w;
        }
        g_xinv[t0 + tid] = 1.0f / fmaxf(sqrtf(s), 1e-8f);
    }

    const float* bsrc = half ? ef : g_gw;
    const int t  = tid & 15;
    const int cg = tid >> 4;
    u64 acc0 = 0ULL, acc1 = 0ULL;

    for (int k0 = 0; k0 < NF; k0 += 32) {
        #pragma unroll
        for (int i = 0; i < 2; i++) {
            int idx = tid + 256 * i;
            int row = idx >> 3;
            int kq  = idx & 7;
            float4 v = *(const float4*)(bsrc + (size_t)row * NF + k0 + kq * 4);
            bs[(kq * 4 + 0) * V5_BSS + row] = v.x;
            bs[(kq * 4 + 1) * V5_BSS + row] = v.y;
            bs[(kq * 4 + 2) * V5_BSS + row] = v.z;
            bs[(kq * 4 + 3) * V5_BSS + row] = v.w;
        }
        __syncthreads();
        #pragma unroll
        for (int kk = 0; kk < 32; kk++) {
            u64 xp = pack_dup(xs[t * V5_XSS + k0 + kk]);
            ulonglong2 w = *(const ulonglong2*)(bs + kk * V5_BSS + cg * 4);
            fma2(acc0, xp, w.x);
            fma2(acc1, xp, w.y);
        }
        __syncthreads();
    }

    float* dst = (half ? g_S : g_L) + (size_t)(t0 + t) * NE + cg * 4;
    float2 a0 = unpack2(acc0), a1 = unpack2(acc1);
    dst[0] = a0.x; dst[1] = a0.y; dst[2] = a1.x; dst[3] = a1.y;
}

// ---------------- kernel 2b: score + top-8 + softmax + scatter -------------
__global__ void __launch_bounds__(256)
route_topk() {
    const int tid  = threadIdx.x;
    const int lane = tid & 31;
    const int tok  = blockIdx.x * 8 + (tid >> 5);
    const float xi = g_xinv[tok];

    float s0, s1;
    {
        int e0 = lane, e1 = lane + 32;
        float gate0 = 1.0f / (1.0f + expf(-(g_L[(size_t)tok * NE + e0] + g_gc[e0]) * 0.0625f));
        float gate1 = 1.0f / (1.0f + expf(-(g_L[(size_t)tok * NE + e1] + g_gc[e1]) * 0.0625f));
        float sim0  = fmaxf(g_S[(size_t)tok * NE + e0] * xi * g_efinv[e0], 0.f);
        float sim1  = fmaxf(g_S[(size_t)tok * NE + e1] * xi * g_efinv[e1], 0.f);
        s0 = gate0 * sim0 * g_escale[e0];
        s1 = gate1 * sim1 * g_escale[e1];
    }
    const int e0 = lane, e1 = lane + 32;

    float vk[NK];
    int   ik[NK];
    #pragma unroll
    for (int k = 0; k < NK; k++) {
        float v; int ix;
        if (s0 >= s1) { v = s0; ix = e0; }
        else          { v = s1; ix = e1; }
        #pragma unroll
        for (int off = 16; off > 0; off >>= 1) {
            float ov = __shfl_down_sync(0xffffffffu, v, off);
            int   oi = __shfl_down_sync(0xffffffffu, ix, off);
            if (ov > v || (ov == v && oi < ix)) { v = ov; ix = oi; }
        }
        v  = __shfl_sync(0xffffffffu, v, 0);
        ix = __shfl_sync(0xffffffffu, ix, 0);
        vk[k] = v; ik[k] = ix;
        if (ix == e0) s0 = -1e30f;
        if (ix == e1) s1 = -1e30f;
    }
    float m = vk[0], sum = 0.f, w[NK];
    #pragma unroll
    for (int k = 0; k < NK; k++) { w[k] = expf(vk[k] - m); sum += w[k]; }
    float inv = 1.0f / sum;
    if (lane < NK) {
        int e = ik[lane];
        int slot = atomicAdd(&g_counts[e], 1);
        g_tok[e * NB + slot] = tok;
        g_wt[e * NB + slot]  = w[lane] * inv;
    }
}

// ---------------- kernel 3: fp16 2-pass grouped MoE GEMM -------------------
// CTA tile 128 tok x 128 cols, K chunks of 64. Stage = A(16K)+BH(16K)+BL(16K)
// = 48KB, double buffered -> ~97KB smem -> 2 CTAs/SM (4 warps/SMSP).
// 2 passes per k16: Xh*Wh + Xh*Wl (X-lo dropped: ~1.4e-4 rel, under 1e-3).
#define MG_DATA    1024
#define MG_STAGE   49152
#define MG_A       0
#define MG_BH      16384
#define MG_BL      32768
#define MG_SMEM    (MG_DATA + 2 * MG_STAGE)   // 99328 bytes

__global__ void __launch_bounds__(256, 2)
moe_gemm_mma(const float* __restrict__ fb, float* __restrict__ out) {
    const int e    = blockIdx.y;
    const int n0   = blockIdx.x * 128;
    const int tile = blockIdx.z;
    const int cnt  = g_counts[e];
    if (tile * 128 >= cnt) return;

    extern __shared__ char smem[];
    const uint32_t sb = smem_to_u32(smem);
    const int tid = threadIdx.x;

    int*   toks = (int*)(smem);
    float* wts  = (float*)(smem + 512);
    {
        int s = tile * 128 + tid;
        if (tid < 128) {
            if (s < cnt) { toks[tid] = g_tok[e * NB + s]; wts[tid] = g_wt[e * NB + s]; }
            else         { toks[tid] = -1;                wts[tid] = 0.f; }
        }
    }
    __syncthreads();

    const int srow  = tid >> 1;
    const int spart = (tid & 1) * 4;
    const int stok  = toks[srow];
    const int asz   = (stok >= 0) ? 16 : 0;
    const uint4* aS = (const uint4*)(g_xh + (size_t)max(stok, 0) * NF);
    const uint4* bH = (const uint4*)(g_wthi + ((size_t)e * NF + n0 + srow) * NF);
    const uint4* bL = (const uint4*)(g_wtlo + ((size_t)e * NF + n0 + srow) * NF);
    const uint32_t srowb = sb + MG_DATA + srow * 128;
    const int      ssw   = (srow & 7) * 16;

    #define PREFETCH(c)                                                          \
    do {                                                                         \
        const uint32_t _d = srowb + ((c) & 1) * MG_STAGE;                        \
        _Pragma("unroll")                                                        \
        for (int j = 0; j < 4; j++) {                                            \
            const int c16 = spart + j;                                           \
            const uint32_t off = (uint32_t)((c16 * 16) ^ ssw);                   \
            cp16(_d + MG_A  + off, aS + (c) * 8 + c16, asz);                     \
            cp16(_d + MG_BH + off, bH + (c) * 8 + c16, 16);                      \
            cp16(_d + MG_BL + off, bL + (c) * 8 + c16, 16);                      \
        }                                                                        \
    } while (0)

    PREFETCH(0);
    CP_COMMIT();

    const int lid = tid & 31;
    const int wid = tid >> 5;
    const int wm  = wid & 1;
    const int wn  = wid >> 1;

    float acc[4][4][4];
    #pragma unroll
    for (int mt = 0; mt < 4; mt++)
        #pragma unroll
        for (int nt = 0; nt < 4; nt++)
            #pragma unroll
            for (int q = 0; q < 4; q++) acc[mt][nt][q] = 0.f;

    const int fa_row = (lid & 15);
    const int fa_hi  = (lid >> 4);

    for (int c = 0; c < 8; c++) {
        if (c < 7) { PREFETCH(c + 1); CP_COMMIT(); CP_WAIT(1); }
        else       { CP_WAIT(0); }
        __syncthreads();

        const uint32_t base = sb + MG_DATA + (c & 1) * MG_STAGE;

        #pragma unroll
        for (int ks = 0; ks < 4; ks++) {
            const int c16 = ks * 2 + fa_hi;
            u32 ah[4][4];
            #pragma unroll
            for (int mt = 0; mt < 4; mt++) {
                const int r = wm * 64 + mt * 16 + fa_row;
                const uint32_t off = r * 128 + (uint32_t)((c16 * 16) ^ ((r & 7) * 16));
                ldm_x4(ah[mt][0], ah[mt][1], ah[mt][2], ah[mt][3], base + MG_A + off);
            }
            u32 bh[2][4], bl[2][4];
            #pragma unroll
            for (int p = 0; p < 2; p++) {
                const int r = wn * 32 + p * 16 + fa_row;
                const uint32_t off = r * 128 + (uint32_t)((c16 * 16) ^ ((r & 7) * 16));
                ldm_x4(bh[p][0], bh[p][1], bh[p][2], bh[p][3], base + MG_BH + off);
                ldm_x4(bl[p][0], bl[p][1], bl[p][2], bl[p][3], base + MG_BL + off);
            }
            #pragma unroll
            for (int mt = 0; mt < 4; mt++) {
                #pragma unroll
                for (int nt = 0; nt < 4; nt++) {
                    const int p = nt >> 1, h = nt & 1;
                    float* cc = acc[mt][nt];
                    mma_f16(cc[0], cc[1], cc[2], cc[3],
                            ah[mt][0], ah[mt][1], ah[mt][2], ah[mt][3],
                            bh[p][h], bh[p][h + 2]);
                    mma_f16(cc[0], cc[1], cc[2], cc[3],
                            ah[mt][0], ah[mt][1], ah[mt][2], ah[mt][3],
                            bl[p][h], bl[p][h + 2]);
                }
            }
        }
        __syncthreads();
    }

    const float* fbr = fb + (size_t)e * NF + n0;
    #pragma unroll
    for (int mt = 0; mt < 4; mt++) {
        const int r0 = wm * 64 + mt * 16 + (lid >> 2);
        const int r1 = r0 + 8;
        const int tok0 = toks[r0], tok1 = toks[r1];
        const float w0 = wts[r0],  w1 = wts[r1];
        #pragma unroll
        for (int nt = 0; nt < 4; nt++) {
            const int cb = wn * 32 + nt * 8 + (lid & 3) * 2;
            const float b0v = fbr[cb], b1v = fbr[cb + 1];
            const float* cc = acc[mt][nt];
            if (tok0 >= 0) {
                float* orow = out + (size_t)tok0 * NF + n0 + cb;
                atomicAdd(orow + 0, w0 * (cc[0] + b0v));
                atomicAdd(orow + 1, w0 * (cc[1] + b1v));
            }
            if (tok1 >= 0) {
                float* orow = out + (size_t)tok1 * NF + n0 + cb;
                atomicAdd(orow + 0, w1 * (cc[2] + b0v));
                atomicAdd(orow + 1, w1 * (cc[3] + b1v));
            }
        }
    }
}

// ---------------- launch (forked-stream graph) ----------------
extern "C" void kernel_launch(void* const* d_in, const int* in_sizes, int n_in,
                              void* d_out, int out_size) {
    const float* feat  = (const float*)d_in[0];  // [B,F]
    const float* pw    = (const float*)d_in[1];  // [H,F]
    const float* pb    = (const float*)d_in[2];  // [H]
    const float* emb   = (const float*)d_in[3];  // [E,H]
    const float* ef    = (const float*)d_in[4];  // [E,F]
    const float* trust = (const float*)d_in[5];  // [E]
    const float* dt    = (const float*)d_in[6];  // [E]
    const float* fw    = (const float*)d_in[7];  // [E,F,F]
    const float* fb    = (const float*)d_in[8];  // [E,F]
    float* out = (float*)d_out;

    static bool init_done = false;
    static cudaStream_t s1, s2;
    static cudaEvent_t evRoot, evJ1, evJ2;
    if (!init_done) {
        cudaFuncSetAttribute(route_gemm,
                             cudaFuncAttributeMaxDynamicSharedMemorySize, ROUT_SMEM);
        cudaFuncSetAttribute(moe_gemm_mma,
                             cudaFuncAttributeMaxDynamicSharedMemorySize, MG_SMEM);
        cudaStreamCreateWithFlags(&s1, cudaStreamNonBlocking);
        cudaStreamCreateWithFlags(&s2, cudaStreamNonBlocking);
        cudaEventCreateWithFlags(&evRoot, cudaEventDisableTiming);
        cudaEventCreateWithFlags(&evJ1,   cudaEventDisableTiming);
        cudaEventCreateWithFlags(&evJ2,   cudaEventDisableTiming);
        init_done = true;
    }

    // fork
    cudaEventRecord(evRoot, 0);
    cudaStreamWaitEvent(s1, evRoot, 0);
    cudaStreamWaitEvent(s2, evRoot, 0);

    // side 1: weight conversion (DRAM-bound, ~23us)
    convert_w<<<dim3(8, 8, NE), 256, 0, s1>>>(fw);
    // side 2: output zero + X conversion + per-expert init
    zero_kernel<<<(NB * NF) / (256 * 4), 256, 0, s2>>>((float4*)out);
    convert_x<<<512, 256, 0, s2>>>(feat);
    init_kernel<<<2, 1024, 0, s2>>>(ef, trust, dt);
    // main: gate precompute -> routing GEMM
    pregate_kernel<<<NE, 256>>>(pw, pb, emb);
    route_gemm<<<dim3(2, NB / 16), 256, ROUT_SMEM>>>(feat, ef);

    // topk needs init (s2) + route_gemm (main)
    cudaEventRecord(evJ2, s2);
    cudaStreamWaitEvent(0, evJ2, 0);
    route_topk<<<NB / 8, 256>>>();

    // moe needs everything
    cudaEventRecord(evJ1, s1);
    cudaStreamWaitEvent(0, evJ1, 0);
    moe_gemm_mma<<<dim3(4, NE, NB / 128), 256, MG_SMEM>>>(fb, out);
}

// round 14
// speedup vs baseline: 2.5079x; 1.2658x over previous
#include <cuda_runtime.h>
#include <cuda_fp16.h>
#include <math.h>
#include <stdint.h>

#define NB 2048   // batch
#define NF 512    // features
#define NH 256    // hidden
#define NE 64     // experts
#define NK 8      // top-k

typedef unsigned int u32;
typedef unsigned long long u64;

// ---------------- scratch (no allocation allowed) ----------------
__device__ int   g_counts[NE];
__device__ int   g_tok[NE * NB];
__device__ float g_wt[NE * NB];
__device__ float g_escale[NE];
__device__ float g_efinv[NE];
__device__ float g_xinv[NB];
__device__ float g_gw[NE * NF];        // gate matrix: emb @ pw  [e][f]
__device__ float g_gc[NE];             // gate bias:   pb . emb_e
__device__ float g_L[NB * NE];         // raw gate logits (pre-bias)
__device__ float g_S[NB * NE];         // raw sims (pre-normalization)
// fp16 buffers: X rounded, W rounded + transposed
__device__ __half g_xh[NB * NF];                   // 2MB
__device__ __half g_wth[(size_t)NE * NF * NF];     // 33.5MB, layout [e][n][k]

// ---------------- PTX helpers ----------------
__device__ __forceinline__ uint32_t smem_to_u32(const void* p) {
    uint32_t a;
    asm("{ .reg .u64 t; cvta.to.shared.u64 t, %1; cvt.u32.u64 %0, t; }"
        : "=r"(a) : "l"(p));
    return a;
}
__device__ __forceinline__ void cp16(uint32_t dst, const void* src, int srcsize) {
    asm volatile("cp.async.cg.shared.global [%0], [%1], 16, %2;"
                 :: "r"(dst), "l"(src), "r"(srcsize));
}
#define CP_COMMIT() asm volatile("cp.async.commit_group;" ::: "memory")
#define CP_WAIT(n)  asm volatile("cp.async.wait_group %0;" :: "n"(n) : "memory")

__device__ __forceinline__ void ldm_x4(u32& r0, u32& r1, u32& r2, u32& r3, u32 addr) {
    asm volatile("ldmatrix.sync.aligned.m8n8.x4.shared.b16 {%0,%1,%2,%3}, [%4];"
                 : "=r"(r0), "=r"(r1), "=r"(r2), "=r"(r3) : "r"(addr));
}
__device__ __forceinline__ void mma_f16(float& c0, float& c1, float& c2, float& c3,
                                        u32 a0, u32 a1, u32 a2, u32 a3,
                                        u32 b0, u32 b1) {
    asm volatile("mma.sync.aligned.m16n8k16.row.col.f32.f16.f16.f32 "
                 "{%0,%1,%2,%3}, {%4,%5,%6,%7}, {%8,%9}, {%0,%1,%2,%3};"
                 : "+f"(c0), "+f"(c1), "+f"(c2), "+f"(c3)
                 : "r"(a0), "r"(a1), "r"(a2), "r"(a3), "r"(b0), "r"(b1));
}
__device__ __forceinline__ void fma2(u64& acc, u64 a, u64 b) {
    asm("fma.rn.f32x2 %0, %1, %2, %0;" : "+l"(acc) : "l"(a), "l"(b));
}
__device__ __forceinline__ u64 pack_dup(float x) {
    u64 p;
    asm("mov.b64 %0, {%1, %1};" : "=l"(p) : "f"(x));
    return p;
}
__device__ __forceinline__ float2 unpack2(u64 v) {
    float2 r;
    asm("mov.b64 {%0, %1}, %2;" : "=f"(r.x), "=f"(r.y) : "l"(v));
    return r;
}

// ---------------- fp16 helpers ----------------
__device__ __forceinline__ u32 pack_h2(float a, float b) {
    __half ha = __float2half(a), hb = __float2half(b);
    return (u32)__half_as_ushort(ha) | ((u32)__half_as_ushort(hb) << 16);
}

// ---------------- kernel 0: per-expert scalars (warp/expert) ---------------
__global__ void __launch_bounds__(1024)
init_kernel(const float* __restrict__ ef, const float* __restrict__ trust,
            const float* __restrict__ dt) {
    const int w    = (blockIdx.x * 1024 + threadIdx.x) >> 5;
    const int lane = threadIdx.x & 31;
    const float4* r = (const float4*)(ef + (size_t)w * NF);
    float s = 0.f;
    #pragma unroll
    for (int j = 0; j < 4; j++) {
        float4 v = r[lane + 32 * j];
        s += v.x * v.x + v.y * v.y + v.z * v.z + v.w * v.w;
    }
    #pragma unroll
    for (int off = 16; off > 0; off >>= 1)
        s += __shfl_xor_sync(0xffffffffu, s, off);
    if (lane == 0) {
        g_counts[w] = 0;
        g_escale[w] = trust[w] * fmaxf(0.1f, expf(-0.005f * dt[w]));
        g_efinv[w]  = 1.0f / fmaxf(sqrtf(s), 1e-8f);
    }
}

// ---------------- kernel 0b: gate matrix precompute --------------------
__global__ void __launch_bounds__(256)
pregate_kernel(const float* __restrict__ pw, const float* __restrict__ pb,
               const float* __restrict__ emb) {
    __shared__ float es[NH];
    const int e   = blockIdx.x;
    const int tid = threadIdx.x;
    es[tid] = emb[(size_t)e * NH + tid];
    __syncthreads();

    const int f0 = tid, f1 = tid + 256;
    float a0 = 0.f, a1 = 0.f;
    #pragma unroll 8
    for (int h = 0; h < NH; h++) {
        float ev = es[h];
        a0 += ev * pw[(size_t)h * NF + f0];
        a1 += ev * pw[(size_t)h * NF + f1];
    }
    g_gw[e * NF + f0] = a0;
    g_gw[e * NF + f1] = a1;

    if (tid < 32) {
        float s = 0.f;
        #pragma unroll
        for (int h = tid; h < NH; h += 32) s += pb[h] * es[h];
        #pragma unroll
        for (int off = 16; off > 0; off >>= 1)
            s += __shfl_xor_sync(0xffffffffu, s, off);
        if (tid == 0) g_gc[e] = s;
    }
}

// ---------------- kernel 1: zero output ----------------
__global__ void zero_kernel(float4* __restrict__ out) {
    out[blockIdx.x * 256 + threadIdx.x] = make_float4(0.f, 0.f, 0.f, 0.f);
}

// ---------------- kernel 1b: X -> fp16 (round only) ----------------
__global__ void convert_x(const float* __restrict__ feat) {
    u32* xh = (u32*)g_xh;
    int p = blockIdx.x * 256 + threadIdx.x;
    const int npairs = NB * NF / 2;
    for (; p < npairs; p += gridDim.x * 256) {
        float2 v = *(const float2*)(feat + 2 * p);
        xh[p] = pack_h2(v.x, v.y);
    }
}

// ---------------- kernel 1c: round + transpose W -> [e][n][k] fp16 ---------
__global__ void __launch_bounds__(256)
convert_w(const float* __restrict__ fw) {
    __shared__ float s[64][65];
    const int e  = blockIdx.z;
    const int k0 = blockIdx.x * 64;
    const int n0 = blockIdx.y * 64;
    const int tid = threadIdx.x;
    const float* src = fw + ((size_t)e * NF + k0) * NF + n0;
    #pragma unroll
    for (int i = 0; i < 16; i++) {
        int idx = tid + 256 * i;
        int kl = idx >> 6, nl = idx & 63;
        s[kl][nl] = src[(size_t)kl * NF + nl];
    }
    __syncthreads();
    u32* wh = (u32*)g_wth;
    #pragma unroll
    for (int i = 0; i < 8; i++) {
        int idx = tid + 256 * i;
        int nl = idx >> 5;
        int kp = (idx & 31) * 2;
        size_t off = (((size_t)e * NF + n0 + nl) * NF + k0 + kp) >> 1;
        wh[off] = pack_h2(s[kp][nl], s[kp + 1][nl]);
    }
}

// ---------------- kernel 2a: routing GEMM halves ---------------------------
#define V5_XSS 516
#define V5_BSS 68
#define V5_XS  0
#define V5_BS  (16 * V5_XSS)                  // 8256
#define ROUT_SMEM ((V5_BS + 32 * V5_BSS) * 4) // ~41.7KB

__global__ void __launch_bounds__(256)
route_gemm(const float* __restrict__ feat, const float* __restrict__ ef) {
    extern __shared__ float sm[];
    float* xs = sm + V5_XS;
    float* bs = sm + V5_BS;

    const int tid  = threadIdx.x;
    const int half = blockIdx.x;
    const int t0   = blockIdx.y * 16;

    const float4* feat4 = (const float4*)feat;
    #pragma unroll
    for (int i = 0; i < 8; i++) {
        int idx = tid + 256 * i;
        int t   = idx >> 7;
        int q   = idx & 127;
        float4 v = feat4[(size_t)(t0 + t) * 128 + q];
        *(float4*)(xs + t * V5_XSS + q * 4) = v;
    }
    __syncthreads();

    if (half == 1 && tid < 16) {
        const float* xr = xs + tid * V5_XSS;
        float s = 0.f;
        #pragma unroll 8
        for (int i = 0; i < NF / 4; i++) {
            float4 v = *(const float4*)(xr + i * 4);
            s += v.x * v.x + v.y * v.y + v.z * v.z + v.w * v.w;
        }
        g_xinv[t0 + tid] = 1.0f / fmaxf(sqrtf(s), 1e-8f);
    }

    const float* bsrc = half ? ef : g_gw;
    const int t  = tid & 15;
    const int cg = tid >> 4;
    u64 acc0 = 0ULL, acc1 = 0ULL;

    for (int k0 = 0; k0 < NF; k0 += 32) {
        #pragma unroll
        for (int i = 0; i < 2; i++) {
            int idx = tid + 256 * i;
            int row = idx >> 3;
            int kq  = idx & 7;
            float4 v = *(const float4*)(bsrc + (size_t)row * NF + k0 + kq * 4);
            bs[(kq * 4 + 0) * V5_BSS + row] = v.x;
            bs[(kq * 4 + 1) * V5_BSS + row] = v.y;
            bs[(kq * 4 + 2) * V5_BSS + row] = v.z;
            bs[(kq * 4 + 3) * V5_BSS + row] = v.w;
        }
        __syncthreads();
        #pragma unroll
        for (int kk = 0; kk < 32; kk++) {
            u64 xp = pack_dup(xs[t * V5_XSS + k0 + kk]);
            ulonglong2 w = *(const ulonglong2*)(bs + kk * V5_BSS + cg * 4);
            fma2(acc0, xp, w.x);
            fma2(acc1, xp, w.y);
        }
        __syncthreads();
    }

    float* dst = (half ? g_S : g_L) + (size_t)(t0 + t) * NE + cg * 4;
    float2 a0 = unpack2(acc0), a1 = unpack2(acc1);
    dst[0] = a0.x; dst[1] = a0.y; dst[2] = a1.x; dst[3] = a1.y;
}

// ---------------- kernel 2b: score + top-8 + softmax + scatter -------------
__global__ void __launch_bounds__(256)
route_topk() {
    const int tid  = threadIdx.x;
    const int lane = tid & 31;
    const int tok  = blockIdx.x * 8 + (tid >> 5);
    const float xi = g_xinv[tok];

    float s0, s1;
    {
        int e0 = lane, e1 = lane + 32;
        float gate0 = 1.0f / (1.0f + expf(-(g_L[(size_t)tok * NE + e0] + g_gc[e0]) * 0.0625f));
        float gate1 = 1.0f / (1.0f + expf(-(g_L[(size_t)tok * NE + e1] + g_gc[e1]) * 0.0625f));
        float sim0  = fmaxf(g_S[(size_t)tok * NE + e0] * xi * g_efinv[e0], 0.f);
        float sim1  = fmaxf(g_S[(size_t)tok * NE + e1] * xi * g_efinv[e1], 0.f);
        s0 = gate0 * sim0 * g_escale[e0];
        s1 = gate1 * sim1 * g_escale[e1];
    }
    const int e0 = lane, e1 = lane + 32;

    float vk[NK];
    int   ik[NK];
    #pragma unroll
    for (int k = 0; k < NK; k++) {
        float v; int ix;
        if (s0 >= s1) { v = s0; ix = e0; }
        else          { v = s1; ix = e1; }
        #pragma unroll
        for (int off = 16; off > 0; off >>= 1) {
            float ov = __shfl_down_sync(0xffffffffu, v, off);
            int   oi = __shfl_down_sync(0xffffffffu, ix, off);
            if (ov > v || (ov == v && oi < ix)) { v = ov; ix = oi; }
        }
        v  = __shfl_sync(0xffffffffu, v, 0);
        ix = __shfl_sync(0xffffffffu, ix, 0);
        vk[k] = v; ik[k] = ix;
        if (ix == e0) s0 = -1e30f;
        if (ix == e1) s1 = -1e30f;
    }
    float m = vk[0], sum = 0.f, w[NK];
    #pragma unroll
    for (int k = 0; k < NK; k++) { w[k] = expf(vk[k] - m); sum += w[k]; }
    float inv = 1.0f / sum;
    if (lane < NK) {
        int e = ik[lane];
        int slot = atomicAdd(&g_counts[e], 1);
        g_tok[e * NB + slot] = tok;
        g_wt[e * NB + slot]  = w[lane] * inv;
    }
}

// ---------------- kernel 3: fp16 single-pass grouped MoE GEMM --------------
// CTA tile 128 tok x 128 cols, K chunks of 64. Stage = A(16K)+B(16K) = 32KB,
// double buffered -> ~66KB smem -> 2 CTAs/SM (register-limited).
// Single pass Xh*Wh; combined rounding error ~3e-4 (3.3x margin under 1e-3).
#define MG_DATA    1024
#define MG_STAGE   32768
#define MG_A       0
#define MG_B       16384
#define MG_SMEM    (MG_DATA + 2 * MG_STAGE)   // 66560 bytes

__global__ void __launch_bounds__(256, 2)
moe_gemm_mma(const float* __restrict__ fb, float* __restrict__ out) {
    const int e    = blockIdx.y;
    const int n0   = blockIdx.x * 128;
    const int tile = blockIdx.z;
    const int cnt  = g_counts[e];
    if (tile * 128 >= cnt) return;

    extern __shared__ char smem[];
    const uint32_t sb = smem_to_u32(smem);
    const int tid = threadIdx.x;

    int*   toks = (int*)(smem);
    float* wts  = (float*)(smem + 512);
    {
        int s = tile * 128 + tid;
        if (tid < 128) {
            if (s < cnt) { toks[tid] = g_tok[e * NB + s]; wts[tid] = g_wt[e * NB + s]; }
            else         { toks[tid] = -1;                wts[tid] = 0.f; }
        }
    }
    __syncthreads();

    const int srow  = tid >> 1;
    const int spart = (tid & 1) * 4;
    const int stok  = toks[srow];
    const int asz   = (stok >= 0) ? 16 : 0;
    const uint4* aS = (const uint4*)(g_xh + (size_t)max(stok, 0) * NF);
    const uint4* bS = (const uint4*)(g_wth + ((size_t)e * NF + n0 + srow) * NF);
    const uint32_t srowb = sb + MG_DATA + srow * 128;
    const int      ssw   = (srow & 7) * 16;

    #define PREFETCH(c)                                                          \
    do {                                                                         \
        const uint32_t _d = srowb + ((c) & 1) * MG_STAGE;                        \
        _Pragma("unroll")                                                        \
        for (int j = 0; j < 4; j++) {                                            \
            const int c16 = spart + j;                                           \
            const uint32_t off = (uint32_t)((c16 * 16) ^ ssw);                   \
            cp16(_d + MG_A + off, aS + (c) * 8 + c16, asz);                      \
            cp16(_d + MG_B + off, bS + (c) * 8 + c16, 16);                       \
        }                                                                        \
    } while (0)

    PREFETCH(0);
    CP_COMMIT();

    const int lid = tid & 31;
    const int wid = tid >> 5;
    const int wm  = wid & 1;
    const int wn  = wid >> 1;

    float acc[4][4][4];
    #pragma unroll
    for (int mt = 0; mt < 4; mt++)
        #pragma unroll
        for (int nt = 0; nt < 4; nt++)
            #pragma unroll
            for (int q = 0; q < 4; q++) acc[mt][nt][q] = 0.f;

    const int fa_row = (lid & 15);
    const int fa_hi  = (lid >> 4);

    for (int c = 0; c < 8; c++) {
        if (c < 7) { PREFETCH(c + 1); CP_COMMIT(); CP_WAIT(1); }
        else       { CP_WAIT(0); }
        __syncthreads();

        const uint32_t base = sb + MG_DATA + (c & 1) * MG_STAGE;

        #pragma unroll
        for (int ks = 0; ks < 4; ks++) {
            const int c16 = ks * 2 + fa_hi;
            u32 ah[4][4];
            #pragma unroll
            for (int mt = 0; mt < 4; mt++) {
                const int r = wm * 64 + mt * 16 + fa_row;
                const uint32_t off = r * 128 + (uint32_t)((c16 * 16) ^ ((r & 7) * 16));
                ldm_x4(ah[mt][0], ah[mt][1], ah[mt][2], ah[mt][3], base + MG_A + off);
            }
            u32 bh[2][4];
            #pragma unroll
            for (int p = 0; p < 2; p++) {
                const int r = wn * 32 + p * 16 + fa_row;
                const uint32_t off = r * 128 + (uint32_t)((c16 * 16) ^ ((r & 7) * 16));
                ldm_x4(bh[p][0], bh[p][1], bh[p][2], bh[p][3], base + MG_B + off);
            }
            #pragma unroll
            for (int mt = 0; mt < 4; mt++) {
                #pragma unroll
                for (int nt = 0; nt < 4; nt++) {
                    const int p = nt >> 1, h = nt & 1;
                    float* cc = acc[mt][nt];
                    mma_f16(cc[0], cc[1], cc[2], cc[3],
                            ah[mt][0], ah[mt][1], ah[mt][2], ah[mt][3],
                            bh[p][h], bh[p][h + 2]);
                }
            }
        }
        __syncthreads();
    }

    const float* fbr = fb + (size_t)e * NF + n0;
    #pragma unroll
    for (int mt = 0; mt < 4; mt++) {
        const int r0 = wm * 64 + mt * 16 + (lid >> 2);
        const int r1 = r0 + 8;
        const int tok0 = toks[r0], tok1 = toks[r1];
        const float w0 = wts[r0],  w1 = wts[r1];
        #pragma unroll
        for (int nt = 0; nt < 4; nt++) {
            const int cb = wn * 32 + nt * 8 + (lid & 3) * 2;
            const float b0v = fbr[cb], b1v = fbr[cb + 1];
            const float* cc = acc[mt][nt];
            if (tok0 >= 0) {
                float* orow = out + (size_t)tok0 * NF + n0 + cb;
                atomicAdd(orow + 0, w0 * (cc[0] + b0v));
                atomicAdd(orow + 1, w0 * (cc[1] + b1v));
            }
            if (tok1 >= 0) {
                float* orow = out + (size_t)tok1 * NF + n0 + cb;
                atomicAdd(orow + 0, w1 * (cc[2] + b0v));
                atomicAdd(orow + 1, w1 * (cc[3] + b1v));
            }
        }
    }
}

// ---------------- launch (forked-stream graph) ----------------
extern "C" void kernel_launch(void* const* d_in, const int* in_sizes, int n_in,
                              void* d_out, int out_size) {
    const float* feat  = (const float*)d_in[0];  // [B,F]
    const float* pw    = (const float*)d_in[1];  // [H,F]
    const float* pb    = (const float*)d_in[2];  // [H]
    const float* emb   = (const float*)d_in[3];  // [E,H]
    const float* ef    = (const float*)d_in[4];  // [E,F]
    const float* trust = (const float*)d_in[5];  // [E]
    const float* dt    = (const float*)d_in[6];  // [E]
    const float* fw    = (const float*)d_in[7];  // [E,F,F]
    const float* fb    = (const float*)d_in[8];  // [E,F]
    float* out = (float*)d_out;

    static bool init_done = false;
    static cudaStream_t s1, s2;
    static cudaEvent_t evRoot, evJ1, evJ2;
    if (!init_done) {
        cudaFuncSetAttribute(route_gemm,
                             cudaFuncAttributeMaxDynamicSharedMemorySize, ROUT_SMEM);
        cudaFuncSetAttribute(moe_gemm_mma,
                             cudaFuncAttributeMaxDynamicSharedMemorySize, MG_SMEM);
        cudaStreamCreateWithFlags(&s1, cudaStreamNonBlocking);
        cudaStreamCreateWithFlags(&s2, cudaStreamNonBlocking);
        cudaEventCreateWithFlags(&evRoot, cudaEventDisableTiming);
        cudaEventCreateWithFlags(&evJ1,   cudaEventDisableTiming);
        cudaEventCreateWithFlags(&evJ2,   cudaEventDisableTiming);
        init_done = true;
    }

    // fork
    cudaEventRecord(evRoot, 0);
    cudaStreamWaitEvent(s1, evRoot, 0);
    cudaStreamWaitEvent(s2, evRoot, 0);

    // side 1: weight round+transpose (DRAM-bound, ~17us)
    convert_w<<<dim3(8, 8, NE), 256, 0, s1>>>(fw);
    // side 2: output zero + X conversion + per-expert init
    zero_kernel<<<(NB * NF) / (256 * 4), 256, 0, s2>>>((float4*)out);
    convert_x<<<512, 256, 0, s2>>>(feat);
    init_kernel<<<2, 1024, 0, s2>>>(ef, trust, dt);
    // main: gate precompute -> routing GEMM
    pregate_kernel<<<NE, 256>>>(pw, pb, emb);
    route_gemm<<<dim3(2, NB / 16), 256, ROUT_SMEM>>>(feat, ef);

    // topk needs init (s2) + route_gemm (main)
    cudaEventRecord(evJ2, s2);
    cudaStreamWaitEvent(0, evJ2, 0);
    route_topk<<<NB / 8, 256>>>();

    // moe needs everything
    cudaEventRecord(evJ1, s1);
    cudaStreamWaitEvent(0, evJ1, 0);
    moe_gemm_mma<<<dim3(4, NE, NB / 128), 256, MG_SMEM>>>(fb, out);
}